// round 1
// baseline (speedup 1.0000x reference)
#include <cuda_runtime.h>
#include <math.h>

#define BB   16384
#define DIN  1024
#define HH   1024
#define DOUT 256
#define DEPTH 7

// Scratch activations (allowed: __device__ globals, no runtime allocation)
__device__ float g_h1[(size_t)BB * HH];
__device__ float g_h2[(size_t)BB * HH];
__device__ float g_probs[HH];

// ---------------------------------------------------------------------------
// Transcendent probs: one block per output row r. State vector of length 1024
// evolves through 7*3 = 21 circular 3-point stencil gates, each with scalar
// (cos, sin) from tw[d, r, 0..2]. Only state[0]^2 survives.
// ---------------------------------------------------------------------------
__global__ void probs_kernel(const float* __restrict__ tw) {
    __shared__ float st[2][HH];
    const int r = blockIdx.x;
    const int t = threadIdx.x;

    for (int i = t; i < HH; i += blockDim.x) st[0][i] = 0.03125f;  // 1/sqrt(1024)
    __syncthreads();

    int cur = 0;
    #pragma unroll 1
    for (int d = 0; d < DEPTH; ++d) {
        #pragma unroll 1
        for (int k = 0; k < 3; ++k) {
            const float ang = tw[((size_t)d * HH + r) * HH + k];
            const float c = cosf(ang), s = sinf(ang);
            const int nxt = cur ^ 1;
            for (int i = t; i < HH; i += blockDim.x) {
                // new[i] = c*st[i] - s*st[i+1] + s*st[i-1]   (circular)
                st[nxt][i] = c * st[cur][i]
                           - s * st[cur][(i + 1) & (HH - 1)]
                           + s * st[cur][(i - 1) & (HH - 1)];
            }
            __syncthreads();
            cur = nxt;
        }
    }
    if (t == 0) {
        const float v = st[cur][0];
        g_probs[r] = v * v;
    }
}

// ---------------------------------------------------------------------------
// fp32 SGEMM, C[M,N] = epi(A[M,K] @ W[K,N] + bias [+ probs])
// 128x128 block tile, KT=16, 256 threads, 8x8 per-thread microtile.
// EPI == 0 : relu(acc + bias)
// EPI == 1 : tanh(acc + bias + probs[col])
// M % 128 == 0, N % 128 == 0, K % 16 == 0 (all shapes here satisfy this).
// ---------------------------------------------------------------------------
template <int EPI>
__global__ void __launch_bounds__(256, 2)
sgemm_kernel(const float* __restrict__ A,
             const float* __restrict__ W,
             const float* __restrict__ bias,
             float* __restrict__ C,
             int M, int N, int K)
{
    __shared__ __align__(16) float As[16][128];   // [k][m] (transposed on store)
    __shared__ __align__(16) float Bs[16][128];   // [k][n]

    const int bm  = blockIdx.y * 128;
    const int bn  = blockIdx.x * 128;
    const int tid = threadIdx.x;
    const int tx  = tid & 15;    // 0..15 -> N microtile
    const int ty  = tid >> 4;    // 0..15 -> M microtile

    float acc[8][8];
    #pragma unroll
    for (int i = 0; i < 8; ++i)
        #pragma unroll
        for (int j = 0; j < 8; ++j) acc[i][j] = 0.f;

    // A tile load mapping: 512 float4 total; thread does q = tid and tid+256
    const int ar0 = tid >> 2;            // row within tile (0..63), +64 for h=1
    const int ak  = (tid & 3) * 4;       // k offset (0,4,8,12)
    // B tile load mapping
    const int bk0 = tid >> 5;            // k row (0..7), +8 for h=1
    const int bc  = (tid & 31) * 4;      // col offset (0..124)

    const float* Aptr = A + (size_t)bm * K;
    const float* Wptr = W + bn;

    for (int k0 = 0; k0 < K; k0 += 16) {
        #pragma unroll
        for (int h = 0; h < 2; ++h) {
            const int row = ar0 + h * 64;
            const float4 v = *reinterpret_cast<const float4*>(
                Aptr + (size_t)row * K + k0 + ak);
            As[ak + 0][row] = v.x;
            As[ak + 1][row] = v.y;
            As[ak + 2][row] = v.z;
            As[ak + 3][row] = v.w;
        }
        #pragma unroll
        for (int h = 0; h < 2; ++h) {
            const int kr = bk0 + h * 8;
            const float4 v = *reinterpret_cast<const float4*>(
                Wptr + (size_t)(k0 + kr) * N + bc);
            *reinterpret_cast<float4*>(&Bs[kr][bc]) = v;
        }
        __syncthreads();

        #pragma unroll
        for (int kk = 0; kk < 16; ++kk) {
            float a[8], b[8];
            *reinterpret_cast<float4*>(a)     = *reinterpret_cast<const float4*>(&As[kk][ty * 4]);
            *reinterpret_cast<float4*>(a + 4) = *reinterpret_cast<const float4*>(&As[kk][64 + ty * 4]);
            *reinterpret_cast<float4*>(b)     = *reinterpret_cast<const float4*>(&Bs[kk][tx * 4]);
            *reinterpret_cast<float4*>(b + 4) = *reinterpret_cast<const float4*>(&Bs[kk][64 + tx * 4]);
            #pragma unroll
            for (int i = 0; i < 8; ++i)
                #pragma unroll
                for (int j = 0; j < 8; ++j)
                    acc[i][j] = fmaf(a[i], b[j], acc[i][j]);
        }
        __syncthreads();
    }

    // Epilogue: columns come in two contiguous float4 groups per thread.
    const int c0 = bn + tx * 4;        // cols c0..c0+3   (acc[.][0..3])
    const int c1 = c0 + 64;            // cols c1..c1+3   (acc[.][4..7])

    float bv[8], pv[8];
    #pragma unroll
    for (int j = 0; j < 8; ++j) {
        const int c = (j < 4) ? (c0 + j) : (c1 + j - 4);
        bv[j] = bias[c];
        pv[j] = (EPI == 1) ? g_probs[c] : 0.f;
    }

    #pragma unroll
    for (int i = 0; i < 8; ++i) {
        const int row = bm + ((i < 4) ? (ty * 4 + i) : (64 + ty * 4 + i - 4));
        float o[8];
        #pragma unroll
        for (int j = 0; j < 8; ++j) {
            float v = acc[i][j] + bv[j];
            if (EPI == 1) v = tanhf(v + pv[j]);
            else          v = fmaxf(v, 0.f);
            o[j] = v;
        }
        *reinterpret_cast<float4*>(&C[(size_t)row * N + c0]) =
            make_float4(o[0], o[1], o[2], o[3]);
        *reinterpret_cast<float4*>(&C[(size_t)row * N + c1]) =
            make_float4(o[4], o[5], o[6], o[7]);
    }
}

// ---------------------------------------------------------------------------
extern "C" void kernel_launch(void* const* d_in, const int* in_sizes, int n_in,
                              void* d_out, int out_size) {
    const float* x    = (const float*)d_in[0];
    const float* w0   = (const float*)d_in[1];
    const float* b0   = (const float*)d_in[2];
    const float* w1   = (const float*)d_in[3];
    const float* b1   = (const float*)d_in[4];
    const float* tw   = (const float*)d_in[5];
    const float* cw   = (const float*)d_in[6];
    const float* cb   = (const float*)d_in[7];
    const float* wout = (const float*)d_in[8];
    const float* bout = (const float*)d_in[9];
    float* out = (float*)d_out;

    float *h1 = nullptr, *h2 = nullptr;
    cudaGetSymbolAddress((void**)&h1, g_h1);
    cudaGetSymbolAddress((void**)&h2, g_h2);

    // 1) transcendent probs (tiny)
    probs_kernel<<<HH, 256>>>(tw);

    // 2) h1 = relu(x @ w0 + b0)
    sgemm_kernel<0><<<dim3(HH / 128, BB / 128), 256>>>(x, w0, b0, h1, BB, HH, DIN);
    // 3) h2 = relu(h1 @ w1 + b1)
    sgemm_kernel<0><<<dim3(HH / 128, BB / 128), 256>>>(h1, w1, b1, h2, BB, HH, HH);
    // 4) h1 = tanh(h2 @ cw + cb + probs)
    sgemm_kernel<1><<<dim3(HH / 128, BB / 128), 256>>>(h2, cw, cb, h1, BB, HH, HH);
    // 5) out = relu(h1 @ wout + bout)
    sgemm_kernel<0><<<dim3(DOUT / 128, BB / 128), 256>>>(h1, wout, bout, out, BB, DOUT, HH);
}

// round 2
// speedup vs baseline: 1.0009x; 1.0009x over previous
#include <cuda_runtime.h>
#include <math.h>

#define BB   16384
#define DIN  1024
#define HH   1024
#define DOUT 256
#define DEPTH 7

// Scratch activations (allowed: __device__ globals, no runtime allocation)
__device__ float g_h1[(size_t)BB * HH];
__device__ float g_h2[(size_t)BB * HH];
__device__ float g_probs[HH];

// ---------------------------------------------------------------------------
// Transcendent probs: one block per output row r. State vector of length 1024
// evolves through 7*3 = 21 circular 3-point stencil gates, each with scalar
// (cos, sin) from tw[d, r, 0..2]. Only state[0]^2 survives.
// ---------------------------------------------------------------------------
__global__ void probs_kernel(const float* __restrict__ tw) {
    __shared__ float st[2][HH];
    const int r = blockIdx.x;
    const int t = threadIdx.x;

    for (int i = t; i < HH; i += blockDim.x) st[0][i] = 0.03125f;  // 1/sqrt(1024)
    __syncthreads();

    int cur = 0;
    #pragma unroll 1
    for (int d = 0; d < DEPTH; ++d) {
        #pragma unroll 1
        for (int k = 0; k < 3; ++k) {
            const float ang = tw[((size_t)d * HH + r) * HH + k];
            const float c = cosf(ang), s = sinf(ang);
            const int nxt = cur ^ 1;
            for (int i = t; i < HH; i += blockDim.x) {
                // new[i] = c*st[i] - s*st[i+1] + s*st[i-1]   (circular)
                st[nxt][i] = c * st[cur][i]
                           - s * st[cur][(i + 1) & (HH - 1)]
                           + s * st[cur][(i - 1) & (HH - 1)];
            }
            __syncthreads();
            cur = nxt;
        }
    }
    if (t == 0) {
        const float v = st[cur][0];
        g_probs[r] = v * v;
    }
}

// ---------------------------------------------------------------------------
// fp32 SGEMM, C[M,N] = epi(A[M,K] @ W[K,N] + bias [+ probs])
// 128x128 block tile, KT=16, 256 threads, 8x8 per-thread microtile.
// EPI == 0 : relu(acc + bias)
// EPI == 1 : tanh(acc + bias + probs[col])
// M % 128 == 0, N % 128 == 0, K % 16 == 0 (all shapes here satisfy this).
// ---------------------------------------------------------------------------
template <int EPI>
__global__ void __launch_bounds__(256, 2)
sgemm_kernel(const float* __restrict__ A,
             const float* __restrict__ W,
             const float* __restrict__ bias,
             float* __restrict__ C,
             int M, int N, int K)
{
    __shared__ __align__(16) float As[16][128];   // [k][m] (transposed on store)
    __shared__ __align__(16) float Bs[16][128];   // [k][n]

    const int bm  = blockIdx.y * 128;
    const int bn  = blockIdx.x * 128;
    const int tid = threadIdx.x;
    const int tx  = tid & 15;    // 0..15 -> N microtile
    const int ty  = tid >> 4;    // 0..15 -> M microtile

    float acc[8][8];
    #pragma unroll
    for (int i = 0; i < 8; ++i)
        #pragma unroll
        for (int j = 0; j < 8; ++j) acc[i][j] = 0.f;

    // A tile load mapping: 512 float4 total; thread does q = tid and tid+256
    const int ar0 = tid >> 2;            // row within tile (0..63), +64 for h=1
    const int ak  = (tid & 3) * 4;       // k offset (0,4,8,12)
    // B tile load mapping
    const int bk0 = tid >> 5;            // k row (0..7), +8 for h=1
    const int bc  = (tid & 31) * 4;      // col offset (0..124)

    const float* Aptr = A + (size_t)bm * K;
    const float* Wptr = W + bn;

    for (int k0 = 0; k0 < K; k0 += 16) {
        #pragma unroll
        for (int h = 0; h < 2; ++h) {
            const int row = ar0 + h * 64;
            const float4 v = *reinterpret_cast<const float4*>(
                Aptr + (size_t)row * K + k0 + ak);
            As[ak + 0][row] = v.x;
            As[ak + 1][row] = v.y;
            As[ak + 2][row] = v.z;
            As[ak + 3][row] = v.w;
        }
        #pragma unroll
        for (int h = 0; h < 2; ++h) {
            const int kr = bk0 + h * 8;
            const float4 v = *reinterpret_cast<const float4*>(
                Wptr + (size_t)(k0 + kr) * N + bc);
            *reinterpret_cast<float4*>(&Bs[kr][bc]) = v;
        }
        __syncthreads();

        #pragma unroll
        for (int kk = 0; kk < 16; ++kk) {
            float a[8], b[8];
            *reinterpret_cast<float4*>(a)     = *reinterpret_cast<const float4*>(&As[kk][ty * 4]);
            *reinterpret_cast<float4*>(a + 4) = *reinterpret_cast<const float4*>(&As[kk][64 + ty * 4]);
            *reinterpret_cast<float4*>(b)     = *reinterpret_cast<const float4*>(&Bs[kk][tx * 4]);
            *reinterpret_cast<float4*>(b + 4) = *reinterpret_cast<const float4*>(&Bs[kk][64 + tx * 4]);
            #pragma unroll
            for (int i = 0; i < 8; ++i)
                #pragma unroll
                for (int j = 0; j < 8; ++j)
                    acc[i][j] = fmaf(a[i], b[j], acc[i][j]);
        }
        __syncthreads();
    }

    // Epilogue: columns come in two contiguous float4 groups per thread.
    const int c0 = bn + tx * 4;        // cols c0..c0+3   (acc[.][0..3])
    const int c1 = c0 + 64;            // cols c1..c1+3   (acc[.][4..7])

    float bv[8], pv[8];
    #pragma unroll
    for (int j = 0; j < 8; ++j) {
        const int c = (j < 4) ? (c0 + j) : (c1 + j - 4);
        bv[j] = bias[c];
        pv[j] = (EPI == 1) ? g_probs[c] : 0.f;
    }

    #pragma unroll
    for (int i = 0; i < 8; ++i) {
        const int row = bm + ((i < 4) ? (ty * 4 + i) : (64 + ty * 4 + i - 4));
        float o[8];
        #pragma unroll
        for (int j = 0; j < 8; ++j) {
            float v = acc[i][j] + bv[j];
            if (EPI == 1) v = tanhf(v + pv[j]);
            else          v = fmaxf(v, 0.f);
            o[j] = v;
        }
        *reinterpret_cast<float4*>(&C[(size_t)row * N + c0]) =
            make_float4(o[0], o[1], o[2], o[3]);
        *reinterpret_cast<float4*>(&C[(size_t)row * N + c1]) =
            make_float4(o[4], o[5], o[6], o[7]);
    }
}

// ---------------------------------------------------------------------------
extern "C" void kernel_launch(void* const* d_in, const int* in_sizes, int n_in,
                              void* d_out, int out_size) {
    const float* x    = (const float*)d_in[0];
    const float* w0   = (const float*)d_in[1];
    const float* b0   = (const float*)d_in[2];
    const float* w1   = (const float*)d_in[3];
    const float* b1   = (const float*)d_in[4];
    const float* tw   = (const float*)d_in[5];
    const float* cw   = (const float*)d_in[6];
    const float* cb   = (const float*)d_in[7];
    const float* wout = (const float*)d_in[8];
    const float* bout = (const float*)d_in[9];
    float* out = (float*)d_out;

    float *h1 = nullptr, *h2 = nullptr;
    cudaGetSymbolAddress((void**)&h1, g_h1);
    cudaGetSymbolAddress((void**)&h2, g_h2);

    // 1) transcendent probs (tiny)
    probs_kernel<<<HH, 256>>>(tw);

    // 2) h1 = relu(x @ w0 + b0)
    sgemm_kernel<0><<<dim3(HH / 128, BB / 128), 256>>>(x, w0, b0, h1, BB, HH, DIN);
    // 3) h2 = relu(h1 @ w1 + b1)
    sgemm_kernel<0><<<dim3(HH / 128, BB / 128), 256>>>(h1, w1, b1, h2, BB, HH, HH);
    // 4) h1 = tanh(h2 @ cw + cb + probs)
    sgemm_kernel<1><<<dim3(HH / 128, BB / 128), 256>>>(h2, cw, cb, h1, BB, HH, HH);
    // 5) out = relu(h1 @ wout + bout)
    sgemm_kernel<0><<<dim3(DOUT / 128, BB / 128), 256>>>(h1, wout, bout, out, BB, DOUT, HH);
}

// round 4
// speedup vs baseline: 1.0875x; 1.0866x over previous
#include <cuda_runtime.h>
#include <math.h>
#include <stdint.h>

#define BB   16384
#define DIN  1024
#define HH   1024
#define DOUT 256
#define DEPTH 7

// ---------------- device scratch ---------------------------------------------
__device__ float g_h1[(size_t)BB * HH];
__device__ float g_h2[(size_t)BB * HH];
__device__ float g_probs[HH];

// ---------------- helpers ------------------------------------------------------
__device__ __forceinline__ uint32_t s2u(const void* p) {
    uint32_t a;
    asm("{ .reg .u64 t; cvta.to.shared.u64 t, %1; cvt.u32.u64 %0, t; }" : "=r"(a) : "l"(p));
    return a;
}
__device__ __forceinline__ uint32_t tf32hi(float x) {
    uint32_t u;
    asm("cvt.rna.tf32.f32 %0, %1;" : "=r"(u) : "f"(x));
    return u;
}
__device__ __forceinline__ void tf32split(float x, uint32_t& h, uint32_t& l) {
    h = tf32hi(x);
    l = tf32hi(x - __uint_as_float(h));
}
__device__ __forceinline__ void mma8(float c[4],
                                     uint32_t a0, uint32_t a1, uint32_t a2, uint32_t a3,
                                     uint32_t b0, uint32_t b1) {
    asm volatile(
        "mma.sync.aligned.m16n8k8.row.col.f32.tf32.tf32.f32 "
        "{%0,%1,%2,%3}, {%4,%5,%6,%7}, {%8,%9}, {%0,%1,%2,%3};"
        : "+f"(c[0]), "+f"(c[1]), "+f"(c[2]), "+f"(c[3])
        : "r"(a0), "r"(a1), "r"(a2), "r"(a3), "r"(b0), "r"(b1));
}
__device__ __forceinline__ void cp16(uint32_t s, const void* g) {
    asm volatile("cp.async.cg.shared.global [%0], [%1], 16;" :: "r"(s), "l"(g));
}
#define CP_COMMIT() asm volatile("cp.async.commit_group;" ::: "memory")
#define CP_WAIT(n)  asm volatile("cp.async.wait_group %0;" :: "n"(n) : "memory")

// ---------------- probs (tiny) -------------------------------------------------
__global__ void probs_kernel(const float* __restrict__ tw) {
    __shared__ float st[2][HH];
    const int r = blockIdx.x, t = threadIdx.x;
    for (int i = t; i < HH; i += blockDim.x) st[0][i] = 0.03125f;
    __syncthreads();
    int cur = 0;
    #pragma unroll 1
    for (int d = 0; d < DEPTH; ++d)
        #pragma unroll 1
        for (int k = 0; k < 3; ++k) {
            const float ang = tw[((size_t)d * HH + r) * HH + k];
            const float c = cosf(ang), s = sinf(ang);
            const int nxt = cur ^ 1;
            for (int i = t; i < HH; i += blockDim.x)
                st[nxt][i] = c * st[cur][i]
                           - s * st[cur][(i + 1) & (HH - 1)]
                           + s * st[cur][(i - 1) & (HH - 1)];
            __syncthreads();
            cur = nxt;
        }
    if (t == 0) { const float v = st[cur][0]; g_probs[r] = v * v; }
}

// ---------------- 3xTF32 GEMM via mma.sync -------------------------------------
// C[M,N] = epi(A[M,K] @ W[K,N] + bias [+probs])
// CTA tile 128x128, KT=32, 256 threads (8 warps, 2(m) x 4(n)), warp tile 64x32.
// Fragments loaded fp32 from SMEM, split to (hi,lo) tf32 in registers;
// acc += Ah*Bh + Al*Bh + Ah*Bl  (lo*lo dropped).
#define KT     32
#define AS_LD  36     // As[128][36] floats  -> conflict-free A-fragment reads
#define BS_LD  136    // Bs[32][136] floats  -> conflict-free B-fragment reads
#define AS_BYTES (128 * AS_LD * 4)          // 18432
#define BS_BYTES (KT * BS_LD * 4)           // 17408
#define SMEM_TOTAL (2 * (AS_BYTES + BS_BYTES))  // 71680

template <int EPI>   // 0: relu   1: tanh(+probs)
__global__ void __launch_bounds__(256, 1)
mma_gemm(const float* __restrict__ A, const float* __restrict__ W,
         const float* __restrict__ bias, float* __restrict__ C,
         int M, int N, int K)
{
    extern __shared__ __align__(16) char smem[];
    float* As[2] = { (float*)smem,                        (float*)(smem + AS_BYTES) };
    float* Bs[2] = { (float*)(smem + 2 * AS_BYTES),       (float*)(smem + 2 * AS_BYTES + BS_BYTES) };

    const int tid  = threadIdx.x;
    const int lane = tid & 31;
    const int warp = tid >> 5;
    const int wm   = (warp & 1) * 64;     // warp m-offset in CTA tile
    const int wn   = (warp >> 1) * 32;    // warp n-offset
    const int g    = lane >> 2;           // groupID 0..7
    const int tg   = lane & 3;            // threadID_in_group 0..3

    const int bm = blockIdx.y * 128;
    const int bn = blockIdx.x * 128;

    float acc[4][4][4];
    #pragma unroll
    for (int i = 0; i < 4; ++i)
        #pragma unroll
        for (int j = 0; j < 4; ++j)
            #pragma unroll
            for (int q = 0; q < 4; ++q) acc[i][j][q] = 0.f;

    // global->smem mappings (one float4 each, x4 iterations)
    const int am = tid >> 3;            // 0..31 (+32*r)
    const int ak = (tid & 7) * 4;       // 0,4,...,28
    const int bk = tid >> 5;            // 0..7 (+8*r)
    const int bq = (tid & 31) * 4;      // 0..124

    const float* Ag = A + (size_t)bm * K;
    const float* Wg = W + bn;

    auto load_chunk = [&](int c, int s) {
        const int k0 = c * KT;
        const uint32_t asb = s2u(As[s]);
        const uint32_t bsb = s2u(Bs[s]);
        #pragma unroll
        for (int r = 0; r < 4; ++r) {
            const int m = am + 32 * r;
            cp16(asb + (m * AS_LD + ak) * 4, Ag + (size_t)m * K + k0 + ak);
        }
        #pragma unroll
        for (int r = 0; r < 4; ++r) {
            const int k = bk + 8 * r;
            cp16(bsb + (k * BS_LD + bq) * 4, Wg + (size_t)(k0 + k) * N + bq);
        }
    };

    const int NC = K / KT;
    load_chunk(0, 0);
    CP_COMMIT();

    #pragma unroll 1
    for (int c = 0; c < NC; ++c) {
        const int s = c & 1;
        if (c + 1 < NC) {
            load_chunk(c + 1, s ^ 1);
            CP_COMMIT();
            CP_WAIT(1);
        } else {
            CP_WAIT(0);
        }
        __syncthreads();

        const float* as = As[s];
        const float* bs = Bs[s];
        #pragma unroll
        for (int k8 = 0; k8 < 4; ++k8) {
            // ---- A fragments: rows wm + i*16 + g (+8), cols k8*8 + tg (+4)
            uint32_t ah[4][4], al[4][4];
            #pragma unroll
            for (int i = 0; i < 4; ++i) {
                const int row = wm + i * 16 + g;
                const int kc  = k8 * 8 + tg;
                const float v0 = as[row * AS_LD + kc];
                const float v1 = as[(row + 8) * AS_LD + kc];
                const float v2 = as[row * AS_LD + kc + 4];
                const float v3 = as[(row + 8) * AS_LD + kc + 4];
                tf32split(v0, ah[i][0], al[i][0]);
                tf32split(v1, ah[i][1], al[i][1]);
                tf32split(v2, ah[i][2], al[i][2]);
                tf32split(v3, ah[i][3], al[i][3]);
            }
            // ---- B fragments: rows(k) k8*8 + tg (+4), col wn + j*8 + g
            uint32_t bh[4][2], bl[4][2];
            #pragma unroll
            for (int j = 0; j < 4; ++j) {
                const int col = wn + j * 8 + g;
                const int kr  = k8 * 8 + tg;
                const float v0 = bs[kr * BS_LD + col];
                const float v1 = bs[(kr + 4) * BS_LD + col];
                tf32split(v0, bh[j][0], bl[j][0]);
                tf32split(v1, bh[j][1], bl[j][1]);
            }
            // ---- 3 products
            #pragma unroll
            for (int i = 0; i < 4; ++i)
                #pragma unroll
                for (int j = 0; j < 4; ++j) {
                    mma8(acc[i][j], ah[i][0], ah[i][1], ah[i][2], ah[i][3], bh[j][0], bh[j][1]);
                    mma8(acc[i][j], al[i][0], al[i][1], al[i][2], al[i][3], bh[j][0], bh[j][1]);
                    mma8(acc[i][j], ah[i][0], ah[i][1], ah[i][2], ah[i][3], bl[j][0], bl[j][1]);
                }
        }
        __syncthreads();
    }

    // ---- epilogue: c0,c1 -> (row, col),(row,col+1); c2,c3 -> (row+8, ...)
    #pragma unroll
    for (int j = 0; j < 4; ++j) {
        const int col = bn + wn + j * 8 + 2 * tg;
        const float b0 = bias[col], b1 = bias[col + 1];
        float p0 = 0.f, p1 = 0.f;
        if (EPI == 1) { p0 = g_probs[col]; p1 = g_probs[col + 1]; }
        #pragma unroll
        for (int i = 0; i < 4; ++i) {
            const int row = bm + wm + i * 16 + g;
            float v0 = acc[i][j][0] + b0;
            float v1 = acc[i][j][1] + b1;
            float v2 = acc[i][j][2] + b0;
            float v3 = acc[i][j][3] + b1;
            if (EPI == 1) {
                v0 = tanhf(v0 + p0); v1 = tanhf(v1 + p1);
                v2 = tanhf(v2 + p0); v3 = tanhf(v3 + p1);
            } else {
                v0 = fmaxf(v0, 0.f); v1 = fmaxf(v1, 0.f);
                v2 = fmaxf(v2, 0.f); v3 = fmaxf(v3, 0.f);
            }
            *reinterpret_cast<float2*>(&C[(size_t)row * N + col])       = make_float2(v0, v1);
            *reinterpret_cast<float2*>(&C[(size_t)(row + 8) * N + col]) = make_float2(v2, v3);
        }
    }
}

// ---------------- host ----------------------------------------------------------
extern "C" void kernel_launch(void* const* d_in, const int* in_sizes, int n_in,
                              void* d_out, int out_size) {
    const float* x    = (const float*)d_in[0];
    const float* w0   = (const float*)d_in[1];
    const float* b0   = (const float*)d_in[2];
    const float* w1   = (const float*)d_in[3];
    const float* b1   = (const float*)d_in[4];
    const float* tw   = (const float*)d_in[5];
    const float* cw   = (const float*)d_in[6];
    const float* cb   = (const float*)d_in[7];
    const float* wout = (const float*)d_in[8];
    const float* bout = (const float*)d_in[9];
    float* out = (float*)d_out;

    float *h1 = nullptr, *h2 = nullptr;
    cudaGetSymbolAddress((void**)&h1, g_h1);
    cudaGetSymbolAddress((void**)&h2, g_h2);

    cudaFuncSetAttribute(mma_gemm<0>, cudaFuncAttributeMaxDynamicSharedMemorySize, SMEM_TOTAL);
    cudaFuncSetAttribute(mma_gemm<1>, cudaFuncAttributeMaxDynamicSharedMemorySize, SMEM_TOTAL);

    probs_kernel<<<HH, 256>>>(tw);

    mma_gemm<0><<<dim3(HH / 128,   BB / 128), 256, SMEM_TOTAL>>>(x,  w0,   b0,   h1,  BB, HH,   DIN);
    mma_gemm<0><<<dim3(HH / 128,   BB / 128), 256, SMEM_TOTAL>>>(h1, w1,   b1,   h2,  BB, HH,   HH);
    mma_gemm<1><<<dim3(HH / 128,   BB / 128), 256, SMEM_TOTAL>>>(h2, cw,   cb,   h1,  BB, HH,   HH);
    mma_gemm<0><<<dim3(DOUT / 128, BB / 128), 256, SMEM_TOTAL>>>(h1, wout, bout, out, BB, DOUT, HH);
}

// round 5
// speedup vs baseline: 1.8695x; 1.7191x over previous
#include <cuda_runtime.h>
#include <cuda_fp16.h>
#include <math.h>
#include <stdint.h>

#define BB   16384
#define DIN  1024
#define HH   1024
#define DOUT 256
#define DEPTH 7

// ---------------- device scratch (fp16 hi/lo operand arrays) ------------------
__device__ __half g_xh[(size_t)BB * HH],  g_xl[(size_t)BB * HH];    // x split; reused for h3
__device__ __half g_h1h[(size_t)BB * HH], g_h1l[(size_t)BB * HH];
__device__ __half g_h2h[(size_t)BB * HH], g_h2l[(size_t)BB * HH];
__device__ __half g_w0h[(size_t)HH * DIN],  g_w0l[(size_t)HH * DIN];   // [N][K]
__device__ __half g_w1h[(size_t)HH * HH],   g_w1l[(size_t)HH * HH];
__device__ __half g_cwh[(size_t)HH * HH],   g_cwl[(size_t)HH * HH];
__device__ __half g_woh[(size_t)DOUT * HH], g_wol[(size_t)DOUT * HH];
__device__ float  g_probs[HH];

// ---------------- helpers -------------------------------------------------------
__device__ __forceinline__ uint32_t s2u(const void* p) {
    uint32_t a;
    asm("{ .reg .u64 t; cvta.to.shared.u64 t, %1; cvt.u32.u64 %0, t; }" : "=r"(a) : "l"(p));
    return a;
}
__device__ __forceinline__ void mma16(float c[4],
                                      uint32_t a0, uint32_t a1, uint32_t a2, uint32_t a3,
                                      uint32_t b0, uint32_t b1) {
    asm volatile(
        "mma.sync.aligned.m16n8k16.row.col.f32.f16.f16.f32 "
        "{%0,%1,%2,%3}, {%4,%5,%6,%7}, {%8,%9}, {%0,%1,%2,%3};"
        : "+f"(c[0]), "+f"(c[1]), "+f"(c[2]), "+f"(c[3])
        : "r"(a0), "r"(a1), "r"(a2), "r"(a3), "r"(b0), "r"(b1));
}
__device__ __forceinline__ void cp16(uint32_t s, const void* g) {
    asm volatile("cp.async.cg.shared.global [%0], [%1], 16;" :: "r"(s), "l"(g));
}
#define CP_COMMIT() asm volatile("cp.async.commit_group;" ::: "memory")
#define CP_WAIT(n)  asm volatile("cp.async.wait_group %0;" :: "n"(n) : "memory")

__device__ __forceinline__ void fsplit(float v, __half& h, __half& l) {
    h = __float2half_rn(v);
    l = __float2half_rn(v - __half2float(h));
}

// ---------------- probs (tiny) ---------------------------------------------------
__global__ void probs_kernel(const float* __restrict__ tw) {
    __shared__ float st[2][HH];
    const int r = blockIdx.x, t = threadIdx.x;
    for (int i = t; i < HH; i += blockDim.x) st[0][i] = 0.03125f;
    __syncthreads();
    int cur = 0;
    #pragma unroll 1
    for (int d = 0; d < DEPTH; ++d)
        #pragma unroll 1
        for (int k = 0; k < 3; ++k) {
            const float ang = tw[((size_t)d * HH + r) * HH + k];
            const float c = cosf(ang), s = sinf(ang);
            const int nxt = cur ^ 1;
            for (int i = t; i < HH; i += blockDim.x)
                st[nxt][i] = c * st[cur][i]
                           - s * st[cur][(i + 1) & (HH - 1)]
                           + s * st[cur][(i - 1) & (HH - 1)];
            __syncthreads();
            cur = nxt;
        }
    if (t == 0) { const float v = st[cur][0]; g_probs[r] = v * v; }
}

// ---------------- x split: fp32 -> fp16 hi/lo -------------------------------------
__global__ void splitx_kernel(const float4* __restrict__ in,
                              __half2* __restrict__ oh, __half2* __restrict__ ol, int n4) {
    int i = blockIdx.x * blockDim.x + threadIdx.x;
    if (i >= n4) return;
    float4 v = in[i];
    __half h0, h1, h2, h3, l0, l1, l2, l3;
    fsplit(v.x, h0, l0); fsplit(v.y, h1, l1);
    fsplit(v.z, h2, l2); fsplit(v.w, h3, l3);
    oh[2 * i]     = __halves2half2(h0, h1);
    oh[2 * i + 1] = __halves2half2(h2, h3);
    ol[2 * i]     = __halves2half2(l0, l1);
    ol[2 * i + 1] = __halves2half2(l2, l3);
}

// ---------------- weight transpose + split: w[K][N] fp32 -> [N][K] fp16 h/l -------
__global__ void tsplit_kernel(const float* __restrict__ w,
                              __half* __restrict__ th, __half* __restrict__ tl,
                              int Kd, int Nd) {
    __shared__ float tile[32][33];
    const int nb = blockIdx.x * 32, kb = blockIdx.y * 32;
    const int tx = threadIdx.x, ty = threadIdx.y;   // 32 x 8
    #pragma unroll
    for (int i = 0; i < 32; i += 8)
        tile[ty + i][tx] = w[(size_t)(kb + ty + i) * Nd + nb + tx];
    __syncthreads();
    #pragma unroll
    for (int i = 0; i < 32; i += 8) {
        const float v = tile[tx][ty + i];
        __half h, l;
        fsplit(v, h, l);
        const size_t o = (size_t)(nb + ty + i) * Kd + kb + tx;
        th[o] = h;
        tl[o] = l;
    }
}

// ---------------- 3-product split-fp16 GEMM via mma.sync m16n8k16 ----------------
// C[M,N] = epi((Ah+Al) @ (Bh+Bl)^T + bias [+probs]), dropping Al*Bl.
// A arrays [M][K] fp16; B arrays [N][K] fp16 (pre-transposed).
// CTA tile 128x128, KT=64, 256 threads (8 warps 2x4), warp tile 64x32.
#define KT      64
#define LDH     72                         // smem row stride in halves
#define TILE_B  (128 * LDH * 2)            // 18432 bytes per (array, tile)
#define STAGE_B (4 * TILE_B)               // Ah,Al,Bh,Bl = 73728
#define SMEM_TOTAL (2 * STAGE_B)           // 147456

template <int EPI>   // 0: relu->split   1: tanh(+probs)->split   2: relu->fp32
__global__ void __launch_bounds__(256, 1)
mma_gemm(const __half* __restrict__ Ah, const __half* __restrict__ Al,
         const __half* __restrict__ Bh, const __half* __restrict__ Bl,
         const float* __restrict__ bias,
         __half* __restrict__ Ch, __half* __restrict__ Cl,
         float* __restrict__ Cf,
         int M, int N, int K)
{
    extern __shared__ __align__(16) char smem[];
    const int tid  = threadIdx.x;
    const int lane = tid & 31;
    const int warp = tid >> 5;
    const int wm   = (warp & 1) * 64;
    const int wn   = (warp >> 1) * 32;
    const int g    = lane >> 2;     // 0..7
    const int tg   = lane & 3;      // 0..3

    const int bm = blockIdx.y * 128;
    const int bn = blockIdx.x * 128;

    __half* sAh[2] = { (__half*)smem,                       (__half*)(smem + STAGE_B) };
    __half* sAl[2] = { (__half*)(smem + TILE_B),            (__half*)(smem + STAGE_B + TILE_B) };
    __half* sBh[2] = { (__half*)(smem + 2 * TILE_B),        (__half*)(smem + STAGE_B + 2 * TILE_B) };
    __half* sBl[2] = { (__half*)(smem + 3 * TILE_B),        (__half*)(smem + STAGE_B + 3 * TILE_B) };

    float acc[4][4][4];
    #pragma unroll
    for (int i = 0; i < 4; ++i)
        #pragma unroll
        for (int j = 0; j < 4; ++j)
            #pragma unroll
            for (int q = 0; q < 4; ++q) acc[i][j][q] = 0.f;

    // cp.async mapping: 1024 segments of 8 halves per (array, tile); 4 per thread.
    const int srow = tid >> 3;          // 0..31  (+32*r)
    const int sseg = tid & 7;           // 0..7 -> halves sseg*8

    auto load_chunk = [&](int c, int s) {
        const int k0 = c * KT;
        const uint32_t ah = s2u(sAh[s]), al = s2u(sAl[s]);
        const uint32_t bh = s2u(sBh[s]), bl = s2u(sBl[s]);
        #pragma unroll
        for (int r = 0; r < 4; ++r) {
            const int row = srow + 32 * r;
            const uint32_t so = (row * LDH + sseg * 8) * 2;
            const size_t  ga = (size_t)(bm + row) * K + k0 + sseg * 8;
            const size_t  gb = (size_t)(bn + row) * K + k0 + sseg * 8;
            cp16(ah + so, Ah + ga);
            cp16(al + so, Al + ga);
            cp16(bh + so, Bh + gb);
            cp16(bl + so, Bl + gb);
        }
    };

    const int NC = K / KT;
    load_chunk(0, 0);
    CP_COMMIT();

    #pragma unroll 1
    for (int c = 0; c < NC; ++c) {
        const int s = c & 1;
        if (c + 1 < NC) {
            load_chunk(c + 1, s ^ 1);
            CP_COMMIT();
            CP_WAIT(1);
        } else {
            CP_WAIT(0);
        }
        __syncthreads();

        const __half* ash = sAh[s];
        const __half* asl = sAl[s];
        const __half* bsh = sBh[s];
        const __half* bsl = sBl[s];

        #pragma unroll
        for (int k16 = 0; k16 < KT / 16; ++k16) {
            const int kc = k16 * 16 + 2 * tg;
            uint32_t a_h[4][4], a_l[4][4];
            #pragma unroll
            for (int i = 0; i < 4; ++i) {
                const int row = wm + i * 16 + g;
                a_h[i][0] = *(const uint32_t*)(ash + row * LDH + kc);
                a_h[i][1] = *(const uint32_t*)(ash + (row + 8) * LDH + kc);
                a_h[i][2] = *(const uint32_t*)(ash + row * LDH + kc + 8);
                a_h[i][3] = *(const uint32_t*)(ash + (row + 8) * LDH + kc + 8);
                a_l[i][0] = *(const uint32_t*)(asl + row * LDH + kc);
                a_l[i][1] = *(const uint32_t*)(asl + (row + 8) * LDH + kc);
                a_l[i][2] = *(const uint32_t*)(asl + row * LDH + kc + 8);
                a_l[i][3] = *(const uint32_t*)(asl + (row + 8) * LDH + kc + 8);
            }
            uint32_t b_h[4][2], b_l[4][2];
            #pragma unroll
            for (int j = 0; j < 4; ++j) {
                const int col = wn + j * 8 + g;
                b_h[j][0] = *(const uint32_t*)(bsh + col * LDH + kc);
                b_h[j][1] = *(const uint32_t*)(bsh + col * LDH + kc + 8);
                b_l[j][0] = *(const uint32_t*)(bsl + col * LDH + kc);
                b_l[j][1] = *(const uint32_t*)(bsl + col * LDH + kc + 8);
            }
            #pragma unroll
            for (int i = 0; i < 4; ++i)
                #pragma unroll
                for (int j = 0; j < 4; ++j) {
                    mma16(acc[i][j], a_h[i][0], a_h[i][1], a_h[i][2], a_h[i][3], b_h[j][0], b_h[j][1]);
                    mma16(acc[i][j], a_l[i][0], a_l[i][1], a_l[i][2], a_l[i][3], b_h[j][0], b_h[j][1]);
                    mma16(acc[i][j], a_h[i][0], a_h[i][1], a_h[i][2], a_h[i][3], b_l[j][0], b_l[j][1]);
                }
        }
        __syncthreads();
    }

    // ---- epilogue: c0,c1 -> (row, col+0/1); c2,c3 -> (row+8, col+0/1)
    #pragma unroll
    for (int j = 0; j < 4; ++j) {
        const int col = bn + wn + j * 8 + 2 * tg;
        const float b0 = bias[col], b1 = bias[col + 1];
        float p0 = 0.f, p1 = 0.f;
        if (EPI == 1) { p0 = g_probs[col]; p1 = g_probs[col + 1]; }
        #pragma unroll
        for (int i = 0; i < 4; ++i) {
            const int row = bm + wm + i * 16 + g;
            float v0 = acc[i][j][0] + b0;
            float v1 = acc[i][j][1] + b1;
            float v2 = acc[i][j][2] + b0;
            float v3 = acc[i][j][3] + b1;
            if (EPI == 1) {
                v0 = tanhf(v0 + p0); v1 = tanhf(v1 + p1);
                v2 = tanhf(v2 + p0); v3 = tanhf(v3 + p1);
            } else {
                v0 = fmaxf(v0, 0.f); v1 = fmaxf(v1, 0.f);
                v2 = fmaxf(v2, 0.f); v3 = fmaxf(v3, 0.f);
            }
            if (EPI == 2) {
                *reinterpret_cast<float2*>(&Cf[(size_t)row * N + col])       = make_float2(v0, v1);
                *reinterpret_cast<float2*>(&Cf[(size_t)(row + 8) * N + col]) = make_float2(v2, v3);
            } else {
                __half h0, h1, h2, h3, l0, l1, l2, l3;
                fsplit(v0, h0, l0); fsplit(v1, h1, l1);
                fsplit(v2, h2, l2); fsplit(v3, h3, l3);
                *reinterpret_cast<__half2*>(&Ch[(size_t)row * N + col])       = __halves2half2(h0, h1);
                *reinterpret_cast<__half2*>(&Ch[(size_t)(row + 8) * N + col]) = __halves2half2(h2, h3);
                *reinterpret_cast<__half2*>(&Cl[(size_t)row * N + col])       = __halves2half2(l0, l1);
                *reinterpret_cast<__half2*>(&Cl[(size_t)(row + 8) * N + col]) = __halves2half2(l2, l3);
            }
        }
    }
}

// ---------------- host --------------------------------------------------------------
extern "C" void kernel_launch(void* const* d_in, const int* in_sizes, int n_in,
                              void* d_out, int out_size) {
    const float* x    = (const float*)d_in[0];
    const float* w0   = (const float*)d_in[1];
    const float* b0   = (const float*)d_in[2];
    const float* w1   = (const float*)d_in[3];
    const float* b1   = (const float*)d_in[4];
    const float* tw   = (const float*)d_in[5];
    const float* cw   = (const float*)d_in[6];
    const float* cb   = (const float*)d_in[7];
    const float* wout = (const float*)d_in[8];
    const float* bout = (const float*)d_in[9];
    float* out = (float*)d_out;

    __half *xh, *xl, *h1h, *h1l, *h2h, *h2l;
    __half *w0h, *w0l, *w1h, *w1l, *cwh, *cwl, *woh, *wol;
    cudaGetSymbolAddress((void**)&xh,  g_xh);   cudaGetSymbolAddress((void**)&xl,  g_xl);
    cudaGetSymbolAddress((void**)&h1h, g_h1h);  cudaGetSymbolAddress((void**)&h1l, g_h1l);
    cudaGetSymbolAddress((void**)&h2h, g_h2h);  cudaGetSymbolAddress((void**)&h2l, g_h2l);
    cudaGetSymbolAddress((void**)&w0h, g_w0h);  cudaGetSymbolAddress((void**)&w0l, g_w0l);
    cudaGetSymbolAddress((void**)&w1h, g_w1h);  cudaGetSymbolAddress((void**)&w1l, g_w1l);
    cudaGetSymbolAddress((void**)&cwh, g_cwh);  cudaGetSymbolAddress((void**)&cwl, g_cwl);
    cudaGetSymbolAddress((void**)&woh, g_woh);  cudaGetSymbolAddress((void**)&wol, g_wol);

    cudaFuncSetAttribute(mma_gemm<0>, cudaFuncAttributeMaxDynamicSharedMemorySize, SMEM_TOTAL);
    cudaFuncSetAttribute(mma_gemm<1>, cudaFuncAttributeMaxDynamicSharedMemorySize, SMEM_TOTAL);
    cudaFuncSetAttribute(mma_gemm<2>, cudaFuncAttributeMaxDynamicSharedMemorySize, SMEM_TOTAL);

    probs_kernel<<<HH, 256>>>(tw);
    {
        const int n4 = BB * DIN / 4;
        splitx_kernel<<<(n4 + 255) / 256, 256>>>((const float4*)x, (__half2*)xh, (__half2*)xl, n4);
    }
    tsplit_kernel<<<dim3(HH / 32,   DIN / 32), dim3(32, 8)>>>(w0,   w0h, w0l, DIN, HH);
    tsplit_kernel<<<dim3(HH / 32,   HH  / 32), dim3(32, 8)>>>(w1,   w1h, w1l, HH,  HH);
    tsplit_kernel<<<dim3(HH / 32,   HH  / 32), dim3(32, 8)>>>(cw,   cwh, cwl, HH,  HH);
    tsplit_kernel<<<dim3(DOUT / 32, HH  / 32), dim3(32, 8)>>>(wout, woh, wol, HH,  DOUT);

    mma_gemm<0><<<dim3(HH / 128,   BB / 128), 256, SMEM_TOTAL>>>(
        xh,  xl,  w0h, w0l, b0,   h1h, h1l, nullptr, BB, HH,   DIN);
    mma_gemm<0><<<dim3(HH / 128,   BB / 128), 256, SMEM_TOTAL>>>(
        h1h, h1l, w1h, w1l, b1,   h2h, h2l, nullptr, BB, HH,   HH);
    mma_gemm<1><<<dim3(HH / 128,   BB / 128), 256, SMEM_TOTAL>>>(
        h2h, h2l, cwh, cwl, cb,   xh,  xl,  nullptr, BB, HH,   HH);
    mma_gemm<2><<<dim3(DOUT / 128, BB / 128), 256, SMEM_TOTAL>>>(
        xh,  xl,  woh, wol, bout, nullptr, nullptr, out, BB, DOUT, HH);
}

// round 6
// speedup vs baseline: 1.9420x; 1.0388x over previous
#include <cuda_runtime.h>
#include <cuda_fp16.h>
#include <math.h>
#include <stdint.h>

#define BB   16384
#define DIN  1024
#define HH   1024
#define DOUT 256
#define DEPTH 7

// ---------------- device scratch (fp16 hi/lo operand arrays) ------------------
__device__ __half g_xh[(size_t)BB * HH],  g_xl[(size_t)BB * HH];    // x split; reused for h3
__device__ __half g_h1h[(size_t)BB * HH], g_h1l[(size_t)BB * HH];
__device__ __half g_h2h[(size_t)BB * HH], g_h2l[(size_t)BB * HH];
__device__ __half g_w0h[(size_t)HH * DIN],  g_w0l[(size_t)HH * DIN];   // [N][K]
__device__ __half g_w1h[(size_t)HH * HH],   g_w1l[(size_t)HH * HH];
__device__ __half g_cwh[(size_t)HH * HH],   g_cwl[(size_t)HH * HH];
__device__ __half g_woh[(size_t)DOUT * HH], g_wol[(size_t)DOUT * HH];
__device__ float  g_probs[HH];

// ---------------- helpers -------------------------------------------------------
__device__ __forceinline__ uint32_t s2u(const void* p) {
    uint32_t a;
    asm("{ .reg .u64 t; cvta.to.shared.u64 t, %1; cvt.u32.u64 %0, t; }" : "=r"(a) : "l"(p));
    return a;
}
__device__ __forceinline__ void mma16(float c[4],
                                      uint32_t a0, uint32_t a1, uint32_t a2, uint32_t a3,
                                      uint32_t b0, uint32_t b1) {
    asm volatile(
        "mma.sync.aligned.m16n8k16.row.col.f32.f16.f16.f32 "
        "{%0,%1,%2,%3}, {%4,%5,%6,%7}, {%8,%9}, {%0,%1,%2,%3};"
        : "+f"(c[0]), "+f"(c[1]), "+f"(c[2]), "+f"(c[3])
        : "r"(a0), "r"(a1), "r"(a2), "r"(a3), "r"(b0), "r"(b1));
}
__device__ __forceinline__ void ldsm4(uint32_t& r0, uint32_t& r1, uint32_t& r2, uint32_t& r3,
                                      uint32_t addr) {
    asm volatile("ldmatrix.sync.aligned.m8n8.x4.shared.b16 {%0,%1,%2,%3}, [%4];"
                 : "=r"(r0), "=r"(r1), "=r"(r2), "=r"(r3) : "r"(addr));
}
__device__ __forceinline__ void cp16(uint32_t s, const void* g) {
    asm volatile("cp.async.cg.shared.global [%0], [%1], 16;" :: "r"(s), "l"(g));
}
#define CP_COMMIT() asm volatile("cp.async.commit_group;" ::: "memory")
#define CP_WAIT(n)  asm volatile("cp.async.wait_group %0;" :: "n"(n) : "memory")

__device__ __forceinline__ void fsplit(float v, __half& h, __half& l) {
    h = __float2half_rn(v);
    l = __float2half_rn(v - __half2float(h));
}

// ---------------- probs (tiny) ---------------------------------------------------
__global__ void probs_kernel(const float* __restrict__ tw) {
    __shared__ float st[2][HH];
    const int r = blockIdx.x, t = threadIdx.x;
    for (int i = t; i < HH; i += blockDim.x) st[0][i] = 0.03125f;
    __syncthreads();
    int cur = 0;
    #pragma unroll 1
    for (int d = 0; d < DEPTH; ++d)
        #pragma unroll 1
        for (int k = 0; k < 3; ++k) {
            const float ang = tw[((size_t)d * HH + r) * HH + k];
            const float c = cosf(ang), s = sinf(ang);
            const int nxt = cur ^ 1;
            for (int i = t; i < HH; i += blockDim.x)
                st[nxt][i] = c * st[cur][i]
                           - s * st[cur][(i + 1) & (HH - 1)]
                           + s * st[cur][(i - 1) & (HH - 1)];
            __syncthreads();
            cur = nxt;
        }
    if (t == 0) { const float v = st[cur][0]; g_probs[r] = v * v; }
}

// ---------------- x split: fp32 -> fp16 hi/lo -------------------------------------
__global__ void splitx_kernel(const float4* __restrict__ in,
                              __half2* __restrict__ oh, __half2* __restrict__ ol, int n4) {
    int i = blockIdx.x * blockDim.x + threadIdx.x;
    if (i >= n4) return;
    float4 v = in[i];
    __half h0, h1, h2, h3, l0, l1, l2, l3;
    fsplit(v.x, h0, l0); fsplit(v.y, h1, l1);
    fsplit(v.z, h2, l2); fsplit(v.w, h3, l3);
    oh[2 * i]     = __halves2half2(h0, h1);
    oh[2 * i + 1] = __halves2half2(h2, h3);
    ol[2 * i]     = __halves2half2(l0, l1);
    ol[2 * i + 1] = __halves2half2(l2, l3);
}

// ---------------- weight transpose + split: w[K][N] fp32 -> [N][K] fp16 h/l -------
__global__ void tsplit_kernel(const float* __restrict__ w,
                              __half* __restrict__ th, __half* __restrict__ tl,
                              int Kd, int Nd) {
    __shared__ float tile[32][33];
    const int nb = blockIdx.x * 32, kb = blockIdx.y * 32;
    const int tx = threadIdx.x, ty = threadIdx.y;   // 32 x 8
    #pragma unroll
    for (int i = 0; i < 32; i += 8)
        tile[ty + i][tx] = w[(size_t)(kb + ty + i) * Nd + nb + tx];
    __syncthreads();
    #pragma unroll
    for (int i = 0; i < 32; i += 8) {
        const float v = tile[tx][ty + i];
        __half h, l;
        fsplit(v, h, l);
        const size_t o = (size_t)(nb + ty + i) * Kd + kb + tx;
        th[o] = h;
        tl[o] = l;
    }
}

// ---------------- 3-product split-fp16 GEMM (ldmatrix + mma.sync m16n8k16) -------
// C[M,N] = epi((Ah+Al) @ (Bh+Bl)^T + bias [+probs]), dropping Al*Bl.
// A arrays [M][K] fp16; B arrays [N][K] fp16.
// CTA tile 128x128, KT=64, 256 threads (8 warps 2x4), warp tile 64x32.
#define KT      64
#define LDH     72                         // smem row stride in halves (conflict-free)
#define TILE_B  (128 * LDH * 2)            // 18432 bytes per (array, tile)
#define STAGE_B (4 * TILE_B)               // Ah,Al,Bh,Bl = 73728
#define SMEM_TOTAL (2 * STAGE_B)           // 147456

template <int EPI>   // 0: relu->split   1: tanh(+probs)->split   2: relu->fp32
__global__ void __launch_bounds__(256, 1)
mma_gemm(const __half* __restrict__ Ah, const __half* __restrict__ Al,
         const __half* __restrict__ Bh, const __half* __restrict__ Bl,
         const float* __restrict__ bias,
         __half* __restrict__ Ch, __half* __restrict__ Cl,
         float* __restrict__ Cf,
         int M, int N, int K)
{
    extern __shared__ __align__(16) char smem[];
    const int tid  = threadIdx.x;
    const int lane = tid & 31;
    const int warp = tid >> 5;
    const int wm   = (warp & 1) * 64;
    const int wn   = (warp >> 1) * 32;
    const int g    = lane >> 2;     // 0..7
    const int tg   = lane & 3;      // 0..3

    const int bm = blockIdx.y * 128;
    const int bn = blockIdx.x * 128;

    const uint32_t sA_h[2] = { s2u(smem),              s2u(smem + STAGE_B) };
    const uint32_t sA_l[2] = { sA_h[0] + TILE_B,       sA_h[1] + TILE_B };
    const uint32_t sB_h[2] = { sA_h[0] + 2 * TILE_B,   sA_h[1] + 2 * TILE_B };
    const uint32_t sB_l[2] = { sA_h[0] + 3 * TILE_B,   sA_h[1] + 3 * TILE_B };

    // ldmatrix lane-relative byte offsets
    // A x4: matrices (m0-7,k0-7),(m8-15,k0-7),(m0-7,k8-15),(m8-15,k8-15)
    const int rowA = wm + (lane & 7) + 8 * ((lane >> 3) & 1);
    const int khA  = 8 * (lane >> 4);
    const uint32_t offA = (uint32_t)(rowA * LDH + khA) * 2;
    // B x4: matrices = col-groups wn+8q (q=lane>>3), row = col, k 0-7
    const int colB = wn + 8 * (lane >> 3) + (lane & 7);
    const uint32_t offB = (uint32_t)(colB * LDH) * 2;

    float acc[4][4][4];
    #pragma unroll
    for (int i = 0; i < 4; ++i)
        #pragma unroll
        for (int j = 0; j < 4; ++j)
            #pragma unroll
            for (int q = 0; q < 4; ++q) acc[i][j][q] = 0.f;

    // cp.async mapping: 1024 16B-segments per (array, tile); 4 per thread per array.
    const int srow = tid >> 3;          // 0..31 (+32*r)
    const int sseg = tid & 7;           // halves sseg*8

    auto load_chunk = [&](int c, int s) {
        const int k0 = c * KT;
        #pragma unroll
        for (int r = 0; r < 4; ++r) {
            const int row = srow + 32 * r;
            const uint32_t so = (uint32_t)(row * LDH + sseg * 8) * 2;
            const size_t  ga = (size_t)(bm + row) * K + k0 + sseg * 8;
            const size_t  gb = (size_t)(bn + row) * K + k0 + sseg * 8;
            cp16(sA_h[s] + so, Ah + ga);
            cp16(sA_l[s] + so, Al + ga);
            cp16(sB_h[s] + so, Bh + gb);
            cp16(sB_l[s] + so, Bl + gb);
        }
    };

    const int NC = K / KT;
    load_chunk(0, 0);
    CP_COMMIT();

    #pragma unroll 1
    for (int c = 0; c < NC; ++c) {
        const int s = c & 1;
        if (c + 1 < NC) {
            load_chunk(c + 1, s ^ 1);
            CP_COMMIT();
            CP_WAIT(1);
        } else {
            CP_WAIT(0);
        }
        __syncthreads();

        #pragma unroll
        for (int k16 = 0; k16 < KT / 16; ++k16) {
            const uint32_t kb = (uint32_t)(k16 * 16) * 2;   // byte advance along k

            uint32_t a_h[4][4], a_l[4][4];
            #pragma unroll
            for (int i = 0; i < 4; ++i) {
                const uint32_t ao = offA + (uint32_t)(i * 16 * LDH) * 2 + kb;
                ldsm4(a_h[i][0], a_h[i][1], a_h[i][2], a_h[i][3], sA_h[s] + ao);
                ldsm4(a_l[i][0], a_l[i][1], a_l[i][2], a_l[i][3], sA_l[s] + ao);
            }
            uint32_t b_h[4][2], b_l[4][2];
            ldsm4(b_h[0][0], b_h[1][0], b_h[2][0], b_h[3][0], sB_h[s] + offB + kb);
            ldsm4(b_h[0][1], b_h[1][1], b_h[2][1], b_h[3][1], sB_h[s] + offB + kb + 16);
            ldsm4(b_l[0][0], b_l[1][0], b_l[2][0], b_l[3][0], sB_l[s] + offB + kb);
            ldsm4(b_l[0][1], b_l[1][1], b_l[2][1], b_l[3][1], sB_l[s] + offB + kb + 16);

            #pragma unroll
            for (int i = 0; i < 4; ++i)
                #pragma unroll
                for (int j = 0; j < 4; ++j) {
                    mma16(acc[i][j], a_h[i][0], a_h[i][1], a_h[i][2], a_h[i][3], b_h[j][0], b_h[j][1]);
                    mma16(acc[i][j], a_l[i][0], a_l[i][1], a_l[i][2], a_l[i][3], b_h[j][0], b_h[j][1]);
                    mma16(acc[i][j], a_h[i][0], a_h[i][1], a_h[i][2], a_h[i][3], b_l[j][0], b_l[j][1]);
                }
        }
        __syncthreads();
    }

    // ---- epilogue ----
    #pragma unroll
    for (int j = 0; j < 4; ++j) {
        const int col = bn + wn + j * 8 + 2 * tg;
        const float b0 = bias[col], b1 = bias[col + 1];
        float p0 = 0.f, p1 = 0.f;
        if (EPI == 1) { p0 = g_probs[col]; p1 = g_probs[col + 1]; }
        #pragma unroll
        for (int i = 0; i < 4; ++i) {
            const int row = bm + wm + i * 16 + g;
            float v0 = acc[i][j][0] + b0;
            float v1 = acc[i][j][1] + b1;
            float v2 = acc[i][j][2] + b0;
            float v3 = acc[i][j][3] + b1;
            if (EPI == 1) {
                v0 = tanhf(v0 + p0); v1 = tanhf(v1 + p1);
                v2 = tanhf(v2 + p0); v3 = tanhf(v3 + p1);
            } else {
                v0 = fmaxf(v0, 0.f); v1 = fmaxf(v1, 0.f);
                v2 = fmaxf(v2, 0.f); v3 = fmaxf(v3, 0.f);
            }
            if (EPI == 2) {
                *reinterpret_cast<float2*>(&Cf[(size_t)row * N + col])       = make_float2(v0, v1);
                *reinterpret_cast<float2*>(&Cf[(size_t)(row + 8) * N + col]) = make_float2(v2, v3);
            } else {
                __half h0, h1, h2, h3, l0, l1, l2, l3;
                fsplit(v0, h0, l0); fsplit(v1, h1, l1);
                fsplit(v2, h2, l2); fsplit(v3, h3, l3);
                *reinterpret_cast<__half2*>(&Ch[(size_t)row * N + col])       = __halves2half2(h0, h1);
                *reinterpret_cast<__half2*>(&Ch[(size_t)(row + 8) * N + col]) = __halves2half2(h2, h3);
                *reinterpret_cast<__half2*>(&Cl[(size_t)row * N + col])       = __halves2half2(l0, l1);
                *reinterpret_cast<__half2*>(&Cl[(size_t)(row + 8) * N + col]) = __halves2half2(l2, l3);
            }
        }
    }
}

// ---------------- host --------------------------------------------------------------
extern "C" void kernel_launch(void* const* d_in, const int* in_sizes, int n_in,
                              void* d_out, int out_size) {
    const float* x    = (const float*)d_in[0];
    const float* w0   = (const float*)d_in[1];
    const float* b0   = (const float*)d_in[2];
    const float* w1   = (const float*)d_in[3];
    const float* b1   = (const float*)d_in[4];
    const float* tw   = (const float*)d_in[5];
    const float* cw   = (const float*)d_in[6];
    const float* cb   = (const float*)d_in[7];
    const float* wout = (const float*)d_in[8];
    const float* bout = (const float*)d_in[9];
    float* out = (float*)d_out;

    __half *xh, *xl, *h1h, *h1l, *h2h, *h2l;
    __half *w0h, *w0l, *w1h, *w1l, *cwh, *cwl, *woh, *wol;
    cudaGetSymbolAddress((void**)&xh,  g_xh);   cudaGetSymbolAddress((void**)&xl,  g_xl);
    cudaGetSymbolAddress((void**)&h1h, g_h1h);  cudaGetSymbolAddress((void**)&h1l, g_h1l);
    cudaGetSymbolAddress((void**)&h2h, g_h2h);  cudaGetSymbolAddress((void**)&h2l, g_h2l);
    cudaGetSymbolAddress((void**)&w0h, g_w0h);  cudaGetSymbolAddress((void**)&w0l, g_w0l);
    cudaGetSymbolAddress((void**)&w1h, g_w1h);  cudaGetSymbolAddress((void**)&w1l, g_w1l);
    cudaGetSymbolAddress((void**)&cwh, g_cwh);  cudaGetSymbolAddress((void**)&cwl, g_cwl);
    cudaGetSymbolAddress((void**)&woh, g_woh);  cudaGetSymbolAddress((void**)&wol, g_wol);

    cudaFuncSetAttribute(mma_gemm<0>, cudaFuncAttributeMaxDynamicSharedMemorySize, SMEM_TOTAL);
    cudaFuncSetAttribute(mma_gemm<1>, cudaFuncAttributeMaxDynamicSharedMemorySize, SMEM_TOTAL);
    cudaFuncSetAttribute(mma_gemm<2>, cudaFuncAttributeMaxDynamicSharedMemorySize, SMEM_TOTAL);

    probs_kernel<<<HH, 256>>>(tw);
    {
        const int n4 = BB * DIN / 4;
        splitx_kernel<<<(n4 + 255) / 256, 256>>>((const float4*)x, (__half2*)xh, (__half2*)xl, n4);
    }
    tsplit_kernel<<<dim3(HH / 32,   DIN / 32), dim3(32, 8)>>>(w0,   w0h, w0l, DIN, HH);
    tsplit_kernel<<<dim3(HH / 32,   HH  / 32), dim3(32, 8)>>>(w1,   w1h, w1l, HH,  HH);
    tsplit_kernel<<<dim3(HH / 32,   HH  / 32), dim3(32, 8)>>>(cw,   cwh, cwl, HH,  HH);
    tsplit_kernel<<<dim3(DOUT / 32, HH  / 32), dim3(32, 8)>>>(wout, woh, wol, HH,  DOUT);

    mma_gemm<0><<<dim3(HH / 128,   BB / 128), 256, SMEM_TOTAL>>>(
        xh,  xl,  w0h, w0l, b0,   h1h, h1l, nullptr, BB, HH,   DIN);
    mma_gemm<0><<<dim3(HH / 128,   BB / 128), 256, SMEM_TOTAL>>>(
        h1h, h1l, w1h, w1l, b1,   h2h, h2l, nullptr, BB, HH,   HH);
    mma_gemm<1><<<dim3(HH / 128,   BB / 128), 256, SMEM_TOTAL>>>(
        h2h, h2l, cwh, cwl, cb,   xh,  xl,  nullptr, BB, HH,   HH);
    mma_gemm<2><<<dim3(DOUT / 128, BB / 128), 256, SMEM_TOTAL>>>(
        xh,  xl,  woh, wol, bout, nullptr, nullptr, out, BB, DOUT, HH);
}

// round 7
// speedup vs baseline: 1.9461x; 1.0021x over previous
#include <cuda_runtime.h>
#include <cuda_fp16.h>
#include <math.h>
#include <stdint.h>

#define BB   16384
#define DIN  1024
#define HH   1024
#define DOUT 256
#define DEPTH 7

// ---------------- device scratch (fp16 hi/lo operand arrays) ------------------
__device__ __half g_xh[(size_t)BB * HH],  g_xl[(size_t)BB * HH];    // x split; reused for h3
__device__ __half g_h1h[(size_t)BB * HH], g_h1l[(size_t)BB * HH];
__device__ __half g_h2h[(size_t)BB * HH], g_h2l[(size_t)BB * HH];
__device__ __half g_w0h[(size_t)HH * DIN],  g_w0l[(size_t)HH * DIN];   // [N][K]
__device__ __half g_w1h[(size_t)HH * HH],   g_w1l[(size_t)HH * HH];
__device__ __half g_cwh[(size_t)HH * HH],   g_cwl[(size_t)HH * HH];
__device__ __half g_woh[(size_t)DOUT * HH], g_wol[(size_t)DOUT * HH];
__device__ float  g_probs[HH];

// ---------------- helpers -------------------------------------------------------
__device__ __forceinline__ uint32_t s2u(const void* p) {
    uint32_t a;
    asm("{ .reg .u64 t; cvta.to.shared.u64 t, %1; cvt.u32.u64 %0, t; }" : "=r"(a) : "l"(p));
    return a;
}
__device__ __forceinline__ void mma16(float c[4],
                                      uint32_t a0, uint32_t a1, uint32_t a2, uint32_t a3,
                                      uint32_t b0, uint32_t b1) {
    asm volatile(
        "mma.sync.aligned.m16n8k16.row.col.f32.f16.f16.f32 "
        "{%0,%1,%2,%3}, {%4,%5,%6,%7}, {%8,%9}, {%0,%1,%2,%3};"
        : "+f"(c[0]), "+f"(c[1]), "+f"(c[2]), "+f"(c[3])
        : "r"(a0), "r"(a1), "r"(a2), "r"(a3), "r"(b0), "r"(b1));
}
// fp16-accumulate variant: c = 2 regs (4 halves)
__device__ __forceinline__ void mma16h(uint32_t c[2],
                                       uint32_t a0, uint32_t a1, uint32_t a2, uint32_t a3,
                                       uint32_t b0, uint32_t b1) {
    asm volatile(
        "mma.sync.aligned.m16n8k16.row.col.f16.f16.f16.f16 "
        "{%0,%1}, {%2,%3,%4,%5}, {%6,%7}, {%0,%1};"
        : "+r"(c[0]), "+r"(c[1])
        : "r"(a0), "r"(a1), "r"(a2), "r"(a3), "r"(b0), "r"(b1));
}
__device__ __forceinline__ void ldsm4(uint32_t& r0, uint32_t& r1, uint32_t& r2, uint32_t& r3,
                                      uint32_t addr) {
    asm volatile("ldmatrix.sync.aligned.m8n8.x4.shared.b16 {%0,%1,%2,%3}, [%4];"
                 : "=r"(r0), "=r"(r1), "=r"(r2), "=r"(r3) : "r"(addr));
}
__device__ __forceinline__ void cp16(uint32_t s, const void* g) {
    asm volatile("cp.async.cg.shared.global [%0], [%1], 16;" :: "r"(s), "l"(g));
}
#define CP_COMMIT() asm volatile("cp.async.commit_group;" ::: "memory")
#define CP_WAIT(n)  asm volatile("cp.async.wait_group %0;" :: "n"(n) : "memory")

__device__ __forceinline__ void fsplit(float v, __half& h, __half& l) {
    h = __float2half_rn(v);
    l = __float2half_rn(v - __half2float(h));
}

// ---------------- probs (tiny) ---------------------------------------------------
__global__ void probs_kernel(const float* __restrict__ tw) {
    __shared__ float st[2][HH];
    const int r = blockIdx.x, t = threadIdx.x;
    for (int i = t; i < HH; i += blockDim.x) st[0][i] = 0.03125f;
    __syncthreads();
    int cur = 0;
    #pragma unroll 1
    for (int d = 0; d < DEPTH; ++d)
        #pragma unroll 1
        for (int k = 0; k < 3; ++k) {
            const float ang = tw[((size_t)d * HH + r) * HH + k];
            const float c = cosf(ang), s = sinf(ang);
            const int nxt = cur ^ 1;
            for (int i = t; i < HH; i += blockDim.x)
                st[nxt][i] = c * st[cur][i]
                           - s * st[cur][(i + 1) & (HH - 1)]
                           + s * st[cur][(i - 1) & (HH - 1)];
            __syncthreads();
            cur = nxt;
        }
    if (t == 0) { const float v = st[cur][0]; g_probs[r] = v * v; }
}

// ---------------- x split: fp32 -> fp16 hi/lo -------------------------------------
__global__ void splitx_kernel(const float4* __restrict__ in,
                              __half2* __restrict__ oh, __half2* __restrict__ ol, int n4) {
    int i = blockIdx.x * blockDim.x + threadIdx.x;
    if (i >= n4) return;
    float4 v = in[i];
    __half h0, h1, h2, h3, l0, l1, l2, l3;
    fsplit(v.x, h0, l0); fsplit(v.y, h1, l1);
    fsplit(v.z, h2, l2); fsplit(v.w, h3, l3);
    oh[2 * i]     = __halves2half2(h0, h1);
    oh[2 * i + 1] = __halves2half2(h2, h3);
    ol[2 * i]     = __halves2half2(l0, l1);
    ol[2 * i + 1] = __halves2half2(l2, l3);
}

// ---------------- weight transpose + split: w[K][N] fp32 -> [N][K] fp16 h/l -------
__global__ void tsplit_kernel(const float* __restrict__ w,
                              __half* __restrict__ th, __half* __restrict__ tl,
                              int Kd, int Nd) {
    __shared__ float tile[32][33];
    const int nb = blockIdx.x * 32, kb = blockIdx.y * 32;
    const int tx = threadIdx.x, ty = threadIdx.y;   // 32 x 8
    #pragma unroll
    for (int i = 0; i < 32; i += 8)
        tile[ty + i][tx] = w[(size_t)(kb + ty + i) * Nd + nb + tx];
    __syncthreads();
    #pragma unroll
    for (int i = 0; i < 32; i += 8) {
        const float v = tile[tx][ty + i];
        __half h, l;
        fsplit(v, h, l);
        const size_t o = (size_t)(nb + ty + i) * Kd + kb + tx;
        th[o] = h;
        tl[o] = l;
    }
}

// ---------------- 3-product split-fp16 GEMM (ldmatrix + mma.sync m16n8k16) -------
// hh product -> fp32 accum; cross products (Al*Bh, Ah*Bl) -> fp16 accum (2x rate).
// C[M,N] = epi(A@B^T + bias [+probs]); A [M][K] fp16 h/l, B [N][K] fp16 h/l.
// CTA tile 128x128, KT=64, 256 threads (8 warps 2x4), warp tile 64x32.
#define KT      64
#define LDH     72
#define TILE_B  (128 * LDH * 2)
#define STAGE_B (4 * TILE_B)
#define SMEM_TOTAL (2 * STAGE_B)           // 147456

template <int EPI>   // 0: relu->split   1: tanh(+probs)->split   2: relu->fp32
__global__ void __launch_bounds__(256, 1)
mma_gemm(const __half* __restrict__ Ah, const __half* __restrict__ Al,
         const __half* __restrict__ Bh, const __half* __restrict__ Bl,
         const float* __restrict__ bias,
         __half* __restrict__ Ch, __half* __restrict__ Cl,
         float* __restrict__ Cf,
         int M, int N, int K)
{
    extern __shared__ __align__(16) char smem[];
    const int tid  = threadIdx.x;
    const int lane = tid & 31;
    const int warp = tid >> 5;
    const int wm   = (warp & 1) * 64;
    const int wn   = (warp >> 1) * 32;
    const int g    = lane >> 2;
    const int tg   = lane & 3;

    const int bm = blockIdx.y * 128;
    const int bn = blockIdx.x * 128;

    const uint32_t sA_h[2] = { s2u(smem),              s2u(smem + STAGE_B) };
    const uint32_t sA_l[2] = { sA_h[0] + TILE_B,       sA_h[1] + TILE_B };
    const uint32_t sB_h[2] = { sA_h[0] + 2 * TILE_B,   sA_h[1] + 2 * TILE_B };
    const uint32_t sB_l[2] = { sA_h[0] + 3 * TILE_B,   sA_h[1] + 3 * TILE_B };

    const int rowA = wm + (lane & 7) + 8 * ((lane >> 3) & 1);
    const int khA  = 8 * (lane >> 4);
    const uint32_t offA = (uint32_t)(rowA * LDH + khA) * 2;
    const int colB = wn + 8 * (lane >> 3) + (lane & 7);
    const uint32_t offB = (uint32_t)(colB * LDH) * 2;

    float    acc[4][4][4];         // hh in fp32
    uint32_t accx[4][4][2];        // cross terms in fp16x2
    #pragma unroll
    for (int i = 0; i < 4; ++i)
        #pragma unroll
        for (int j = 0; j < 4; ++j) {
            #pragma unroll
            for (int q = 0; q < 4; ++q) acc[i][j][q] = 0.f;
            accx[i][j][0] = 0u; accx[i][j][1] = 0u;
        }

    const int srow = tid >> 3;
    const int sseg = tid & 7;

    auto load_chunk = [&](int c, int s) {
        const int k0 = c * KT;
        #pragma unroll
        for (int r = 0; r < 4; ++r) {
            const int row = srow + 32 * r;
            const uint32_t so = (uint32_t)(row * LDH + sseg * 8) * 2;
            const size_t  ga = (size_t)(bm + row) * K + k0 + sseg * 8;
            const size_t  gb = (size_t)(bn + row) * K + k0 + sseg * 8;
            cp16(sA_h[s] + so, Ah + ga);
            cp16(sA_l[s] + so, Al + ga);
            cp16(sB_h[s] + so, Bh + gb);
            cp16(sB_l[s] + so, Bl + gb);
        }
    };

    const int NC = K / KT;
    load_chunk(0, 0);
    CP_COMMIT();

    #pragma unroll 1
    for (int c = 0; c < NC; ++c) {
        const int s = c & 1;
        if (c + 1 < NC) {
            load_chunk(c + 1, s ^ 1);
            CP_COMMIT();
            CP_WAIT(1);
        } else {
            CP_WAIT(0);
        }
        __syncthreads();

        #pragma unroll
        for (int k16 = 0; k16 < KT / 16; ++k16) {
            const uint32_t kb = (uint32_t)(k16 * 16) * 2;

            uint32_t a_h[4][4], a_l[4][4];
            #pragma unroll
            for (int i = 0; i < 4; ++i) {
                const uint32_t ao = offA + (uint32_t)(i * 16 * LDH) * 2 + kb;
                ldsm4(a_h[i][0], a_h[i][1], a_h[i][2], a_h[i][3], sA_h[s] + ao);
                ldsm4(a_l[i][0], a_l[i][1], a_l[i][2], a_l[i][3], sA_l[s] + ao);
            }
            uint32_t b_h[4][2], b_l[4][2];
            ldsm4(b_h[0][0], b_h[1][0], b_h[2][0], b_h[3][0], sB_h[s] + offB + kb);
            ldsm4(b_h[0][1], b_h[1][1], b_h[2][1], b_h[3][1], sB_h[s] + offB + kb + 16);
            ldsm4(b_l[0][0], b_l[1][0], b_l[2][0], b_l[3][0], sB_l[s] + offB + kb);
            ldsm4(b_l[0][1], b_l[1][1], b_l[2][1], b_l[3][1], sB_l[s] + offB + kb + 16);

            #pragma unroll
            for (int i = 0; i < 4; ++i)
                #pragma unroll
                for (int j = 0; j < 4; ++j) {
                    mma16 (acc[i][j],  a_h[i][0], a_h[i][1], a_h[i][2], a_h[i][3], b_h[j][0], b_h[j][1]);
                    mma16h(accx[i][j], a_l[i][0], a_l[i][1], a_l[i][2], a_l[i][3], b_h[j][0], b_h[j][1]);
                    mma16h(accx[i][j], a_h[i][0], a_h[i][1], a_h[i][2], a_h[i][3], b_l[j][0], b_l[j][1]);
                }
        }
        __syncthreads();
    }

    // ---- epilogue ----
    #pragma unroll
    for (int j = 0; j < 4; ++j) {
        const int col = bn + wn + j * 8 + 2 * tg;
        const float b0 = bias[col], b1 = bias[col + 1];
        float p0 = 0.f, p1 = 0.f;
        if (EPI == 1) { p0 = g_probs[col]; p1 = g_probs[col + 1]; }
        #pragma unroll
        for (int i = 0; i < 4; ++i) {
            const int row = bm + wm + i * 16 + g;
            const float2 x0 = __half22float2(*(__half2*)&accx[i][j][0]);
            const float2 x1 = __half22float2(*(__half2*)&accx[i][j][1]);
            float v0 = acc[i][j][0] + x0.x + b0;
            float v1 = acc[i][j][1] + x0.y + b1;
            float v2 = acc[i][j][2] + x1.x + b0;
            float v3 = acc[i][j][3] + x1.y + b1;
            if (EPI == 1) {
                v0 = tanhf(v0 + p0); v1 = tanhf(v1 + p1);
                v2 = tanhf(v2 + p0); v3 = tanhf(v3 + p1);
            } else {
                v0 = fmaxf(v0, 0.f); v1 = fmaxf(v1, 0.f);
                v2 = fmaxf(v2, 0.f); v3 = fmaxf(v3, 0.f);
            }
            if (EPI == 2) {
                *reinterpret_cast<float2*>(&Cf[(size_t)row * N + col])       = make_float2(v0, v1);
                *reinterpret_cast<float2*>(&Cf[(size_t)(row + 8) * N + col]) = make_float2(v2, v3);
            } else {
                __half h0, h1, h2, h3, l0, l1, l2, l3;
                fsplit(v0, h0, l0); fsplit(v1, h1, l1);
                fsplit(v2, h2, l2); fsplit(v3, h3, l3);
                *reinterpret_cast<__half2*>(&Ch[(size_t)row * N + col])       = __halves2half2(h0, h1);
                *reinterpret_cast<__half2*>(&Ch[(size_t)(row + 8) * N + col]) = __halves2half2(h2, h3);
                *reinterpret_cast<__half2*>(&Cl[(size_t)row * N + col])       = __halves2half2(l0, l1);
                *reinterpret_cast<__half2*>(&Cl[(size_t)(row + 8) * N + col]) = __halves2half2(l2, l3);
            }
        }
    }
}

// ---------------- host --------------------------------------------------------------
extern "C" void kernel_launch(void* const* d_in, const int* in_sizes, int n_in,
                              void* d_out, int out_size) {
    const float* x    = (const float*)d_in[0];
    const float* w0   = (const float*)d_in[1];
    const float* b0   = (const float*)d_in[2];
    const float* w1   = (const float*)d_in[3];
    const float* b1   = (const float*)d_in[4];
    const float* tw   = (const float*)d_in[5];
    const float* cw   = (const float*)d_in[6];
    const float* cb   = (const float*)d_in[7];
    const float* wout = (const float*)d_in[8];
    const float* bout = (const float*)d_in[9];
    float* out = (float*)d_out;

    __half *xh, *xl, *h1h, *h1l, *h2h, *h2l;
    __half *w0h, *w0l, *w1h, *w1l, *cwh, *cwl, *woh, *wol;
    cudaGetSymbolAddress((void**)&xh,  g_xh);   cudaGetSymbolAddress((void**)&xl,  g_xl);
    cudaGetSymbolAddress((void**)&h1h, g_h1h);  cudaGetSymbolAddress((void**)&h1l, g_h1l);
    cudaGetSymbolAddress((void**)&h2h, g_h2h);  cudaGetSymbolAddress((void**)&h2l, g_h2l);
    cudaGetSymbolAddress((void**)&w0h, g_w0h);  cudaGetSymbolAddress((void**)&w0l, g_w0l);
    cudaGetSymbolAddress((void**)&w1h, g_w1h);  cudaGetSymbolAddress((void**)&w1l, g_w1l);
    cudaGetSymbolAddress((void**)&cwh, g_cwh);  cudaGetSymbolAddress((void**)&cwl, g_cwl);
    cudaGetSymbolAddress((void**)&woh, g_woh);  cudaGetSymbolAddress((void**)&wol, g_wol);

    cudaFuncSetAttribute(mma_gemm<0>, cudaFuncAttributeMaxDynamicSharedMemorySize, SMEM_TOTAL);
    cudaFuncSetAttribute(mma_gemm<1>, cudaFuncAttributeMaxDynamicSharedMemorySize, SMEM_TOTAL);
    cudaFuncSetAttribute(mma_gemm<2>, cudaFuncAttributeMaxDynamicSharedMemorySize, SMEM_TOTAL);

    probs_kernel<<<HH, 256>>>(tw);
    {
        const int n4 = BB * DIN / 4;
        splitx_kernel<<<(n4 + 255) / 256, 256>>>((const float4*)x, (__half2*)xh, (__half2*)xl, n4);
    }
    tsplit_kernel<<<dim3(HH / 32,   DIN / 32), dim3(32, 8)>>>(w0,   w0h, w0l, DIN, HH);
    tsplit_kernel<<<dim3(HH / 32,   HH  / 32), dim3(32, 8)>>>(w1,   w1h, w1l, HH,  HH);
    tsplit_kernel<<<dim3(HH / 32,   HH  / 32), dim3(32, 8)>>>(cw,   cwh, cwl, HH,  HH);
    tsplit_kernel<<<dim3(DOUT / 32, HH  / 32), dim3(32, 8)>>>(wout, woh, wol, HH,  DOUT);

    mma_gemm<0><<<dim3(HH / 128,   BB / 128), 256, SMEM_TOTAL>>>(
        xh,  xl,  w0h, w0l, b0,   h1h, h1l, nullptr, BB, HH,   DIN);
    mma_gemm<0><<<dim3(HH / 128,   BB / 128), 256, SMEM_TOTAL>>>(
        h1h, h1l, w1h, w1l, b1,   h2h, h2l, nullptr, BB, HH,   HH);
    mma_gemm<1><<<dim3(HH / 128,   BB / 128), 256, SMEM_TOTAL>>>(
        h2h, h2l, cwh, cwl, cb,   xh,  xl,  nullptr, BB, HH,   HH);
    mma_gemm<2><<<dim3(DOUT / 128, BB / 128), 256, SMEM_TOTAL>>>(
        xh,  xl,  woh, wol, bout, nullptr, nullptr, out, BB, DOUT, HH);
}

// round 8
// speedup vs baseline: 2.0900x; 1.0739x over previous
#include <cuda_runtime.h>
#include <cuda_fp16.h>
#include <math.h>
#include <stdint.h>

#define BB   16384
#define DIN  1024
#define HH   1024
#define DOUT 256
#define DEPTH 7

#define FLAG_CAP (1u << 22)
#define FLAG_T   128.0f

// ---------------- device scratch (fp16 hi/lo operand arrays) ------------------
__device__ __half g_xh[(size_t)BB * HH],  g_xl[(size_t)BB * HH];    // x split; reused for h3
__device__ __half g_h1h[(size_t)BB * HH], g_h1l[(size_t)BB * HH];
__device__ __half g_h2h[(size_t)BB * HH], g_h2l[(size_t)BB * HH];
__device__ __half g_w0h[(size_t)HH * DIN],  g_w0l[(size_t)HH * DIN];   // [N][K]
__device__ __half g_w1h[(size_t)HH * HH],   g_w1l[(size_t)HH * HH];
__device__ __half g_cwh[(size_t)HH * HH],   g_cwl[(size_t)HH * HH];
__device__ __half g_woh[(size_t)DOUT * HH], g_wol[(size_t)DOUT * HH];
__device__ float  g_probs[HH];
__device__ uint32_t g_flags[FLAG_CAP];
__device__ uint32_t g_flagn;

// ---------------- helpers -------------------------------------------------------
__device__ __forceinline__ uint32_t s2u(const void* p) {
    uint32_t a;
    asm("{ .reg .u64 t; cvta.to.shared.u64 t, %1; cvt.u32.u64 %0, t; }" : "=r"(a) : "l"(p));
    return a;
}
__device__ __forceinline__ void mma16(float c[4],
                                      uint32_t a0, uint32_t a1, uint32_t a2, uint32_t a3,
                                      uint32_t b0, uint32_t b1) {
    asm volatile(
        "mma.sync.aligned.m16n8k16.row.col.f32.f16.f16.f32 "
        "{%0,%1,%2,%3}, {%4,%5,%6,%7}, {%8,%9}, {%0,%1,%2,%3};"
        : "+f"(c[0]), "+f"(c[1]), "+f"(c[2]), "+f"(c[3])
        : "r"(a0), "r"(a1), "r"(a2), "r"(a3), "r"(b0), "r"(b1));
}
__device__ __forceinline__ void mma16h(uint32_t c[2],
                                       uint32_t a0, uint32_t a1, uint32_t a2, uint32_t a3,
                                       uint32_t b0, uint32_t b1) {
    asm volatile(
        "mma.sync.aligned.m16n8k16.row.col.f16.f16.f16.f16 "
        "{%0,%1}, {%2,%3,%4,%5}, {%6,%7}, {%0,%1};"
        : "+r"(c[0]), "+r"(c[1])
        : "r"(a0), "r"(a1), "r"(a2), "r"(a3), "r"(b0), "r"(b1));
}
__device__ __forceinline__ void ldsm4(uint32_t& r0, uint32_t& r1, uint32_t& r2, uint32_t& r3,
                                      uint32_t addr) {
    asm volatile("ldmatrix.sync.aligned.m8n8.x4.shared.b16 {%0,%1,%2,%3}, [%4];"
                 : "=r"(r0), "=r"(r1), "=r"(r2), "=r"(r3) : "r"(addr));
}
__device__ __forceinline__ void cp16(uint32_t s, const void* g) {
    asm volatile("cp.async.cg.shared.global [%0], [%1], 16;" :: "r"(s), "l"(g));
}
#define CP_COMMIT() asm volatile("cp.async.commit_group;" ::: "memory")
#define CP_WAIT(n)  asm volatile("cp.async.wait_group %0;" :: "n"(n) : "memory")

__device__ __forceinline__ void fsplit(float v, __half& h, __half& l) {
    h = __float2half_rn(v);
    l = __float2half_rn(v - __half2float(h));
}

// ---------------- probs (tiny) ---------------------------------------------------
__global__ void probs_kernel(const float* __restrict__ tw) {
    __shared__ float st[2][HH];
    const int r = blockIdx.x, t = threadIdx.x;
    for (int i = t; i < HH; i += blockDim.x) st[0][i] = 0.03125f;
    __syncthreads();
    int cur = 0;
    #pragma unroll 1
    for (int d = 0; d < DEPTH; ++d)
        #pragma unroll 1
        for (int k = 0; k < 3; ++k) {
            const float ang = tw[((size_t)d * HH + r) * HH + k];
            const float c = cosf(ang), s = sinf(ang);
            const int nxt = cur ^ 1;
            for (int i = t; i < HH; i += blockDim.x)
                st[nxt][i] = c * st[cur][i]
                           - s * st[cur][(i + 1) & (HH - 1)]
                           + s * st[cur][(i - 1) & (HH - 1)];
            __syncthreads();
            cur = nxt;
        }
    if (t == 0) { const float v = st[cur][0]; g_probs[r] = v * v; }
}

// ---------------- x split: fp32 -> fp16 hi/lo -------------------------------------
__global__ void splitx_kernel(const float4* __restrict__ in,
                              __half2* __restrict__ oh, __half2* __restrict__ ol, int n4) {
    int i = blockIdx.x * blockDim.x + threadIdx.x;
    if (i >= n4) return;
    float4 v = in[i];
    __half h0, h1, h2, h3, l0, l1, l2, l3;
    fsplit(v.x, h0, l0); fsplit(v.y, h1, l1);
    fsplit(v.z, h2, l2); fsplit(v.w, h3, l3);
    oh[2 * i]     = __halves2half2(h0, h1);
    oh[2 * i + 1] = __halves2half2(h2, h3);
    ol[2 * i]     = __halves2half2(l0, l1);
    ol[2 * i + 1] = __halves2half2(l2, l3);
}

// ---------------- weight transpose + split: w[K][N] fp32 -> [N][K] fp16 h/l -------
__global__ void tsplit_kernel(const float* __restrict__ w,
                              __half* __restrict__ th, __half* __restrict__ tl,
                              int Kd, int Nd) {
    __shared__ float tile[32][33];
    const int nb = blockIdx.x * 32, kb = blockIdx.y * 32;
    const int tx = threadIdx.x, ty = threadIdx.y;   // 32 x 8
    #pragma unroll
    for (int i = 0; i < 32; i += 8)
        tile[ty + i][tx] = w[(size_t)(kb + ty + i) * Nd + nb + tx];
    __syncthreads();
    #pragma unroll
    for (int i = 0; i < 32; i += 8) {
        const float v = tile[tx][ty + i];
        __half h, l;
        fsplit(v, h, l);
        const size_t o = (size_t)(nb + ty + i) * Kd + kb + tx;
        th[o] = h;
        tl[o] = l;
    }
}

// ---------------- repair: exact fp32 recompute of flagged tanh entries ------------
__global__ void repair_kernel(const __half2* __restrict__ h2h, const __half2* __restrict__ h2l,
                              const __half2* __restrict__ cwh, const __half2* __restrict__ cwl,
                              const float* __restrict__ cb,
                              __half* __restrict__ xh, __half* __restrict__ xl) {
    const uint32_t n = min(g_flagn, FLAG_CAP);
    const int lane = threadIdx.x & 31;
    const uint32_t warp = (blockIdx.x * blockDim.x + threadIdx.x) >> 5;
    const uint32_t nw = (gridDim.x * blockDim.x) >> 5;
    for (uint32_t e = warp; e < n; e += nw) {
        const uint32_t f = g_flags[e];
        const int row = f >> 10, col = f & 1023;
        const __half2* ah = h2h + (size_t)row * 512;
        const __half2* al = h2l + (size_t)row * 512;
        const __half2* wh = cwh + (size_t)col * 512;
        const __half2* wl = cwl + (size_t)col * 512;
        float s = 0.f;
        #pragma unroll 4
        for (int k = lane; k < 512; k += 32) {
            const float2 a0 = __half22float2(ah[k]);
            const float2 a1 = __half22float2(al[k]);
            const float2 w0 = __half22float2(wh[k]);
            const float2 w1 = __half22float2(wl[k]);
            s = fmaf(a0.x + a1.x, w0.x + w1.x, s);
            s = fmaf(a0.y + a1.y, w0.y + w1.y, s);
        }
        #pragma unroll
        for (int o = 16; o; o >>= 1) s += __shfl_xor_sync(0xFFFFFFFFu, s, o);
        if (lane == 0) {
            const float v = tanhf(s + cb[col] + g_probs[col]);
            __half h, l;
            fsplit(v, h, l);
            xh[(size_t)row * HH + col] = h;
            xl[(size_t)row * HH + col] = l;
        }
    }
}

// ---------------- split-fp16 GEMM (ldmatrix + mma.sync m16n8k16) ------------------
// PROD=3: hh(f32) + Al*Bh(f16) + Ah*Bl(f16).  PROD=2: hh + Ah*Bl.  PROD=1: hh only.
// EPI 0: relu->split   1: tanh(+probs)->split + flag |pre|<T   2: relu->fp32
#define KT      64
#define LDH     72
#define TILE_B  (128 * LDH * 2)
#define STAGE_B (4 * TILE_B)
#define SMEM_TOTAL (2 * STAGE_B)           // 147456

template <int EPI, int PROD>
__global__ void __launch_bounds__(256, 1)
mma_gemm(const __half* __restrict__ Ah, const __half* __restrict__ Al,
         const __half* __restrict__ Bh, const __half* __restrict__ Bl,
         const float* __restrict__ bias,
         __half* __restrict__ Ch, __half* __restrict__ Cl,
         float* __restrict__ Cf,
         int M, int N, int K)
{
    constexpr bool NEED_AL = (PROD == 3);
    constexpr bool NEED_BL = (PROD >= 2);

    extern __shared__ __align__(16) char smem[];
    const int tid  = threadIdx.x;
    const int lane = tid & 31;
    const int warp = tid >> 5;
    const int wm   = (warp & 1) * 64;
    const int wn   = (warp >> 1) * 32;
    const int g    = lane >> 2;
    const int tg   = lane & 3;

    const int bm = blockIdx.y * 128;
    const int bn = blockIdx.x * 128;

    const uint32_t sA_h[2] = { s2u(smem),              s2u(smem + STAGE_B) };
    const uint32_t sA_l[2] = { sA_h[0] + TILE_B,       sA_h[1] + TILE_B };
    const uint32_t sB_h[2] = { sA_h[0] + 2 * TILE_B,   sA_h[1] + 2 * TILE_B };
    const uint32_t sB_l[2] = { sA_h[0] + 3 * TILE_B,   sA_h[1] + 3 * TILE_B };

    const int rowA = wm + (lane & 7) + 8 * ((lane >> 3) & 1);
    const int khA  = 8 * (lane >> 4);
    const uint32_t offA = (uint32_t)(rowA * LDH + khA) * 2;
    const int colB = wn + 8 * (lane >> 3) + (lane & 7);
    const uint32_t offB = (uint32_t)(colB * LDH) * 2;

    float    acc[4][4][4];
    uint32_t accx[4][4][2];
    #pragma unroll
    for (int i = 0; i < 4; ++i)
        #pragma unroll
        for (int j = 0; j < 4; ++j) {
            #pragma unroll
            for (int q = 0; q < 4; ++q) acc[i][j][q] = 0.f;
            accx[i][j][0] = 0u; accx[i][j][1] = 0u;
        }

    const int srow = tid >> 3;
    const int sseg = tid & 7;

    auto load_chunk = [&](int c, int s) {
        const int k0 = c * KT;
        #pragma unroll
        for (int r = 0; r < 4; ++r) {
            const int row = srow + 32 * r;
            const uint32_t so = (uint32_t)(row * LDH + sseg * 8) * 2;
            const size_t  ga = (size_t)(bm + row) * K + k0 + sseg * 8;
            const size_t  gb = (size_t)(bn + row) * K + k0 + sseg * 8;
            cp16(sA_h[s] + so, Ah + ga);
            if (NEED_AL) cp16(sA_l[s] + so, Al + ga);
            cp16(sB_h[s] + so, Bh + gb);
            if (NEED_BL) cp16(sB_l[s] + so, Bl + gb);
        }
    };

    const int NC = K / KT;
    load_chunk(0, 0);
    CP_COMMIT();

    #pragma unroll 1
    for (int c = 0; c < NC; ++c) {
        const int s = c & 1;
        if (c + 1 < NC) {
            load_chunk(c + 1, s ^ 1);
            CP_COMMIT();
            CP_WAIT(1);
        } else {
            CP_WAIT(0);
        }
        __syncthreads();

        #pragma unroll
        for (int k16 = 0; k16 < KT / 16; ++k16) {
            const uint32_t kb = (uint32_t)(k16 * 16) * 2;

            uint32_t a_h[4][4], a_l[4][4];
            #pragma unroll
            for (int i = 0; i < 4; ++i) {
                const uint32_t ao = offA + (uint32_t)(i * 16 * LDH) * 2 + kb;
                ldsm4(a_h[i][0], a_h[i][1], a_h[i][2], a_h[i][3], sA_h[s] + ao);
                if (NEED_AL) ldsm4(a_l[i][0], a_l[i][1], a_l[i][2], a_l[i][3], sA_l[s] + ao);
            }
            uint32_t b_h[4][2], b_l[4][2];
            ldsm4(b_h[0][0], b_h[1][0], b_h[2][0], b_h[3][0], sB_h[s] + offB + kb);
            ldsm4(b_h[0][1], b_h[1][1], b_h[2][1], b_h[3][1], sB_h[s] + offB + kb + 16);
            if (NEED_BL) {
                ldsm4(b_l[0][0], b_l[1][0], b_l[2][0], b_l[3][0], sB_l[s] + offB + kb);
                ldsm4(b_l[0][1], b_l[1][1], b_l[2][1], b_l[3][1], sB_l[s] + offB + kb + 16);
            }

            #pragma unroll
            for (int i = 0; i < 4; ++i)
                #pragma unroll
                for (int j = 0; j < 4; ++j) {
                    mma16(acc[i][j], a_h[i][0], a_h[i][1], a_h[i][2], a_h[i][3], b_h[j][0], b_h[j][1]);
                    if (NEED_AL)
                        mma16h(accx[i][j], a_l[i][0], a_l[i][1], a_l[i][2], a_l[i][3], b_h[j][0], b_h[j][1]);
                    if (NEED_BL)
                        mma16h(accx[i][j], a_h[i][0], a_h[i][1], a_h[i][2], a_h[i][3], b_l[j][0], b_l[j][1]);
                }
        }
        __syncthreads();
    }

    // ---- epilogue ----
    #pragma unroll
    for (int j = 0; j < 4; ++j) {
        const int col = bn + wn + j * 8 + 2 * tg;
        const float b0 = bias[col], b1 = bias[col + 1];
        float p0 = 0.f, p1 = 0.f;
        if (EPI == 1) { p0 = g_probs[col]; p1 = g_probs[col + 1]; }
        #pragma unroll
        for (int i = 0; i < 4; ++i) {
            const int row = bm + wm + i * 16 + g;
            const float2 x0 = __half22float2(*(__half2*)&accx[i][j][0]);
            const float2 x1 = __half22float2(*(__half2*)&accx[i][j][1]);
            float v0 = acc[i][j][0] + x0.x + b0;
            float v1 = acc[i][j][1] + x0.y + b1;
            float v2 = acc[i][j][2] + x1.x + b0;
            float v3 = acc[i][j][3] + x1.y + b1;
            if (EPI == 1) {
                v0 += p0; v1 += p1; v2 += p0; v3 += p1;
                // flag low-magnitude pre-activations for exact repair
                auto push = [&](float pv, int r, int cc) {
                    if (fabsf(pv) < FLAG_T) {
                        const uint32_t idx = atomicAdd(&g_flagn, 1u);
                        if (idx < FLAG_CAP)
                            g_flags[idx] = ((uint32_t)r << 10) | (uint32_t)cc;
                    }
                };
                push(v0, row, col); push(v1, row, col + 1);
                push(v2, row + 8, col); push(v3, row + 8, col + 1);
                v0 = tanhf(v0); v1 = tanhf(v1);
                v2 = tanhf(v2); v3 = tanhf(v3);
            } else {
                v0 = fmaxf(v0, 0.f); v1 = fmaxf(v1, 0.f);
                v2 = fmaxf(v2, 0.f); v3 = fmaxf(v3, 0.f);
            }
            if (EPI == 2) {
                *reinterpret_cast<float2*>(&Cf[(size_t)row * N + col])       = make_float2(v0, v1);
                *reinterpret_cast<float2*>(&Cf[(size_t)(row + 8) * N + col]) = make_float2(v2, v3);
            } else {
                __half h0, h1, h2, h3, l0, l1, l2, l3;
                fsplit(v0, h0, l0); fsplit(v1, h1, l1);
                fsplit(v2, h2, l2); fsplit(v3, h3, l3);
                *reinterpret_cast<__half2*>(&Ch[(size_t)row * N + col])       = __halves2half2(h0, h1);
                *reinterpret_cast<__half2*>(&Ch[(size_t)(row + 8) * N + col]) = __halves2half2(h2, h3);
                *reinterpret_cast<__half2*>(&Cl[(size_t)row * N + col])       = __halves2half2(l0, l1);
                *reinterpret_cast<__half2*>(&Cl[(size_t)(row + 8) * N + col]) = __halves2half2(l2, l3);
            }
        }
    }
}

// ---------------- host --------------------------------------------------------------
extern "C" void kernel_launch(void* const* d_in, const int* in_sizes, int n_in,
                              void* d_out, int out_size) {
    const float* x    = (const float*)d_in[0];
    const float* w0   = (const float*)d_in[1];
    const float* b0   = (const float*)d_in[2];
    const float* w1   = (const float*)d_in[3];
    const float* b1   = (const float*)d_in[4];
    const float* tw   = (const float*)d_in[5];
    const float* cw   = (const float*)d_in[6];
    const float* cb   = (const float*)d_in[7];
    const float* wout = (const float*)d_in[8];
    const float* bout = (const float*)d_in[9];
    float* out = (float*)d_out;

    __half *xh, *xl, *h1h, *h1l, *h2h, *h2l;
    __half *w0h, *w0l, *w1h, *w1l, *cwh, *cwl, *woh, *wol;
    uint32_t* flagn;
    cudaGetSymbolAddress((void**)&xh,  g_xh);   cudaGetSymbolAddress((void**)&xl,  g_xl);
    cudaGetSymbolAddress((void**)&h1h, g_h1h);  cudaGetSymbolAddress((void**)&h1l, g_h1l);
    cudaGetSymbolAddress((void**)&h2h, g_h2h);  cudaGetSymbolAddress((void**)&h2l, g_h2l);
    cudaGetSymbolAddress((void**)&w0h, g_w0h);  cudaGetSymbolAddress((void**)&w0l, g_w0l);
    cudaGetSymbolAddress((void**)&w1h, g_w1h);  cudaGetSymbolAddress((void**)&w1l, g_w1l);
    cudaGetSymbolAddress((void**)&cwh, g_cwh);  cudaGetSymbolAddress((void**)&cwl, g_cwl);
    cudaGetSymbolAddress((void**)&woh, g_woh);  cudaGetSymbolAddress((void**)&wol, g_wol);
    cudaGetSymbolAddress((void**)&flagn, g_flagn);

    cudaFuncSetAttribute(mma_gemm<0,3>, cudaFuncAttributeMaxDynamicSharedMemorySize, SMEM_TOTAL);
    cudaFuncSetAttribute(mma_gemm<1,1>, cudaFuncAttributeMaxDynamicSharedMemorySize, SMEM_TOTAL);
    cudaFuncSetAttribute(mma_gemm<2,2>, cudaFuncAttributeMaxDynamicSharedMemorySize, SMEM_TOTAL);

    probs_kernel<<<HH, 256>>>(tw);
    {
        const int n4 = BB * DIN / 4;
        splitx_kernel<<<(n4 + 255) / 256, 256>>>((const float4*)x, (__half2*)xh, (__half2*)xl, n4);
    }
    tsplit_kernel<<<dim3(HH / 32,   DIN / 32), dim3(32, 8)>>>(w0,   w0h, w0l, DIN, HH);
    tsplit_kernel<<<dim3(HH / 32,   HH  / 32), dim3(32, 8)>>>(w1,   w1h, w1l, HH,  HH);
    tsplit_kernel<<<dim3(HH / 32,   HH  / 32), dim3(32, 8)>>>(cw,   cwh, cwl, HH,  HH);
    tsplit_kernel<<<dim3(DOUT / 32, HH  / 32), dim3(32, 8)>>>(wout, woh, wol, HH,  DOUT);
    cudaMemsetAsync(flagn, 0, sizeof(uint32_t));

    // layer 1: relu(x @ w0 + b0)            — 3 products
    mma_gemm<0,3><<<dim3(HH / 128,   BB / 128), 256, SMEM_TOTAL>>>(
        xh,  xl,  w0h, w0l, b0,   h1h, h1l, nullptr, BB, HH,   DIN);
    // layer 2: relu(h1 @ w1 + b1)           — 3 products
    mma_gemm<0,3><<<dim3(HH / 128,   BB / 128), 256, SMEM_TOTAL>>>(
        h1h, h1l, w1h, w1l, b1,   h2h, h2l, nullptr, BB, HH,   HH);
    // layer 3: tanh(h2 @ cw + cb + probs)   — hh only + flags
    mma_gemm<1,1><<<dim3(HH / 128,   BB / 128), 256, SMEM_TOTAL>>>(
        h2h, h2l, cwh, cwl, cb,   xh,  xl,  nullptr, BB, HH,   HH);
    // repair flagged entries exactly
    repair_kernel<<<512, 256>>>((const __half2*)h2h, (const __half2*)h2l,
                                (const __half2*)cwh, (const __half2*)cwl,
                                cb, xh, xl);
    // layer 4: relu(h3 @ wout + bout)       — 2 products (h3 lo ~ 0)
    mma_gemm<2,2><<<dim3(DOUT / 128, BB / 128), 256, SMEM_TOTAL>>>(
        xh,  xl,  woh, wol, bout, nullptr, nullptr, out, BB, DOUT, HH);
}

// round 9
// speedup vs baseline: 2.0925x; 1.0012x over previous
#include <cuda_runtime.h>
#include <cuda_fp16.h>
#include <math.h>
#include <stdint.h>

#define BB   16384
#define DIN  1024
#define HH   1024
#define DOUT 256
#define DEPTH 7

#define FLAG_CAP (1u << 22)
#define FLAG_T   128.0f

// ---------------- device scratch (fp16 hi/lo operand arrays) ------------------
__device__ __half g_xh[(size_t)BB * HH],  g_xl[(size_t)BB * HH];    // x split; reused for h3
__device__ __half g_h1h[(size_t)BB * HH], g_h1l[(size_t)BB * HH];
__device__ __half g_h2h[(size_t)BB * HH], g_h2l[(size_t)BB * HH];
__device__ __half g_w0h[(size_t)HH * DIN],  g_w0l[(size_t)HH * DIN];   // [N][K]
__device__ __half g_w1h[(size_t)HH * HH],   g_w1l[(size_t)HH * HH];
__device__ __half g_cwh[(size_t)HH * HH],   g_cwl[(size_t)HH * HH];
__device__ __half g_woh[(size_t)DOUT * HH], g_wol[(size_t)DOUT * HH];
__device__ float  g_probs[HH];
__device__ uint32_t g_flags[FLAG_CAP];
__device__ uint32_t g_flagn;

// ---------------- helpers -------------------------------------------------------
__device__ __forceinline__ uint32_t s2u(const void* p) {
    uint32_t a;
    asm("{ .reg .u64 t; cvta.to.shared.u64 t, %1; cvt.u32.u64 %0, t; }" : "=r"(a) : "l"(p));
    return a;
}
__device__ __forceinline__ void mma16(float c[4],
                                      uint32_t a0, uint32_t a1, uint32_t a2, uint32_t a3,
                                      uint32_t b0, uint32_t b1) {
    asm volatile(
        "mma.sync.aligned.m16n8k16.row.col.f32.f16.f16.f32 "
        "{%0,%1,%2,%3}, {%4,%5,%6,%7}, {%8,%9}, {%0,%1,%2,%3};"
        : "+f"(c[0]), "+f"(c[1]), "+f"(c[2]), "+f"(c[3])
        : "r"(a0), "r"(a1), "r"(a2), "r"(a3), "r"(b0), "r"(b1));
}
__device__ __forceinline__ void mma16h(uint32_t c[2],
                                       uint32_t a0, uint32_t a1, uint32_t a2, uint32_t a3,
                                       uint32_t b0, uint32_t b1) {
    asm volatile(
        "mma.sync.aligned.m16n8k16.row.col.f16.f16.f16.f16 "
        "{%0,%1}, {%2,%3,%4,%5}, {%6,%7}, {%0,%1};"
        : "+r"(c[0]), "+r"(c[1])
        : "r"(a0), "r"(a1), "r"(a2), "r"(a3), "r"(b0), "r"(b1));
}
__device__ __forceinline__ void ldsm4(uint32_t& r0, uint32_t& r1, uint32_t& r2, uint32_t& r3,
                                      uint32_t addr) {
    asm volatile("ldmatrix.sync.aligned.m8n8.x4.shared.b16 {%0,%1,%2,%3}, [%4];"
                 : "=r"(r0), "=r"(r1), "=r"(r2), "=r"(r3) : "r"(addr));
}
__device__ __forceinline__ void cp16(uint32_t s, const void* g) {
    asm volatile("cp.async.cg.shared.global [%0], [%1], 16;" :: "r"(s), "l"(g));
}
#define CP_COMMIT() asm volatile("cp.async.commit_group;" ::: "memory")
#define CP_WAIT(n)  asm volatile("cp.async.wait_group %0;" :: "n"(n) : "memory")

__device__ __forceinline__ void fsplit(float v, __half& h, __half& l) {
    h = __float2half_rn(v);
    l = __float2half_rn(v - __half2float(h));
}

// ---------------- probs (tiny) ---------------------------------------------------
__global__ void probs_kernel(const float* __restrict__ tw) {
    __shared__ float st[2][HH];
    const int r = blockIdx.x, t = threadIdx.x;
    for (int i = t; i < HH; i += blockDim.x) st[0][i] = 0.03125f;
    __syncthreads();
    int cur = 0;
    #pragma unroll 1
    for (int d = 0; d < DEPTH; ++d)
        #pragma unroll 1
        for (int k = 0; k < 3; ++k) {
            const float ang = tw[((size_t)d * HH + r) * HH + k];
            const float c = cosf(ang), s = sinf(ang);
            const int nxt = cur ^ 1;
            for (int i = t; i < HH; i += blockDim.x)
                st[nxt][i] = c * st[cur][i]
                           - s * st[cur][(i + 1) & (HH - 1)]
                           + s * st[cur][(i - 1) & (HH - 1)];
            __syncthreads();
            cur = nxt;
        }
    if (t == 0) { const float v = st[cur][0]; g_probs[r] = v * v; }
}

// ---------------- x split: fp32 -> fp16 hi/lo -------------------------------------
__global__ void splitx_kernel(const float4* __restrict__ in,
                              __half2* __restrict__ oh, __half2* __restrict__ ol, int n4) {
    int i = blockIdx.x * blockDim.x + threadIdx.x;
    if (i >= n4) return;
    float4 v = in[i];
    __half h0, h1, h2, h3, l0, l1, l2, l3;
    fsplit(v.x, h0, l0); fsplit(v.y, h1, l1);
    fsplit(v.z, h2, l2); fsplit(v.w, h3, l3);
    oh[2 * i]     = __halves2half2(h0, h1);
    oh[2 * i + 1] = __halves2half2(h2, h3);
    ol[2 * i]     = __halves2half2(l0, l1);
    ol[2 * i + 1] = __halves2half2(l2, l3);
}

// ---------------- weight transpose + split: w[K][N] fp32 -> [N][K] fp16 h/l -------
__global__ void tsplit_kernel(const float* __restrict__ w,
                              __half* __restrict__ th, __half* __restrict__ tl,
                              int Kd, int Nd) {
    __shared__ float tile[32][33];
    const int nb = blockIdx.x * 32, kb = blockIdx.y * 32;
    const int tx = threadIdx.x, ty = threadIdx.y;   // 32 x 8
    #pragma unroll
    for (int i = 0; i < 32; i += 8)
        tile[ty + i][tx] = w[(size_t)(kb + ty + i) * Nd + nb + tx];
    __syncthreads();
    #pragma unroll
    for (int i = 0; i < 32; i += 8) {
        const float v = tile[tx][ty + i];
        __half h, l;
        fsplit(v, h, l);
        const size_t o = (size_t)(nb + ty + i) * Kd + kb + tx;
        th[o] = h;
        tl[o] = l;
    }
}

// ---------------- repair: exact fp32 recompute of flagged tanh entries ------------
__global__ void repair_kernel(const __half2* __restrict__ h2h, const __half2* __restrict__ h2l,
                              const __half2* __restrict__ cwh, const __half2* __restrict__ cwl,
                              const float* __restrict__ cb,
                              __half* __restrict__ xh, __half* __restrict__ xl) {
    const uint32_t n = min(g_flagn, FLAG_CAP);
    const int lane = threadIdx.x & 31;
    const uint32_t warp = (blockIdx.x * blockDim.x + threadIdx.x) >> 5;
    const uint32_t nw = (gridDim.x * blockDim.x) >> 5;
    for (uint32_t e = warp; e < n; e += nw) {
        const uint32_t f = g_flags[e];
        const int row = f >> 10, col = f & 1023;
        const __half2* ah = h2h + (size_t)row * 512;
        const __half2* al = h2l + (size_t)row * 512;
        const __half2* wh = cwh + (size_t)col * 512;
        const __half2* wl = cwl + (size_t)col * 512;
        float s = 0.f;
        #pragma unroll 4
        for (int k = lane; k < 512; k += 32) {
            const float2 a0 = __half22float2(ah[k]);
            const float2 a1 = __half22float2(al[k]);
            const float2 w0 = __half22float2(wh[k]);
            const float2 w1 = __half22float2(wl[k]);
            s = fmaf(a0.x + a1.x, w0.x + w1.x, s);
            s = fmaf(a0.y + a1.y, w0.y + w1.y, s);
        }
        #pragma unroll
        for (int o = 16; o; o >>= 1) s += __shfl_xor_sync(0xFFFFFFFFu, s, o);
        if (lane == 0) {
            const float v = tanhf(s + cb[col] + g_probs[col]);
            __half h, l;
            fsplit(v, h, l);
            xh[(size_t)row * HH + col] = h;
            xl[(size_t)row * HH + col] = l;
        }
    }
}

// ---------------- split-fp16 GEMM (ldmatrix + mma.sync m16n8k16) ------------------
// Product-major mma ordering: 16 independent mmas per product group so no
// back-to-back RAW on any accumulator (HMMA latency hiding with 2 warps/SMSP).
// PROD=3: hh(f32) + Al*Bh(f16) + Ah*Bl(f16).  PROD=2: hh + Ah*Bl.  PROD=1: hh only.
// EPI 0: relu->split   1: tanh(+probs)->split + flag |pre|<T   2: relu->fp32
#define KT      64
#define LDH     72
#define TILE_B  (128 * LDH * 2)
#define STAGE_B (4 * TILE_B)
#define SMEM_TOTAL (2 * STAGE_B)           // 147456

template <int EPI, int PROD>
__global__ void __launch_bounds__(256, 1)
mma_gemm(const __half* __restrict__ Ah, const __half* __restrict__ Al,
         const __half* __restrict__ Bh, const __half* __restrict__ Bl,
         const float* __restrict__ bias,
         __half* __restrict__ Ch, __half* __restrict__ Cl,
         float* __restrict__ Cf,
         int M, int N, int K)
{
    constexpr bool NEED_AL = (PROD == 3);
    constexpr bool NEED_BL = (PROD >= 2);

    extern __shared__ __align__(16) char smem[];
    const int tid  = threadIdx.x;
    const int lane = tid & 31;
    const int warp = tid >> 5;
    const int wm   = (warp & 1) * 64;
    const int wn   = (warp >> 1) * 32;
    const int g    = lane >> 2;
    const int tg   = lane & 3;

    const int bm = blockIdx.y * 128;
    const int bn = blockIdx.x * 128;

    const uint32_t sA_h[2] = { s2u(smem),              s2u(smem + STAGE_B) };
    const uint32_t sA_l[2] = { sA_h[0] + TILE_B,       sA_h[1] + TILE_B };
    const uint32_t sB_h[2] = { sA_h[0] + 2 * TILE_B,   sA_h[1] + 2 * TILE_B };
    const uint32_t sB_l[2] = { sA_h[0] + 3 * TILE_B,   sA_h[1] + 3 * TILE_B };

    const int rowA = wm + (lane & 7) + 8 * ((lane >> 3) & 1);
    const int khA  = 8 * (lane >> 4);
    const uint32_t offA = (uint32_t)(rowA * LDH + khA) * 2;
    const int colB = wn + 8 * (lane >> 3) + (lane & 7);
    const uint32_t offB = (uint32_t)(colB * LDH) * 2;

    float    acc[4][4][4];
    uint32_t accx[4][4][2];
    #pragma unroll
    for (int i = 0; i < 4; ++i)
        #pragma unroll
        for (int j = 0; j < 4; ++j) {
            #pragma unroll
            for (int q = 0; q < 4; ++q) acc[i][j][q] = 0.f;
            accx[i][j][0] = 0u; accx[i][j][1] = 0u;
        }

    const int srow = tid >> 3;
    const int sseg = tid & 7;

    auto load_chunk = [&](int c, int s) {
        const int k0 = c * KT;
        #pragma unroll
        for (int r = 0; r < 4; ++r) {
            const int row = srow + 32 * r;
            const uint32_t so = (uint32_t)(row * LDH + sseg * 8) * 2;
            const size_t  ga = (size_t)(bm + row) * K + k0 + sseg * 8;
            const size_t  gb = (size_t)(bn + row) * K + k0 + sseg * 8;
            cp16(sA_h[s] + so, Ah + ga);
            if (NEED_AL) cp16(sA_l[s] + so, Al + ga);
            cp16(sB_h[s] + so, Bh + gb);
            if (NEED_BL) cp16(sB_l[s] + so, Bl + gb);
        }
    };

    const int NC = K / KT;
    load_chunk(0, 0);
    CP_COMMIT();

    #pragma unroll 1
    for (int c = 0; c < NC; ++c) {
        const int s = c & 1;
        if (c + 1 < NC) {
            load_chunk(c + 1, s ^ 1);
            CP_COMMIT();
            CP_WAIT(1);
        } else {
            CP_WAIT(0);
        }
        __syncthreads();

        #pragma unroll
        for (int k16 = 0; k16 < KT / 16; ++k16) {
            const uint32_t kb = (uint32_t)(k16 * 16) * 2;

            uint32_t a_h[4][4], a_l[4][4];
            #pragma unroll
            for (int i = 0; i < 4; ++i) {
                const uint32_t ao = offA + (uint32_t)(i * 16 * LDH) * 2 + kb;
                ldsm4(a_h[i][0], a_h[i][1], a_h[i][2], a_h[i][3], sA_h[s] + ao);
                if (NEED_AL) ldsm4(a_l[i][0], a_l[i][1], a_l[i][2], a_l[i][3], sA_l[s] + ao);
            }
            uint32_t b_h[4][2], b_l[4][2];
            ldsm4(b_h[0][0], b_h[1][0], b_h[2][0], b_h[3][0], sB_h[s] + offB + kb);
            ldsm4(b_h[0][1], b_h[1][1], b_h[2][1], b_h[3][1], sB_h[s] + offB + kb + 16);
            if (NEED_BL) {
                ldsm4(b_l[0][0], b_l[1][0], b_l[2][0], b_l[3][0], sB_l[s] + offB + kb);
                ldsm4(b_l[0][1], b_l[1][1], b_l[2][1], b_l[3][1], sB_l[s] + offB + kb + 16);
            }

            // product-major: 16 independent mmas per group, no adjacent RAW
            #pragma unroll
            for (int i = 0; i < 4; ++i)
                #pragma unroll
                for (int j = 0; j < 4; ++j)
                    mma16(acc[i][j], a_h[i][0], a_h[i][1], a_h[i][2], a_h[i][3], b_h[j][0], b_h[j][1]);
            if (NEED_AL) {
                #pragma unroll
                for (int i = 0; i < 4; ++i)
                    #pragma unroll
                    for (int j = 0; j < 4; ++j)
                        mma16h(accx[i][j], a_l[i][0], a_l[i][1], a_l[i][2], a_l[i][3], b_h[j][0], b_h[j][1]);
            }
            if (NEED_BL) {
                #pragma unroll
                for (int i = 0; i < 4; ++i)
                    #pragma unroll
                    for (int j = 0; j < 4; ++j)
                        mma16h(accx[i][j], a_h[i][0], a_h[i][1], a_h[i][2], a_h[i][3], b_l[j][0], b_l[j][1]);
            }
        }
        __syncthreads();
    }

    // ---- epilogue ----
    #pragma unroll
    for (int j = 0; j < 4; ++j) {
        const int col = bn + wn + j * 8 + 2 * tg;
        const float b0 = bias[col], b1 = bias[col + 1];
        float p0 = 0.f, p1 = 0.f;
        if (EPI == 1) { p0 = g_probs[col]; p1 = g_probs[col + 1]; }
        #pragma unroll
        for (int i = 0; i < 4; ++i) {
            const int row = bm + wm + i * 16 + g;
            const float2 x0 = __half22float2(*(__half2*)&accx[i][j][0]);
            const float2 x1 = __half22float2(*(__half2*)&accx[i][j][1]);
            float v0 = acc[i][j][0] + x0.x + b0;
            float v1 = acc[i][j][1] + x0.y + b1;
            float v2 = acc[i][j][2] + x1.x + b0;
            float v3 = acc[i][j][3] + x1.y + b1;
            if (EPI == 1) {
                v0 += p0; v1 += p1; v2 += p0; v3 += p1;
                auto push = [&](float pv, int r, int cc) {
                    if (fabsf(pv) < FLAG_T) {
                        const uint32_t idx = atomicAdd(&g_flagn, 1u);
                        if (idx < FLAG_CAP)
                            g_flags[idx] = ((uint32_t)r << 10) | (uint32_t)cc;
                    }
                };
                push(v0, row, col); push(v1, row, col + 1);
                push(v2, row + 8, col); push(v3, row + 8, col + 1);
                v0 = tanhf(v0); v1 = tanhf(v1);
                v2 = tanhf(v2); v3 = tanhf(v3);
            } else {
                v0 = fmaxf(v0, 0.f); v1 = fmaxf(v1, 0.f);
                v2 = fmaxf(v2, 0.f); v3 = fmaxf(v3, 0.f);
            }
            if (EPI == 2) {
                *reinterpret_cast<float2*>(&Cf[(size_t)row * N + col])       = make_float2(v0, v1);
                *reinterpret_cast<float2*>(&Cf[(size_t)(row + 8) * N + col]) = make_float2(v2, v3);
            } else {
                __half h0, h1, h2, h3, l0, l1, l2, l3;
                fsplit(v0, h0, l0); fsplit(v1, h1, l1);
                fsplit(v2, h2, l2); fsplit(v3, h3, l3);
                *reinterpret_cast<__half2*>(&Ch[(size_t)row * N + col])       = __halves2half2(h0, h1);
                *reinterpret_cast<__half2*>(&Ch[(size_t)(row + 8) * N + col]) = __halves2half2(h2, h3);
                *reinterpret_cast<__half2*>(&Cl[(size_t)row * N + col])       = __halves2half2(l0, l1);
                *reinterpret_cast<__half2*>(&Cl[(size_t)(row + 8) * N + col]) = __halves2half2(l2, l3);
            }
        }
    }
}

// ---------------- host --------------------------------------------------------------
extern "C" void kernel_launch(void* const* d_in, const int* in_sizes, int n_in,
                              void* d_out, int out_size) {
    const float* x    = (const float*)d_in[0];
    const float* w0   = (const float*)d_in[1];
    const float* b0   = (const float*)d_in[2];
    const float* w1   = (const float*)d_in[3];
    const float* b1   = (const float*)d_in[4];
    const float* tw   = (const float*)d_in[5];
    const float* cw   = (const float*)d_in[6];
    const float* cb   = (const float*)d_in[7];
    const float* wout = (const float*)d_in[8];
    const float* bout = (const float*)d_in[9];
    float* out = (float*)d_out;

    __half *xh, *xl, *h1h, *h1l, *h2h, *h2l;
    __half *w0h, *w0l, *w1h, *w1l, *cwh, *cwl, *woh, *wol;
    uint32_t* flagn;
    cudaGetSymbolAddress((void**)&xh,  g_xh);   cudaGetSymbolAddress((void**)&xl,  g_xl);
    cudaGetSymbolAddress((void**)&h1h, g_h1h);  cudaGetSymbolAddress((void**)&h1l, g_h1l);
    cudaGetSymbolAddress((void**)&h2h, g_h2h);  cudaGetSymbolAddress((void**)&h2l, g_h2l);
    cudaGetSymbolAddress((void**)&w0h, g_w0h);  cudaGetSymbolAddress((void**)&w0l, g_w0l);
    cudaGetSymbolAddress((void**)&w1h, g_w1h);  cudaGetSymbolAddress((void**)&w1l, g_w1l);
    cudaGetSymbolAddress((void**)&cwh, g_cwh);  cudaGetSymbolAddress((void**)&cwl, g_cwl);
    cudaGetSymbolAddress((void**)&woh, g_woh);  cudaGetSymbolAddress((void**)&wol, g_wol);
    cudaGetSymbolAddress((void**)&flagn, g_flagn);

    cudaFuncSetAttribute(mma_gemm<0,3>, cudaFuncAttributeMaxDynamicSharedMemorySize, SMEM_TOTAL);
    cudaFuncSetAttribute(mma_gemm<1,1>, cudaFuncAttributeMaxDynamicSharedMemorySize, SMEM_TOTAL);
    cudaFuncSetAttribute(mma_gemm<2,2>, cudaFuncAttributeMaxDynamicSharedMemorySize, SMEM_TOTAL);

    probs_kernel<<<HH, 256>>>(tw);
    {
        const int n4 = BB * DIN / 4;
        splitx_kernel<<<(n4 + 255) / 256, 256>>>((const float4*)x, (__half2*)xh, (__half2*)xl, n4);
    }
    tsplit_kernel<<<dim3(HH / 32,   DIN / 32), dim3(32, 8)>>>(w0,   w0h, w0l, DIN, HH);
    tsplit_kernel<<<dim3(HH / 32,   HH  / 32), dim3(32, 8)>>>(w1,   w1h, w1l, HH,  HH);
    tsplit_kernel<<<dim3(HH / 32,   HH  / 32), dim3(32, 8)>>>(cw,   cwh, cwl, HH,  HH);
    tsplit_kernel<<<dim3(DOUT / 32, HH  / 32), dim3(32, 8)>>>(wout, woh, wol, HH,  DOUT);
    cudaMemsetAsync(flagn, 0, sizeof(uint32_t));

    // layer 1: relu(x @ w0 + b0)            — 3 products
    mma_gemm<0,3><<<dim3(HH / 128,   BB / 128), 256, SMEM_TOTAL>>>(
        xh,  xl,  w0h, w0l, b0,   h1h, h1l, nullptr, BB, HH,   DIN);
    // layer 2: relu(h1 @ w1 + b1)           — 3 products
    mma_gemm<0,3><<<dim3(HH / 128,   BB / 128), 256, SMEM_TOTAL>>>(
        h1h, h1l, w1h, w1l, b1,   h2h, h2l, nullptr, BB, HH,   HH);
    // layer 3: tanh(h2 @ cw + cb + probs)   — hh only + flags
    mma_gemm<1,1><<<dim3(HH / 128,   BB / 128), 256, SMEM_TOTAL>>>(
        h2h, h2l, cwh, cwl, cb,   xh,  xl,  nullptr, BB, HH,   HH);
    // repair flagged entries exactly
    repair_kernel<<<512, 256>>>((const __half2*)h2h, (const __half2*)h2l,
                                (const __half2*)cwh, (const __half2*)cwl,
                                cb, xh, xl);
    // layer 4: relu(h3 @ wout + bout)       — 2 products (h3 lo ~ 0)
    mma_gemm<2,2><<<dim3(DOUT / 128, BB / 128), 256, SMEM_TOTAL>>>(
        xh,  xl,  woh, wol, bout, nullptr, nullptr, out, BB, DOUT, HH);
}

// round 10
// speedup vs baseline: 2.1663x; 1.0352x over previous
#include <cuda_runtime.h>
#include <cuda_fp16.h>
#include <math.h>
#include <stdint.h>

#define BB   16384
#define DIN  1024
#define HH   1024
#define DOUT 256
#define DEPTH 7

#define FLAG_CAP (1u << 22)
#define FLAG_T   128.0f

// ---------------- device scratch (fp16 hi/lo operand arrays) ------------------
__device__ __half g_xh[(size_t)BB * HH],  g_xl[(size_t)BB * HH];    // x split; reused for h3
__device__ __half g_h1h[(size_t)BB * HH], g_h1l[(size_t)BB * HH];
__device__ __half g_h2h[(size_t)BB * HH], g_h2l[(size_t)BB * HH];
__device__ __half g_w0h[(size_t)HH * DIN],  g_w0l[(size_t)HH * DIN];   // [N][K]
__device__ __half g_w1h[(size_t)HH * HH],   g_w1l[(size_t)HH * HH];
__device__ __half g_cwh[(size_t)HH * HH],   g_cwl[(size_t)HH * HH];
__device__ __half g_woh[(size_t)DOUT * HH], g_wol[(size_t)DOUT * HH];
__device__ float  g_probs[HH];
__device__ uint32_t g_flags[FLAG_CAP];
__device__ uint32_t g_flagn;

// ---------------- helpers -------------------------------------------------------
__device__ __forceinline__ uint32_t s2u(const void* p) {
    uint32_t a;
    asm("{ .reg .u64 t; cvta.to.shared.u64 t, %1; cvt.u32.u64 %0, t; }" : "=r"(a) : "l"(p));
    return a;
}
__device__ __forceinline__ void mma16(float c[4],
                                      uint32_t a0, uint32_t a1, uint32_t a2, uint32_t a3,
                                      uint32_t b0, uint32_t b1) {
    asm volatile(
        "mma.sync.aligned.m16n8k16.row.col.f32.f16.f16.f32 "
        "{%0,%1,%2,%3}, {%4,%5,%6,%7}, {%8,%9}, {%0,%1,%2,%3};"
        : "+f"(c[0]), "+f"(c[1]), "+f"(c[2]), "+f"(c[3])
        : "r"(a0), "r"(a1), "r"(a2), "r"(a3), "r"(b0), "r"(b1));
}
__device__ __forceinline__ void mma16h(uint32_t c[2],
                                       uint32_t a0, uint32_t a1, uint32_t a2, uint32_t a3,
                                       uint32_t b0, uint32_t b1) {
    asm volatile(
        "mma.sync.aligned.m16n8k16.row.col.f16.f16.f16.f16 "
        "{%0,%1}, {%2,%3,%4,%5}, {%6,%7}, {%0,%1};"
        : "+r"(c[0]), "+r"(c[1])
        : "r"(a0), "r"(a1), "r"(a2), "r"(a3), "r"(b0), "r"(b1));
}
__device__ __forceinline__ void ldsm4(uint32_t& r0, uint32_t& r1, uint32_t& r2, uint32_t& r3,
                                      uint32_t addr) {
    asm volatile("ldmatrix.sync.aligned.m8n8.x4.shared.b16 {%0,%1,%2,%3}, [%4];"
                 : "=r"(r0), "=r"(r1), "=r"(r2), "=r"(r3) : "r"(addr));
}
__device__ __forceinline__ void cp16(uint32_t s, const void* g) {
    asm volatile("cp.async.cg.shared.global [%0], [%1], 16;" :: "r"(s), "l"(g));
}
#define CP_COMMIT() asm volatile("cp.async.commit_group;" ::: "memory")
#define CP_WAIT(n)  asm volatile("cp.async.wait_group %0;" :: "n"(n) : "memory")

__device__ __forceinline__ void fsplit(float v, __half& h, __half& l) {
    h = __float2half_rn(v);
    l = __float2half_rn(v - __half2float(h));
}

// ---------------- probs (tiny) ---------------------------------------------------
__global__ void probs_kernel(const float* __restrict__ tw) {
    __shared__ float st[2][HH];
    const int r = blockIdx.x, t = threadIdx.x;
    for (int i = t; i < HH; i += blockDim.x) st[0][i] = 0.03125f;
    __syncthreads();
    int cur = 0;
    #pragma unroll 1
    for (int d = 0; d < DEPTH; ++d)
        #pragma unroll 1
        for (int k = 0; k < 3; ++k) {
            const float ang = tw[((size_t)d * HH + r) * HH + k];
            const float c = cosf(ang), s = sinf(ang);
            const int nxt = cur ^ 1;
            for (int i = t; i < HH; i += blockDim.x)
                st[nxt][i] = c * st[cur][i]
                           - s * st[cur][(i + 1) & (HH - 1)]
                           + s * st[cur][(i - 1) & (HH - 1)];
            __syncthreads();
            cur = nxt;
        }
    if (t == 0) { const float v = st[cur][0]; g_probs[r] = v * v; }
}

// ---------------- x split: fp32 -> fp16 hi/lo -------------------------------------
__global__ void splitx_kernel(const float4* __restrict__ in,
                              __half2* __restrict__ oh, __half2* __restrict__ ol, int n4) {
    int i = blockIdx.x * blockDim.x + threadIdx.x;
    if (i >= n4) return;
    float4 v = in[i];
    __half h0, h1, h2, h3, l0, l1, l2, l3;
    fsplit(v.x, h0, l0); fsplit(v.y, h1, l1);
    fsplit(v.z, h2, l2); fsplit(v.w, h3, l3);
    oh[2 * i]     = __halves2half2(h0, h1);
    oh[2 * i + 1] = __halves2half2(h2, h3);
    ol[2 * i]     = __halves2half2(l0, l1);
    ol[2 * i + 1] = __halves2half2(l2, l3);
}

// ---------------- weight transpose + split: w[K][N] fp32 -> [N][K] fp16 h/l -------
__global__ void tsplit_kernel(const float* __restrict__ w,
                              __half* __restrict__ th, __half* __restrict__ tl,
                              int Kd, int Nd) {
    __shared__ float tile[32][33];
    const int nb = blockIdx.x * 32, kb = blockIdx.y * 32;
    const int tx = threadIdx.x, ty = threadIdx.y;   // 32 x 8
    #pragma unroll
    for (int i = 0; i < 32; i += 8)
        tile[ty + i][tx] = w[(size_t)(kb + ty + i) * Nd + nb + tx];
    __syncthreads();
    #pragma unroll
    for (int i = 0; i < 32; i += 8) {
        const float v = tile[tx][ty + i];
        __half h, l;
        fsplit(v, h, l);
        const size_t o = (size_t)(nb + ty + i) * Kd + kb + tx;
        th[o] = h;
        tl[o] = l;
    }
}

// ---------------- repair: exact fp32 recompute of flagged tanh entries ------------
__global__ void repair_kernel(const __half2* __restrict__ h2h, const __half2* __restrict__ h2l,
                              const __half2* __restrict__ cwh, const __half2* __restrict__ cwl,
                              const float* __restrict__ cb,
                              __half* __restrict__ xh, __half* __restrict__ xl) {
    const uint32_t n = min(g_flagn, FLAG_CAP);
    const int lane = threadIdx.x & 31;
    const uint32_t warp = (blockIdx.x * blockDim.x + threadIdx.x) >> 5;
    const uint32_t nw = (gridDim.x * blockDim.x) >> 5;
    for (uint32_t e = warp; e < n; e += nw) {
        const uint32_t f = g_flags[e];
        const int row = f >> 10, col = f & 1023;
        const __half2* ah = h2h + (size_t)row * 512;
        const __half2* al = h2l + (size_t)row * 512;
        const __half2* wh = cwh + (size_t)col * 512;
        const __half2* wl = cwl + (size_t)col * 512;
        float s = 0.f;
        #pragma unroll 4
        for (int k = lane; k < 512; k += 32) {
            const float2 a0 = __half22float2(ah[k]);
            const float2 a1 = __half22float2(al[k]);
            const float2 w0 = __half22float2(wh[k]);
            const float2 w1 = __half22float2(wl[k]);
            s = fmaf(a0.x + a1.x, w0.x + w1.x, s);
            s = fmaf(a0.y + a1.y, w0.y + w1.y, s);
        }
        #pragma unroll
        for (int o = 16; o; o >>= 1) s += __shfl_xor_sync(0xFFFFFFFFu, s, o);
        if (lane == 0) {
            const float v = tanhf(s + cb[col] + g_probs[col]);
            __half h, l;
            fsplit(v, h, l);
            xh[(size_t)row * HH + col] = h;
            xl[(size_t)row * HH + col] = l;
        }
    }
}

// ---------------- split-fp16 GEMM (ldmatrix + mma.sync m16n8k16) ------------------
// 512 threads, 16 warps (4m x 4n), warp tile 32x32 -> 4 warps/SMSP for latency
// hiding (previous 8-warp config left the HMMA pipe half idle at occ=12.5%).
// PROD=3: hh(f32) + Al*Bh(f16) + Ah*Bl(f16).  PROD=2: hh + Ah*Bl.  PROD=1: hh only.
// EPI 0: relu->split   1: tanh(+probs)->split + flag |pre|<T   2: relu->fp32
#define KT      64
#define LDH     72
#define TILE_B  (128 * LDH * 2)
#define STAGE_B (4 * TILE_B)
#define SMEM_TOTAL (2 * STAGE_B)           // 147456
#define NTHREADS 512

template <int EPI, int PROD>
__global__ void __launch_bounds__(NTHREADS, 1)
mma_gemm(const __half* __restrict__ Ah, const __half* __restrict__ Al,
         const __half* __restrict__ Bh, const __half* __restrict__ Bl,
         const float* __restrict__ bias,
         __half* __restrict__ Ch, __half* __restrict__ Cl,
         float* __restrict__ Cf,
         int M, int N, int K)
{
    constexpr bool NEED_AL = (PROD == 3);
    constexpr bool NEED_BL = (PROD >= 2);

    extern __shared__ __align__(16) char smem[];
    const int tid  = threadIdx.x;
    const int lane = tid & 31;
    const int warp = tid >> 5;          // 0..15
    const int wm   = (warp & 3) * 32;   // 4 warps along M
    const int wn   = (warp >> 2) * 32;  // 4 warps along N
    const int g    = lane >> 2;
    const int tg   = lane & 3;

    const int bm = blockIdx.y * 128;
    const int bn = blockIdx.x * 128;

    const uint32_t sA_h[2] = { s2u(smem),              s2u(smem + STAGE_B) };
    const uint32_t sA_l[2] = { sA_h[0] + TILE_B,       sA_h[1] + TILE_B };
    const uint32_t sB_h[2] = { sA_h[0] + 2 * TILE_B,   sA_h[1] + 2 * TILE_B };
    const uint32_t sB_l[2] = { sA_h[0] + 3 * TILE_B,   sA_h[1] + 3 * TILE_B };

    const int rowA = wm + (lane & 7) + 8 * ((lane >> 3) & 1);
    const int khA  = 8 * (lane >> 4);
    const uint32_t offA = (uint32_t)(rowA * LDH + khA) * 2;
    const int colB = wn + 8 * (lane >> 3) + (lane & 7);
    const uint32_t offB = (uint32_t)(colB * LDH) * 2;

    float    acc[2][4][4];
    uint32_t accx[2][4][2];
    #pragma unroll
    for (int i = 0; i < 2; ++i)
        #pragma unroll
        for (int j = 0; j < 4; ++j) {
            #pragma unroll
            for (int q = 0; q < 4; ++q) acc[i][j][q] = 0.f;
            accx[i][j][0] = 0u; accx[i][j][1] = 0u;
        }

    // cp.async mapping: 1024 16B segments per (array, tile); 2 per thread per array.
    const int srow = tid >> 3;          // 0..63 (+64*r)
    const int sseg = tid & 7;           // halves sseg*8

    auto load_chunk = [&](int c, int s) {
        const int k0 = c * KT;
        #pragma unroll
        for (int r = 0; r < 2; ++r) {
            const int row = srow + 64 * r;
            const uint32_t so = (uint32_t)(row * LDH + sseg * 8) * 2;
            const size_t  ga = (size_t)(bm + row) * K + k0 + sseg * 8;
            const size_t  gb = (size_t)(bn + row) * K + k0 + sseg * 8;
            cp16(sA_h[s] + so, Ah + ga);
            if (NEED_AL) cp16(sA_l[s] + so, Al + ga);
            cp16(sB_h[s] + so, Bh + gb);
            if (NEED_BL) cp16(sB_l[s] + so, Bl + gb);
        }
    };

    const int NC = K / KT;
    load_chunk(0, 0);
    CP_COMMIT();

    #pragma unroll 1
    for (int c = 0; c < NC; ++c) {
        const int s = c & 1;
        if (c + 1 < NC) {
            load_chunk(c + 1, s ^ 1);
            CP_COMMIT();
            CP_WAIT(1);
        } else {
            CP_WAIT(0);
        }
        __syncthreads();

        #pragma unroll
        for (int k16 = 0; k16 < KT / 16; ++k16) {
            const uint32_t kb = (uint32_t)(k16 * 16) * 2;

            uint32_t a_h[2][4], a_l[2][4];
            #pragma unroll
            for (int i = 0; i < 2; ++i) {
                const uint32_t ao = offA + (uint32_t)(i * 16 * LDH) * 2 + kb;
                ldsm4(a_h[i][0], a_h[i][1], a_h[i][2], a_h[i][3], sA_h[s] + ao);
                if (NEED_AL) ldsm4(a_l[i][0], a_l[i][1], a_l[i][2], a_l[i][3], sA_l[s] + ao);
            }
            uint32_t b_h[4][2], b_l[4][2];
            ldsm4(b_h[0][0], b_h[1][0], b_h[2][0], b_h[3][0], sB_h[s] + offB + kb);
            ldsm4(b_h[0][1], b_h[1][1], b_h[2][1], b_h[3][1], sB_h[s] + offB + kb + 16);
            if (NEED_BL) {
                ldsm4(b_l[0][0], b_l[1][0], b_l[2][0], b_l[3][0], sB_l[s] + offB + kb);
                ldsm4(b_l[0][1], b_l[1][1], b_l[2][1], b_l[3][1], sB_l[s] + offB + kb + 16);
            }

            #pragma unroll
            for (int i = 0; i < 2; ++i)
                #pragma unroll
                for (int j = 0; j < 4; ++j)
                    mma16(acc[i][j], a_h[i][0], a_h[i][1], a_h[i][2], a_h[i][3], b_h[j][0], b_h[j][1]);
            if (NEED_AL) {
                #pragma unroll
                for (int i = 0; i < 2; ++i)
                    #pragma unroll
                    for (int j = 0; j < 4; ++j)
                        mma16h(accx[i][j], a_l[i][0], a_l[i][1], a_l[i][2], a_l[i][3], b_h[j][0], b_h[j][1]);
            }
            if (NEED_BL) {
                #pragma unroll
                for (int i = 0; i < 2; ++i)
                    #pragma unroll
                    for (int j = 0; j < 4; ++j)
                        mma16h(accx[i][j], a_h[i][0], a_h[i][1], a_h[i][2], a_h[i][3], b_l[j][0], b_l[j][1]);
            }
        }
        __syncthreads();
    }

    // ---- epilogue ----
    #pragma unroll
    for (int j = 0; j < 4; ++j) {
        const int col = bn + wn + j * 8 + 2 * tg;
        const float b0 = bias[col], b1 = bias[col + 1];
        float p0 = 0.f, p1 = 0.f;
        if (EPI == 1) { p0 = g_probs[col]; p1 = g_probs[col + 1]; }
        #pragma unroll
        for (int i = 0; i < 2; ++i) {
            const int row = bm + wm + i * 16 + g;
            const float2 x0 = __half22float2(*(__half2*)&accx[i][j][0]);
            const float2 x1 = __half22float2(*(__half2*)&accx[i][j][1]);
            float v0 = acc[i][j][0] + x0.x + b0;
            float v1 = acc[i][j][1] + x0.y + b1;
            float v2 = acc[i][j][2] + x1.x + b0;
            float v3 = acc[i][j][3] + x1.y + b1;
            if (EPI == 1) {
                v0 += p0; v1 += p1; v2 += p0; v3 += p1;
                auto push = [&](float pv, int r, int cc) {
                    if (fabsf(pv) < FLAG_T) {
                        const uint32_t idx = atomicAdd(&g_flagn, 1u);
                        if (idx < FLAG_CAP)
                            g_flags[idx] = ((uint32_t)r << 10) | (uint32_t)cc;
                    }
                };
                push(v0, row, col); push(v1, row, col + 1);
                push(v2, row + 8, col); push(v3, row + 8, col + 1);
                v0 = tanhf(v0); v1 = tanhf(v1);
                v2 = tanhf(v2); v3 = tanhf(v3);
            } else {
                v0 = fmaxf(v0, 0.f); v1 = fmaxf(v1, 0.f);
                v2 = fmaxf(v2, 0.f); v3 = fmaxf(v3, 0.f);
            }
            if (EPI == 2) {
                *reinterpret_cast<float2*>(&Cf[(size_t)row * N + col])       = make_float2(v0, v1);
                *reinterpret_cast<float2*>(&Cf[(size_t)(row + 8) * N + col]) = make_float2(v2, v3);
            } else {
                __half h0, h1, h2, h3, l0, l1, l2, l3;
                fsplit(v0, h0, l0); fsplit(v1, h1, l1);
                fsplit(v2, h2, l2); fsplit(v3, h3, l3);
                *reinterpret_cast<__half2*>(&Ch[(size_t)row * N + col])       = __halves2half2(h0, h1);
                *reinterpret_cast<__half2*>(&Ch[(size_t)(row + 8) * N + col]) = __halves2half2(h2, h3);
                *reinterpret_cast<__half2*>(&Cl[(size_t)row * N + col])       = __halves2half2(l0, l1);
                *reinterpret_cast<__half2*>(&Cl[(size_t)(row + 8) * N + col]) = __halves2half2(l2, l3);
            }
        }
    }
}

// ---------------- host --------------------------------------------------------------
extern "C" void kernel_launch(void* const* d_in, const int* in_sizes, int n_in,
                              void* d_out, int out_size) {
    const float* x    = (const float*)d_in[0];
    const float* w0   = (const float*)d_in[1];
    const float* b0   = (const float*)d_in[2];
    const float* w1   = (const float*)d_in[3];
    const float* b1   = (const float*)d_in[4];
    const float* tw   = (const float*)d_in[5];
    const float* cw   = (const float*)d_in[6];
    const float* cb   = (const float*)d_in[7];
    const float* wout = (const float*)d_in[8];
    const float* bout = (const float*)d_in[9];
    float* out = (float*)d_out;

    __half *xh, *xl, *h1h, *h1l, *h2h, *h2l;
    __half *w0h, *w0l, *w1h, *w1l, *cwh, *cwl, *woh, *wol;
    uint32_t* flagn;
    cudaGetSymbolAddress((void**)&xh,  g_xh);   cudaGetSymbolAddress((void**)&xl,  g_xl);
    cudaGetSymbolAddress((void**)&h1h, g_h1h);  cudaGetSymbolAddress((void**)&h1l, g_h1l);
    cudaGetSymbolAddress((void**)&h2h, g_h2h);  cudaGetSymbolAddress((void**)&h2l, g_h2l);
    cudaGetSymbolAddress((void**)&w0h, g_w0h);  cudaGetSymbolAddress((void**)&w0l, g_w0l);
    cudaGetSymbolAddress((void**)&w1h, g_w1h);  cudaGetSymbolAddress((void**)&w1l, g_w1l);
    cudaGetSymbolAddress((void**)&cwh, g_cwh);  cudaGetSymbolAddress((void**)&cwl, g_cwl);
    cudaGetSymbolAddress((void**)&woh, g_woh);  cudaGetSymbolAddress((void**)&wol, g_wol);
    cudaGetSymbolAddress((void**)&flagn, g_flagn);

    cudaFuncSetAttribute(mma_gemm<0,3>, cudaFuncAttributeMaxDynamicSharedMemorySize, SMEM_TOTAL);
    cudaFuncSetAttribute(mma_gemm<1,1>, cudaFuncAttributeMaxDynamicSharedMemorySize, SMEM_TOTAL);
    cudaFuncSetAttribute(mma_gemm<2,2>, cudaFuncAttributeMaxDynamicSharedMemorySize, SMEM_TOTAL);

    probs_kernel<<<HH, 256>>>(tw);
    {
        const int n4 = BB * DIN / 4;
        splitx_kernel<<<(n4 + 255) / 256, 256>>>((const float4*)x, (__half2*)xh, (__half2*)xl, n4);
    }
    tsplit_kernel<<<dim3(HH / 32,   DIN / 32), dim3(32, 8)>>>(w0,   w0h, w0l, DIN, HH);
    tsplit_kernel<<<dim3(HH / 32,   HH  / 32), dim3(32, 8)>>>(w1,   w1h, w1l, HH,  HH);
    tsplit_kernel<<<dim3(HH / 32,   HH  / 32), dim3(32, 8)>>>(cw,   cwh, cwl, HH,  HH);
    tsplit_kernel<<<dim3(DOUT / 32, HH  / 32), dim3(32, 8)>>>(wout, woh, wol, HH,  DOUT);
    cudaMemsetAsync(flagn, 0, sizeof(uint32_t));

    // layer 1: relu(x @ w0 + b0)            — 3 products
    mma_gemm<0,3><<<dim3(HH / 128,   BB / 128), NTHREADS, SMEM_TOTAL>>>(
        xh,  xl,  w0h, w0l, b0,   h1h, h1l, nullptr, BB, HH,   DIN);
    // layer 2: relu(h1 @ w1 + b1)           — 3 products
    mma_gemm<0,3><<<dim3(HH / 128,   BB / 128), NTHREADS, SMEM_TOTAL>>>(
        h1h, h1l, w1h, w1l, b1,   h2h, h2l, nullptr, BB, HH,   HH);
    // layer 3: tanh(h2 @ cw + cb + probs)   — hh only + flags
    mma_gemm<1,1><<<dim3(HH / 128,   BB / 128), NTHREADS, SMEM_TOTAL>>>(
        h2h, h2l, cwh, cwl, cb,   xh,  xl,  nullptr, BB, HH,   HH);
    // repair flagged entries exactly
    repair_kernel<<<512, 256>>>((const __half2*)h2h, (const __half2*)h2l,
                                (const __half2*)cwh, (const __half2*)cwl,
                                cb, xh, xl);
    // layer 4: relu(h3 @ wout + bout)       — 2 products (h3 lo ~ 0)
    mma_gemm<2,2><<<dim3(DOUT / 128, BB / 128), NTHREADS, SMEM_TOTAL>>>(
        xh,  xl,  woh, wol, bout, nullptr, nullptr, out, BB, DOUT, HH);
}

// round 11
// speedup vs baseline: 2.2661x; 1.0461x over previous
#include <cuda_runtime.h>
#include <cuda_fp16.h>
#include <math.h>
#include <stdint.h>

#define BB   16384
#define DIN  1024
#define HH   1024
#define DOUT 256
#define DEPTH 7

#define FLAG_CAP (1u << 22)
#define FLAG_T   128.0f

// ---------------- device scratch (fp16 hi/lo operand arrays) ------------------
__device__ __half g_xh[(size_t)BB * HH],  g_xl[(size_t)BB * HH];    // x split; reused for h3
__device__ __half g_h1h[(size_t)BB * HH], g_h1l[(size_t)BB * HH];
__device__ __half g_h2h[(size_t)BB * HH], g_h2l[(size_t)BB * HH];
__device__ __half g_w0h[(size_t)HH * DIN],  g_w0l[(size_t)HH * DIN];   // [N][K]
__device__ __half g_w1h[(size_t)HH * HH],   g_w1l[(size_t)HH * HH];
__device__ __half g_cwh[(size_t)HH * HH],   g_cwl[(size_t)HH * HH];
__device__ __half g_woh[(size_t)DOUT * HH], g_wol[(size_t)DOUT * HH];
__device__ float  g_probs[HH];
__device__ uint32_t g_flags[FLAG_CAP];
__device__ uint32_t g_flagn;

// ---------------- helpers -------------------------------------------------------
__device__ __forceinline__ uint32_t s2u(const void* p) {
    uint32_t a;
    asm("{ .reg .u64 t; cvta.to.shared.u64 t, %1; cvt.u32.u64 %0, t; }" : "=r"(a) : "l"(p));
    return a;
}
__device__ __forceinline__ void mma16(float c[4],
                                      uint32_t a0, uint32_t a1, uint32_t a2, uint32_t a3,
                                      uint32_t b0, uint32_t b1) {
    asm volatile(
        "mma.sync.aligned.m16n8k16.row.col.f32.f16.f16.f32 "
        "{%0,%1,%2,%3}, {%4,%5,%6,%7}, {%8,%9}, {%0,%1,%2,%3};"
        : "+f"(c[0]), "+f"(c[1]), "+f"(c[2]), "+f"(c[3])
        : "r"(a0), "r"(a1), "r"(a2), "r"(a3), "r"(b0), "r"(b1));
}
__device__ __forceinline__ void mma16h(uint32_t c[2],
                                       uint32_t a0, uint32_t a1, uint32_t a2, uint32_t a3,
                                       uint32_t b0, uint32_t b1) {
    asm volatile(
        "mma.sync.aligned.m16n8k16.row.col.f16.f16.f16.f16 "
        "{%0,%1}, {%2,%3,%4,%5}, {%6,%7}, {%0,%1};"
        : "+r"(c[0]), "+r"(c[1])
        : "r"(a0), "r"(a1), "r"(a2), "r"(a3), "r"(b0), "r"(b1));
}
__device__ __forceinline__ void ldsm4(uint32_t& r0, uint32_t& r1, uint32_t& r2, uint32_t& r3,
                                      uint32_t addr) {
    asm volatile("ldmatrix.sync.aligned.m8n8.x4.shared.b16 {%0,%1,%2,%3}, [%4];"
                 : "=r"(r0), "=r"(r1), "=r"(r2), "=r"(r3) : "r"(addr));
}
__device__ __forceinline__ void cp16(uint32_t s, const void* g) {
    asm volatile("cp.async.cg.shared.global [%0], [%1], 16;" :: "r"(s), "l"(g));
}
#define CP_COMMIT() asm volatile("cp.async.commit_group;" ::: "memory")
#define CP_WAIT(n)  asm volatile("cp.async.wait_group %0;" :: "n"(n) : "memory")

__device__ __forceinline__ void fsplit(float v, __half& h, __half& l) {
    h = __float2half_rn(v);
    l = __float2half_rn(v - __half2float(h));
}

// ---------------- probs (tiny) ---------------------------------------------------
__global__ void probs_kernel(const float* __restrict__ tw) {
    __shared__ float st[2][HH];
    const int r = blockIdx.x, t = threadIdx.x;
    for (int i = t; i < HH; i += blockDim.x) st[0][i] = 0.03125f;
    __syncthreads();
    int cur = 0;
    #pragma unroll 1
    for (int d = 0; d < DEPTH; ++d)
        #pragma unroll 1
        for (int k = 0; k < 3; ++k) {
            const float ang = tw[((size_t)d * HH + r) * HH + k];
            const float c = cosf(ang), s = sinf(ang);
            const int nxt = cur ^ 1;
            for (int i = t; i < HH; i += blockDim.x)
                st[nxt][i] = c * st[cur][i]
                           - s * st[cur][(i + 1) & (HH - 1)]
                           + s * st[cur][(i - 1) & (HH - 1)];
            __syncthreads();
            cur = nxt;
        }
    if (t == 0) { const float v = st[cur][0]; g_probs[r] = v * v; }
}

// ---------------- x split: fp32 -> fp16 hi/lo -------------------------------------
__global__ void splitx_kernel(const float4* __restrict__ in,
                              __half2* __restrict__ oh, __half2* __restrict__ ol, int n4) {
    int i = blockIdx.x * blockDim.x + threadIdx.x;
    if (i >= n4) return;
    float4 v = in[i];
    __half h0, h1, h2, h3, l0, l1, l2, l3;
    fsplit(v.x, h0, l0); fsplit(v.y, h1, l1);
    fsplit(v.z, h2, l2); fsplit(v.w, h3, l3);
    oh[2 * i]     = __halves2half2(h0, h1);
    oh[2 * i + 1] = __halves2half2(h2, h3);
    ol[2 * i]     = __halves2half2(l0, l1);
    ol[2 * i + 1] = __halves2half2(l2, l3);
}

// ---------------- weight transpose + split: w[K][N] fp32 -> [N][K] fp16 h/l -------
__global__ void tsplit_kernel(const float* __restrict__ w,
                              __half* __restrict__ th, __half* __restrict__ tl,
                              int Kd, int Nd) {
    __shared__ float tile[32][33];
    const int nb = blockIdx.x * 32, kb = blockIdx.y * 32;
    const int tx = threadIdx.x, ty = threadIdx.y;   // 32 x 8
    #pragma unroll
    for (int i = 0; i < 32; i += 8)
        tile[ty + i][tx] = w[(size_t)(kb + ty + i) * Nd + nb + tx];
    __syncthreads();
    #pragma unroll
    for (int i = 0; i < 32; i += 8) {
        const float v = tile[tx][ty + i];
        __half h, l;
        fsplit(v, h, l);
        const size_t o = (size_t)(nb + ty + i) * Kd + kb + tx;
        th[o] = h;
        tl[o] = l;
    }
}

// ---------------- repair: exact fp32 recompute of flagged tanh entries ------------
__global__ void repair_kernel(const __half2* __restrict__ h2h, const __half2* __restrict__ h2l,
                              const __half2* __restrict__ cwh, const __half2* __restrict__ cwl,
                              const float* __restrict__ cb,
                              __half* __restrict__ xh, __half* __restrict__ xl) {
    const uint32_t n = min(g_flagn, FLAG_CAP);
    const int lane = threadIdx.x & 31;
    const uint32_t warp = (blockIdx.x * blockDim.x + threadIdx.x) >> 5;
    const uint32_t nw = (gridDim.x * blockDim.x) >> 5;
    for (uint32_t e = warp; e < n; e += nw) {
        const uint32_t f = g_flags[e];
        const int row = f >> 10, col = f & 1023;
        const __half2* ah = h2h + (size_t)row * 512;
        const __half2* al = h2l + (size_t)row * 512;
        const __half2* wh = cwh + (size_t)col * 512;
        const __half2* wl = cwl + (size_t)col * 512;
        float s = 0.f;
        #pragma unroll 4
        for (int k = lane; k < 512; k += 32) {
            const float2 a0 = __half22float2(ah[k]);
            const float2 a1 = __half22float2(al[k]);
            const float2 w0 = __half22float2(wh[k]);
            const float2 w1 = __half22float2(wl[k]);
            s = fmaf(a0.x + a1.x, w0.x + w1.x, s);
            s = fmaf(a0.y + a1.y, w0.y + w1.y, s);
        }
        #pragma unroll
        for (int o = 16; o; o >>= 1) s += __shfl_xor_sync(0xFFFFFFFFu, s, o);
        if (lane == 0) {
            const float v = tanhf(s + cb[col] + g_probs[col]);
            __half h, l;
            fsplit(v, h, l);
            xh[(size_t)row * HH + col] = h;
            xl[(size_t)row * HH + col] = l;
        }
    }
}

// ---------------- split-fp16 GEMM (ldmatrix + mma.sync m16n8k16) ------------------
// 3-stage cp.async pipeline, ONE __syncthreads per chunk (write target at iter c
// is stage (c+2)%3 whose readers finished before this iter's barrier).
// 512 threads, 16 warps (4m x 4n), warp tile 32x32.
// PROD=3: hh(f32) + Al*Bh(f16) + Ah*Bl(f16).  PROD=2: hh + Ah*Bl.  PROD=1: hh only.
// Arrays packed per PROD: 4 / 3 / 2 per stage.
// EPI 0: relu->split   1: tanh(+probs)->split + flag |pre|<T   2: relu->fp32
#define KT      64
#define LDH     72
#define TILE_B  (128 * LDH * 2)          // 18432 bytes per (array, tile)
#define NSTAGE  3
#define NTHREADS 512

template <int P> struct ArrCnt { static const int v = (P == 3) ? 4 : (P == 2) ? 3 : 2; };
#define SMEM_FOR(P) (NSTAGE * ArrCnt<P>::v * TILE_B)

template <int EPI, int PROD>
__global__ void __launch_bounds__(NTHREADS, 1)
mma_gemm(const __half* __restrict__ Ah, const __half* __restrict__ Al,
         const __half* __restrict__ Bh, const __half* __restrict__ Bl,
         const float* __restrict__ bias,
         __half* __restrict__ Ch, __half* __restrict__ Cl,
         float* __restrict__ Cf,
         int M, int N, int K)
{
    constexpr bool NEED_AL = (PROD == 3);
    constexpr bool NEED_BL = (PROD >= 2);
    constexpr int  ARR     = ArrCnt<PROD>::v;
    constexpr uint32_t STAGE_B = ARR * TILE_B;
    constexpr uint32_t OFF_AL  = TILE_B;                      // valid iff NEED_AL
    constexpr uint32_t OFF_BH  = (NEED_AL ? 2 : 1) * TILE_B;
    constexpr uint32_t OFF_BL  = OFF_BH + TILE_B;             // valid iff NEED_BL

    extern __shared__ __align__(16) char smem[];
    const uint32_t sbase = s2u(smem);
    const int tid  = threadIdx.x;
    const int lane = tid & 31;
    const int warp = tid >> 5;          // 0..15
    const int wm   = (warp & 3) * 32;
    const int wn   = (warp >> 2) * 32;
    const int g    = lane >> 2;
    const int tg   = lane & 3;

    const int bm = blockIdx.y * 128;
    const int bn = blockIdx.x * 128;

    const int rowA = wm + (lane & 7) + 8 * ((lane >> 3) & 1);
    const int khA  = 8 * (lane >> 4);
    const uint32_t offA = (uint32_t)(rowA * LDH + khA) * 2;
    const int colB = wn + 8 * (lane >> 3) + (lane & 7);
    const uint32_t offB = (uint32_t)(colB * LDH) * 2;

    float    acc[2][4][4];
    uint32_t accx[2][4][2];
    #pragma unroll
    for (int i = 0; i < 2; ++i)
        #pragma unroll
        for (int j = 0; j < 4; ++j) {
            #pragma unroll
            for (int q = 0; q < 4; ++q) acc[i][j][q] = 0.f;
            accx[i][j][0] = 0u; accx[i][j][1] = 0u;
        }

    const int srow = tid >> 3;          // 0..63 (+64*r)
    const int sseg = tid & 7;           // halves sseg*8

    auto load_chunk = [&](int c, int s) {
        const int k0 = c * KT;
        const uint32_t sb = sbase + (uint32_t)s * STAGE_B;
        #pragma unroll
        for (int r = 0; r < 2; ++r) {
            const int row = srow + 64 * r;
            const uint32_t so = (uint32_t)(row * LDH + sseg * 8) * 2;
            const size_t  ga = (size_t)(bm + row) * K + k0 + sseg * 8;
            const size_t  gb = (size_t)(bn + row) * K + k0 + sseg * 8;
            cp16(sb + so, Ah + ga);
            if (NEED_AL) cp16(sb + OFF_AL + so, Al + ga);
            cp16(sb + OFF_BH + so, Bh + gb);
            if (NEED_BL) cp16(sb + OFF_BL + so, Bl + gb);
        }
    };

    const int NC = K / KT;      // >= 4 for all layers
    load_chunk(0, 0); CP_COMMIT();
    load_chunk(1, 1); CP_COMMIT();

    #pragma unroll 1
    for (int c = 0; c < NC; ++c) {
        const int s = c - (c / NSTAGE) * NSTAGE;   // c % 3
        if (c + 2 < NC) { CP_WAIT(1); } else { CP_WAIT(0); }
        __syncthreads();
        if (c + 2 < NC) {
            const int ns = (c + 2) - ((c + 2) / NSTAGE) * NSTAGE;
            load_chunk(c + 2, ns);
            CP_COMMIT();
        }

        const uint32_t sb = sbase + (uint32_t)s * STAGE_B;
        #pragma unroll
        for (int k16 = 0; k16 < KT / 16; ++k16) {
            const uint32_t kb = (uint32_t)(k16 * 16) * 2;

            uint32_t a_h[2][4], a_l[2][4];
            #pragma unroll
            for (int i = 0; i < 2; ++i) {
                const uint32_t ao = offA + (uint32_t)(i * 16 * LDH) * 2 + kb;
                ldsm4(a_h[i][0], a_h[i][1], a_h[i][2], a_h[i][3], sb + ao);
                if (NEED_AL) ldsm4(a_l[i][0], a_l[i][1], a_l[i][2], a_l[i][3], sb + OFF_AL + ao);
            }
            uint32_t b_h[4][2], b_l[4][2];
            ldsm4(b_h[0][0], b_h[1][0], b_h[2][0], b_h[3][0], sb + OFF_BH + offB + kb);
            ldsm4(b_h[0][1], b_h[1][1], b_h[2][1], b_h[3][1], sb + OFF_BH + offB + kb + 16);
            if (NEED_BL) {
                ldsm4(b_l[0][0], b_l[1][0], b_l[2][0], b_l[3][0], sb + OFF_BL + offB + kb);
                ldsm4(b_l[0][1], b_l[1][1], b_l[2][1], b_l[3][1], sb + OFF_BL + offB + kb + 16);
            }

            #pragma unroll
            for (int i = 0; i < 2; ++i)
                #pragma unroll
                for (int j = 0; j < 4; ++j)
                    mma16(acc[i][j], a_h[i][0], a_h[i][1], a_h[i][2], a_h[i][3], b_h[j][0], b_h[j][1]);
            if (NEED_AL) {
                #pragma unroll
                for (int i = 0; i < 2; ++i)
                    #pragma unroll
                    for (int j = 0; j < 4; ++j)
                        mma16h(accx[i][j], a_l[i][0], a_l[i][1], a_l[i][2], a_l[i][3], b_h[j][0], b_h[j][1]);
            }
            if (NEED_BL) {
                #pragma unroll
                for (int i = 0; i < 2; ++i)
                    #pragma unroll
                    for (int j = 0; j < 4; ++j)
                        mma16h(accx[i][j], a_h[i][0], a_h[i][1], a_h[i][2], a_h[i][3], b_l[j][0], b_l[j][1]);
            }
        }
    }

    // ---- epilogue ----
    #pragma unroll
    for (int j = 0; j < 4; ++j) {
        const int col = bn + wn + j * 8 + 2 * tg;
        const float b0 = bias[col], b1 = bias[col + 1];
        float p0 = 0.f, p1 = 0.f;
        if (EPI == 1) { p0 = g_probs[col]; p1 = g_probs[col + 1]; }
        #pragma unroll
        for (int i = 0; i < 2; ++i) {
            const int row = bm + wm + i * 16 + g;
            const float2 x0 = __half22float2(*(__half2*)&accx[i][j][0]);
            const float2 x1 = __half22float2(*(__half2*)&accx[i][j][1]);
            float v0 = acc[i][j][0] + x0.x + b0;
            float v1 = acc[i][j][1] + x0.y + b1;
            float v2 = acc[i][j][2] + x1.x + b0;
            float v3 = acc[i][j][3] + x1.y + b1;
            if (EPI == 1) {
                v0 += p0; v1 += p1; v2 += p0; v3 += p1;
                auto push = [&](float pv, int r, int cc) {
                    if (fabsf(pv) < FLAG_T) {
                        const uint32_t idx = atomicAdd(&g_flagn, 1u);
                        if (idx < FLAG_CAP)
                            g_flags[idx] = ((uint32_t)r << 10) | (uint32_t)cc;
                    }
                };
                push(v0, row, col); push(v1, row, col + 1);
                push(v2, row + 8, col); push(v3, row + 8, col + 1);
                v0 = tanhf(v0); v1 = tanhf(v1);
                v2 = tanhf(v2); v3 = tanhf(v3);
            } else {
                v0 = fmaxf(v0, 0.f); v1 = fmaxf(v1, 0.f);
                v2 = fmaxf(v2, 0.f); v3 = fmaxf(v3, 0.f);
            }
            if (EPI == 2) {
                *reinterpret_cast<float2*>(&Cf[(size_t)row * N + col])       = make_float2(v0, v1);
                *reinterpret_cast<float2*>(&Cf[(size_t)(row + 8) * N + col]) = make_float2(v2, v3);
            } else {
                __half h0, h1, h2, h3, l0, l1, l2, l3;
                fsplit(v0, h0, l0); fsplit(v1, h1, l1);
                fsplit(v2, h2, l2); fsplit(v3, h3, l3);
                *reinterpret_cast<__half2*>(&Ch[(size_t)row * N + col])       = __halves2half2(h0, h1);
                *reinterpret_cast<__half2*>(&Ch[(size_t)(row + 8) * N + col]) = __halves2half2(h2, h3);
                *reinterpret_cast<__half2*>(&Cl[(size_t)row * N + col])       = __halves2half2(l0, l1);
                *reinterpret_cast<__half2*>(&Cl[(size_t)(row + 8) * N + col]) = __halves2half2(l2, l3);
            }
        }
    }
}

// ---------------- host --------------------------------------------------------------
extern "C" void kernel_launch(void* const* d_in, const int* in_sizes, int n_in,
                              void* d_out, int out_size) {
    const float* x    = (const float*)d_in[0];
    const float* w0   = (const float*)d_in[1];
    const float* b0   = (const float*)d_in[2];
    const float* w1   = (const float*)d_in[3];
    const float* b1   = (const float*)d_in[4];
    const float* tw   = (const float*)d_in[5];
    const float* cw   = (const float*)d_in[6];
    const float* cb   = (const float*)d_in[7];
    const float* wout = (const float*)d_in[8];
    const float* bout = (const float*)d_in[9];
    float* out = (float*)d_out;

    __half *xh, *xl, *h1h, *h1l, *h2h, *h2l;
    __half *w0h, *w0l, *w1h, *w1l, *cwh, *cwl, *woh, *wol;
    uint32_t* flagn;
    cudaGetSymbolAddress((void**)&xh,  g_xh);   cudaGetSymbolAddress((void**)&xl,  g_xl);
    cudaGetSymbolAddress((void**)&h1h, g_h1h);  cudaGetSymbolAddress((void**)&h1l, g_h1l);
    cudaGetSymbolAddress((void**)&h2h, g_h2h);  cudaGetSymbolAddress((void**)&h2l, g_h2l);
    cudaGetSymbolAddress((void**)&w0h, g_w0h);  cudaGetSymbolAddress((void**)&w0l, g_w0l);
    cudaGetSymbolAddress((void**)&w1h, g_w1h);  cudaGetSymbolAddress((void**)&w1l, g_w1l);
    cudaGetSymbolAddress((void**)&cwh, g_cwh);  cudaGetSymbolAddress((void**)&cwl, g_cwl);
    cudaGetSymbolAddress((void**)&woh, g_woh);  cudaGetSymbolAddress((void**)&wol, g_wol);
    cudaGetSymbolAddress((void**)&flagn, g_flagn);

    cudaFuncSetAttribute(mma_gemm<0,3>, cudaFuncAttributeMaxDynamicSharedMemorySize, SMEM_FOR(3));
    cudaFuncSetAttribute(mma_gemm<1,1>, cudaFuncAttributeMaxDynamicSharedMemorySize, SMEM_FOR(1));
    cudaFuncSetAttribute(mma_gemm<2,2>, cudaFuncAttributeMaxDynamicSharedMemorySize, SMEM_FOR(2));

    probs_kernel<<<HH, 256>>>(tw);
    {
        const int n4 = BB * DIN / 4;
        splitx_kernel<<<(n4 + 255) / 256, 256>>>((const float4*)x, (__half2*)xh, (__half2*)xl, n4);
    }
    tsplit_kernel<<<dim3(HH / 32,   DIN / 32), dim3(32, 8)>>>(w0,   w0h, w0l, DIN, HH);
    tsplit_kernel<<<dim3(HH / 32,   HH  / 32), dim3(32, 8)>>>(w1,   w1h, w1l, HH,  HH);
    tsplit_kernel<<<dim3(HH / 32,   HH  / 32), dim3(32, 8)>>>(cw,   cwh, cwl, HH,  HH);
    tsplit_kernel<<<dim3(DOUT / 32, HH  / 32), dim3(32, 8)>>>(wout, woh, wol, HH,  DOUT);
    cudaMemsetAsync(flagn, 0, sizeof(uint32_t));

    // layer 1: relu(x @ w0 + b0)            — 3 products
    mma_gemm<0,3><<<dim3(HH / 128,   BB / 128), NTHREADS, SMEM_FOR(3)>>>(
        xh,  xl,  w0h, w0l, b0,   h1h, h1l, nullptr, BB, HH,   DIN);
    // layer 2: relu(h1 @ w1 + b1)           — 3 products
    mma_gemm<0,3><<<dim3(HH / 128,   BB / 128), NTHREADS, SMEM_FOR(3)>>>(
        h1h, h1l, w1h, w1l, b1,   h2h, h2l, nullptr, BB, HH,   HH);
    // layer 3: tanh(h2 @ cw + cb + probs)   — hh only + flags
    mma_gemm<1,1><<<dim3(HH / 128,   BB / 128), NTHREADS, SMEM_FOR(1)>>>(
        h2h, h2l, cwh, cwl, cb,   xh,  xl,  nullptr, BB, HH,   HH);
    // repair flagged entries exactly
    repair_kernel<<<512, 256>>>((const __half2*)h2h, (const __half2*)h2l,
                                (const __half2*)cwh, (const __half2*)cwl,
                                cb, xh, xl);
    // layer 4: relu(h3 @ wout + bout)       — 2 products (h3 lo ~ 0)
    mma_gemm<2,2><<<dim3(DOUT / 128, BB / 128), NTHREADS, SMEM_FOR(2)>>>(
        xh,  xl,  woh, wol, bout, nullptr, nullptr, out, BB, DOUT, HH);
}

// round 12
// speedup vs baseline: 2.3848x; 1.0524x over previous
#include <cuda_runtime.h>
#include <cuda_fp16.h>
#include <math.h>
#include <stdint.h>

#define BB   16384
#define DIN  1024
#define HH   1024
#define DOUT 256
#define DEPTH 7

#define FLAG_CAP (1u << 22)
#define FLAG_T   64.0f
#define SAT_T    20.0f

// ---------------- device scratch (fp16 hi/lo operand arrays) ------------------
__device__ __half g_xh[(size_t)BB * HH],  g_xl[(size_t)BB * HH];    // x split; reused for h3
__device__ __half g_h1h[(size_t)BB * HH], g_h1l[(size_t)BB * HH];
__device__ __half g_h2h[(size_t)BB * HH], g_h2l[(size_t)BB * HH];
__device__ __half g_w0h[(size_t)HH * DIN],  g_w0l[(size_t)HH * DIN];   // [N][K]
__device__ __half g_w1h[(size_t)HH * HH],   g_w1l[(size_t)HH * HH];
__device__ __half g_cwh[(size_t)HH * HH],   g_cwl[(size_t)HH * HH];
__device__ __half g_woh[(size_t)DOUT * HH], g_wol[(size_t)DOUT * HH];
__device__ float  g_probs[HH];
__device__ uint32_t g_flags[FLAG_CAP];
__device__ uint32_t g_flagn;

// ---------------- helpers -------------------------------------------------------
__device__ __forceinline__ uint32_t s2u(const void* p) {
    uint32_t a;
    asm("{ .reg .u64 t; cvta.to.shared.u64 t, %1; cvt.u32.u64 %0, t; }" : "=r"(a) : "l"(p));
    return a;
}
__device__ __forceinline__ void mma16(float c[4],
                                      uint32_t a0, uint32_t a1, uint32_t a2, uint32_t a3,
                                      uint32_t b0, uint32_t b1) {
    asm volatile(
        "mma.sync.aligned.m16n8k16.row.col.f32.f16.f16.f32 "
        "{%0,%1,%2,%3}, {%4,%5,%6,%7}, {%8,%9}, {%0,%1,%2,%3};"
        : "+f"(c[0]), "+f"(c[1]), "+f"(c[2]), "+f"(c[3])
        : "r"(a0), "r"(a1), "r"(a2), "r"(a3), "r"(b0), "r"(b1));
}
__device__ __forceinline__ void mma16h(uint32_t c[2],
                                       uint32_t a0, uint32_t a1, uint32_t a2, uint32_t a3,
                                       uint32_t b0, uint32_t b1) {
    asm volatile(
        "mma.sync.aligned.m16n8k16.row.col.f16.f16.f16.f16 "
        "{%0,%1}, {%2,%3,%4,%5}, {%6,%7}, {%0,%1};"
        : "+r"(c[0]), "+r"(c[1])
        : "r"(a0), "r"(a1), "r"(a2), "r"(a3), "r"(b0), "r"(b1));
}
__device__ __forceinline__ void ldsm4(uint32_t& r0, uint32_t& r1, uint32_t& r2, uint32_t& r3,
                                      uint32_t addr) {
    asm volatile("ldmatrix.sync.aligned.m8n8.x4.shared.b16 {%0,%1,%2,%3}, [%4];"
                 : "=r"(r0), "=r"(r1), "=r"(r2), "=r"(r3) : "r"(addr));
}
__device__ __forceinline__ void cp16(uint32_t s, const void* g) {
    asm volatile("cp.async.cg.shared.global [%0], [%1], 16;" :: "r"(s), "l"(g));
}
#define CP_COMMIT() asm volatile("cp.async.commit_group;" ::: "memory")
#define CP_WAIT(n)  asm volatile("cp.async.wait_group %0;" :: "n"(n) : "memory")

__device__ __forceinline__ void fsplit(float v, __half& h, __half& l) {
    h = __float2half_rn(v);
    l = __float2half_rn(v - __half2float(h));
}
// fast tanh: exact ±1 in the saturated region, libm tanhf only in |v| < SAT_T
__device__ __forceinline__ float tanh_sat(float v) {
    if (fabsf(v) >= SAT_T) return copysignf(1.0f, v);
    return tanhf(v);
}

// ---------------- probs (tiny) ---------------------------------------------------
__global__ void probs_kernel(const float* __restrict__ tw) {
    __shared__ float st[2][HH];
    const int r = blockIdx.x, t = threadIdx.x;
    for (int i = t; i < HH; i += blockDim.x) st[0][i] = 0.03125f;
    __syncthreads();
    int cur = 0;
    #pragma unroll 1
    for (int d = 0; d < DEPTH; ++d)
        #pragma unroll 1
        for (int k = 0; k < 3; ++k) {
            const float ang = tw[((size_t)d * HH + r) * HH + k];
            const float c = cosf(ang), s = sinf(ang);
            const int nxt = cur ^ 1;
            for (int i = t; i < HH; i += blockDim.x)
                st[nxt][i] = c * st[cur][i]
                           - s * st[cur][(i + 1) & (HH - 1)]
                           + s * st[cur][(i - 1) & (HH - 1)];
            __syncthreads();
            cur = nxt;
        }
    if (t == 0) { const float v = st[cur][0]; g_probs[r] = v * v; }
}

// ---------------- x split: fp32 -> fp16 hi/lo -------------------------------------
__global__ void splitx_kernel(const float4* __restrict__ in,
                              __half2* __restrict__ oh, __half2* __restrict__ ol, int n4) {
    int i = blockIdx.x * blockDim.x + threadIdx.x;
    if (i >= n4) return;
    float4 v = in[i];
    __half h0, h1, h2, h3, l0, l1, l2, l3;
    fsplit(v.x, h0, l0); fsplit(v.y, h1, l1);
    fsplit(v.z, h2, l2); fsplit(v.w, h3, l3);
    oh[2 * i]     = __halves2half2(h0, h1);
    oh[2 * i + 1] = __halves2half2(h2, h3);
    ol[2 * i]     = __halves2half2(l0, l1);
    ol[2 * i + 1] = __halves2half2(l2, l3);
}

// ---------------- weight transpose + split: w[K][N] fp32 -> [N][K] fp16 h/l -------
__global__ void tsplit_kernel(const float* __restrict__ w,
                              __half* __restrict__ th, __half* __restrict__ tl,
                              int Kd, int Nd) {
    __shared__ float tile[32][33];
    const int nb = blockIdx.x * 32, kb = blockIdx.y * 32;
    const int tx = threadIdx.x, ty = threadIdx.y;   // 32 x 8
    #pragma unroll
    for (int i = 0; i < 32; i += 8)
        tile[ty + i][tx] = w[(size_t)(kb + ty + i) * Nd + nb + tx];
    __syncthreads();
    #pragma unroll
    for (int i = 0; i < 32; i += 8) {
        const float v = tile[tx][ty + i];
        __half h, l;
        fsplit(v, h, l);
        const size_t o = (size_t)(nb + ty + i) * Kd + kb + tx;
        th[o] = h;
        tl[o] = l;
    }
}

// ---------------- repair: exact fp32 recompute of flagged tanh entries ------------
__global__ void repair_kernel(const __half2* __restrict__ h2h, const __half2* __restrict__ h2l,
                              const __half2* __restrict__ cwh, const __half2* __restrict__ cwl,
                              const float* __restrict__ cb,
                              __half* __restrict__ xh, __half* __restrict__ xl) {
    const uint32_t n = min(g_flagn, FLAG_CAP);
    const int lane = threadIdx.x & 31;
    const uint32_t warp = (blockIdx.x * blockDim.x + threadIdx.x) >> 5;
    const uint32_t nw = (gridDim.x * blockDim.x) >> 5;
    for (uint32_t e = warp; e < n; e += nw) {
        const uint32_t f = g_flags[e];
        const int row = f >> 10, col = f & 1023;
        const __half2* ah = h2h + (size_t)row * 512;
        const __half2* al = h2l + (size_t)row * 512;
        const __half2* wh = cwh + (size_t)col * 512;
        const __half2* wl = cwl + (size_t)col * 512;
        float s = 0.f;
        #pragma unroll 4
        for (int k = lane; k < 512; k += 32) {
            const float2 a0 = __half22float2(ah[k]);
            const float2 a1 = __half22float2(al[k]);
            const float2 w0 = __half22float2(wh[k]);
            const float2 w1 = __half22float2(wl[k]);
            s = fmaf(a0.x + a1.x, w0.x + w1.x, s);
            s = fmaf(a0.y + a1.y, w0.y + w1.y, s);
        }
        #pragma unroll
        for (int o = 16; o; o >>= 1) s += __shfl_xor_sync(0xFFFFFFFFu, s, o);
        if (lane == 0) {
            const float v = tanh_sat(s + cb[col] + g_probs[col]);
            __half h, l;
            fsplit(v, h, l);
            xh[(size_t)row * HH + col] = h;
            xl[(size_t)row * HH + col] = l;
        }
    }
}

// ---------------- split-fp16 GEMM (ldmatrix + mma.sync m16n8k16) ------------------
// 3-stage cp.async pipeline, ONE __syncthreads per chunk.
// 512 threads, 16 warps (4m x 4n), warp tile 32x32.
// PROD=3: hh(f32) + Al*Bh(f16) + Ah*Bl(f16).  PROD=2: hh + Ah*Bl.  PROD=1: hh only.
// EPI 0: relu->split   1: tanh_sat(+probs)->split + flag |pre|<T   2: relu->fp32
#define KT      64
#define LDH     72
#define TILE_B  (128 * LDH * 2)          // 18432 bytes per (array, tile)
#define NSTAGE  3
#define NTHREADS 512

template <int P> struct ArrCnt { static const int v = (P == 3) ? 4 : (P == 2) ? 3 : 2; };
#define SMEM_FOR(P) (NSTAGE * ArrCnt<P>::v * TILE_B)

template <int EPI, int PROD>
__global__ void __launch_bounds__(NTHREADS, 1)
mma_gemm(const __half* __restrict__ Ah, const __half* __restrict__ Al,
         const __half* __restrict__ Bh, const __half* __restrict__ Bl,
         const float* __restrict__ bias,
         __half* __restrict__ Ch, __half* __restrict__ Cl,
         float* __restrict__ Cf,
         int M, int N, int K)
{
    constexpr bool NEED_AL = (PROD == 3);
    constexpr bool NEED_BL = (PROD >= 2);
    constexpr uint32_t STAGE_B = ArrCnt<PROD>::v * TILE_B;
    constexpr uint32_t OFF_AL  = TILE_B;
    constexpr uint32_t OFF_BH  = (NEED_AL ? 2 : 1) * TILE_B;
    constexpr uint32_t OFF_BL  = OFF_BH + TILE_B;

    extern __shared__ __align__(16) char smem[];
    const uint32_t sbase = s2u(smem);
    const int tid  = threadIdx.x;
    const int lane = tid & 31;
    const int warp = tid >> 5;
    const int wm   = (warp & 3) * 32;
    const int wn   = (warp >> 2) * 32;
    const int g    = lane >> 2;
    const int tg   = lane & 3;

    const int bm = blockIdx.y * 128;
    const int bn = blockIdx.x * 128;

    const int rowA = wm + (lane & 7) + 8 * ((lane >> 3) & 1);
    const int khA  = 8 * (lane >> 4);
    const uint32_t offA = (uint32_t)(rowA * LDH + khA) * 2;
    const int colB = wn + 8 * (lane >> 3) + (lane & 7);
    const uint32_t offB = (uint32_t)(colB * LDH) * 2;

    float    acc[2][4][4];
    uint32_t accx[2][4][2];
    #pragma unroll
    for (int i = 0; i < 2; ++i)
        #pragma unroll
        for (int j = 0; j < 4; ++j) {
            #pragma unroll
            for (int q = 0; q < 4; ++q) acc[i][j][q] = 0.f;
            accx[i][j][0] = 0u; accx[i][j][1] = 0u;
        }

    const int srow = tid >> 3;
    const int sseg = tid & 7;

    auto load_chunk = [&](int c, int s) {
        const int k0 = c * KT;
        const uint32_t sb = sbase + (uint32_t)s * STAGE_B;
        #pragma unroll
        for (int r = 0; r < 2; ++r) {
            const int row = srow + 64 * r;
            const uint32_t so = (uint32_t)(row * LDH + sseg * 8) * 2;
            const size_t  ga = (size_t)(bm + row) * K + k0 + sseg * 8;
            const size_t  gb = (size_t)(bn + row) * K + k0 + sseg * 8;
            cp16(sb + so, Ah + ga);
            if (NEED_AL) cp16(sb + OFF_AL + so, Al + ga);
            cp16(sb + OFF_BH + so, Bh + gb);
            if (NEED_BL) cp16(sb + OFF_BL + so, Bl + gb);
        }
    };

    const int NC = K / KT;
    load_chunk(0, 0); CP_COMMIT();
    load_chunk(1, 1); CP_COMMIT();

    #pragma unroll 1
    for (int c = 0; c < NC; ++c) {
        const int s = c - (c / NSTAGE) * NSTAGE;
        if (c + 2 < NC) { CP_WAIT(1); } else { CP_WAIT(0); }
        __syncthreads();
        if (c + 2 < NC) {
            const int ns = (c + 2) - ((c + 2) / NSTAGE) * NSTAGE;
            load_chunk(c + 2, ns);
            CP_COMMIT();
        }

        const uint32_t sb = sbase + (uint32_t)s * STAGE_B;
        #pragma unroll
        for (int k16 = 0; k16 < KT / 16; ++k16) {
            const uint32_t kb = (uint32_t)(k16 * 16) * 2;

            uint32_t a_h[2][4], a_l[2][4];
            #pragma unroll
            for (int i = 0; i < 2; ++i) {
                const uint32_t ao = offA + (uint32_t)(i * 16 * LDH) * 2 + kb;
                ldsm4(a_h[i][0], a_h[i][1], a_h[i][2], a_h[i][3], sb + ao);
                if (NEED_AL) ldsm4(a_l[i][0], a_l[i][1], a_l[i][2], a_l[i][3], sb + OFF_AL + ao);
            }
            uint32_t b_h[4][2], b_l[4][2];
            ldsm4(b_h[0][0], b_h[1][0], b_h[2][0], b_h[3][0], sb + OFF_BH + offB + kb);
            ldsm4(b_h[0][1], b_h[1][1], b_h[2][1], b_h[3][1], sb + OFF_BH + offB + kb + 16);
            if (NEED_BL) {
                ldsm4(b_l[0][0], b_l[1][0], b_l[2][0], b_l[3][0], sb + OFF_BL + offB + kb);
                ldsm4(b_l[0][1], b_l[1][1], b_l[2][1], b_l[3][1], sb + OFF_BL + offB + kb + 16);
            }

            #pragma unroll
            for (int i = 0; i < 2; ++i)
                #pragma unroll
                for (int j = 0; j < 4; ++j)
                    mma16(acc[i][j], a_h[i][0], a_h[i][1], a_h[i][2], a_h[i][3], b_h[j][0], b_h[j][1]);
            if (NEED_AL) {
                #pragma unroll
                for (int i = 0; i < 2; ++i)
                    #pragma unroll
                    for (int j = 0; j < 4; ++j)
                        mma16h(accx[i][j], a_l[i][0], a_l[i][1], a_l[i][2], a_l[i][3], b_h[j][0], b_h[j][1]);
            }
            if (NEED_BL) {
                #pragma unroll
                for (int i = 0; i < 2; ++i)
                    #pragma unroll
                    for (int j = 0; j < 4; ++j)
                        mma16h(accx[i][j], a_h[i][0], a_h[i][1], a_h[i][2], a_h[i][3], b_l[j][0], b_l[j][1]);
            }
        }
    }

    // ---- epilogue ----
    #pragma unroll
    for (int j = 0; j < 4; ++j) {
        const int col = bn + wn + j * 8 + 2 * tg;
        const float b0 = bias[col], b1 = bias[col + 1];
        float p0 = 0.f, p1 = 0.f;
        if (EPI == 1) { p0 = g_probs[col]; p1 = g_probs[col + 1]; }
        #pragma unroll
        for (int i = 0; i < 2; ++i) {
            const int row = bm + wm + i * 16 + g;
            const float2 x0 = __half22float2(*(__half2*)&accx[i][j][0]);
            const float2 x1 = __half22float2(*(__half2*)&accx[i][j][1]);
            float v0 = acc[i][j][0] + x0.x + b0;
            float v1 = acc[i][j][1] + x0.y + b1;
            float v2 = acc[i][j][2] + x1.x + b0;
            float v3 = acc[i][j][3] + x1.y + b1;
            if (EPI == 1) {
                v0 += p0; v1 += p1; v2 += p0; v3 += p1;
                auto push = [&](float pv, int r, int cc) {
                    if (fabsf(pv) < FLAG_T) {
                        const uint32_t idx = atomicAdd(&g_flagn, 1u);
                        if (idx < FLAG_CAP)
                            g_flags[idx] = ((uint32_t)r << 10) | (uint32_t)cc;
                    }
                };
                push(v0, row, col); push(v1, row, col + 1);
                push(v2, row + 8, col); push(v3, row + 8, col + 1);
                v0 = tanh_sat(v0); v1 = tanh_sat(v1);
                v2 = tanh_sat(v2); v3 = tanh_sat(v3);
            } else {
                v0 = fmaxf(v0, 0.f); v1 = fmaxf(v1, 0.f);
                v2 = fmaxf(v2, 0.f); v3 = fmaxf(v3, 0.f);
            }
            if (EPI == 2) {
                *reinterpret_cast<float2*>(&Cf[(size_t)row * N + col])       = make_float2(v0, v1);
                *reinterpret_cast<float2*>(&Cf[(size_t)(row + 8) * N + col]) = make_float2(v2, v3);
            } else {
                __half h0, h1, h2, h3, l0, l1, l2, l3;
                fsplit(v0, h0, l0); fsplit(v1, h1, l1);
                fsplit(v2, h2, l2); fsplit(v3, h3, l3);
                *reinterpret_cast<__half2*>(&Ch[(size_t)row * N + col])       = __halves2half2(h0, h1);
                *reinterpret_cast<__half2*>(&Ch[(size_t)(row + 8) * N + col]) = __halves2half2(h2, h3);
                *reinterpret_cast<__half2*>(&Cl[(size_t)row * N + col])       = __halves2half2(l0, l1);
                *reinterpret_cast<__half2*>(&Cl[(size_t)(row + 8) * N + col]) = __halves2half2(l2, l3);
            }
        }
    }
}

// ---------------- host --------------------------------------------------------------
extern "C" void kernel_launch(void* const* d_in, const int* in_sizes, int n_in,
                              void* d_out, int out_size) {
    const float* x    = (const float*)d_in[0];
    const float* w0   = (const float*)d_in[1];
    const float* b0   = (const float*)d_in[2];
    const float* w1   = (const float*)d_in[3];
    const float* b1   = (const float*)d_in[4];
    const float* tw   = (const float*)d_in[5];
    const float* cw   = (const float*)d_in[6];
    const float* cb   = (const float*)d_in[7];
    const float* wout = (const float*)d_in[8];
    const float* bout = (const float*)d_in[9];
    float* out = (float*)d_out;

    __half *xh, *xl, *h1h, *h1l, *h2h, *h2l;
    __half *w0h, *w0l, *w1h, *w1l, *cwh, *cwl, *woh, *wol;
    uint32_t* flagn;
    cudaGetSymbolAddress((void**)&xh,  g_xh);   cudaGetSymbolAddress((void**)&xl,  g_xl);
    cudaGetSymbolAddress((void**)&h1h, g_h1h);  cudaGetSymbolAddress((void**)&h1l, g_h1l);
    cudaGetSymbolAddress((void**)&h2h, g_h2h);  cudaGetSymbolAddress((void**)&h2l, g_h2l);
    cudaGetSymbolAddress((void**)&w0h, g_w0h);  cudaGetSymbolAddress((void**)&w0l, g_w0l);
    cudaGetSymbolAddress((void**)&w1h, g_w1h);  cudaGetSymbolAddress((void**)&w1l, g_w1l);
    cudaGetSymbolAddress((void**)&cwh, g_cwh);  cudaGetSymbolAddress((void**)&cwl, g_cwl);
    cudaGetSymbolAddress((void**)&woh, g_woh);  cudaGetSymbolAddress((void**)&wol, g_wol);
    cudaGetSymbolAddress((void**)&flagn, g_flagn);

    cudaFuncSetAttribute(mma_gemm<0,3>, cudaFuncAttributeMaxDynamicSharedMemorySize, SMEM_FOR(3));
    cudaFuncSetAttribute(mma_gemm<1,1>, cudaFuncAttributeMaxDynamicSharedMemorySize, SMEM_FOR(1));
    cudaFuncSetAttribute(mma_gemm<2,1>, cudaFuncAttributeMaxDynamicSharedMemorySize, SMEM_FOR(1));

    probs_kernel<<<HH, 256>>>(tw);
    {
        const int n4 = BB * DIN / 4;
        splitx_kernel<<<(n4 + 255) / 256, 256>>>((const float4*)x, (__half2*)xh, (__half2*)xl, n4);
    }
    tsplit_kernel<<<dim3(HH / 32,   DIN / 32), dim3(32, 8)>>>(w0,   w0h, w0l, DIN, HH);
    tsplit_kernel<<<dim3(HH / 32,   HH  / 32), dim3(32, 8)>>>(w1,   w1h, w1l, HH,  HH);
    tsplit_kernel<<<dim3(HH / 32,   HH  / 32), dim3(32, 8)>>>(cw,   cwh, cwl, HH,  HH);
    tsplit_kernel<<<dim3(DOUT / 32, HH  / 32), dim3(32, 8)>>>(wout, woh, wol, HH,  DOUT);
    cudaMemsetAsync(flagn, 0, sizeof(uint32_t));

    // layer 1: relu(x @ w0 + b0)            — 3 products
    mma_gemm<0,3><<<dim3(HH / 128,   BB / 128), NTHREADS, SMEM_FOR(3)>>>(
        xh,  xl,  w0h, w0l, b0,   h1h, h1l, nullptr, BB, HH,   DIN);
    // layer 2: relu(h1 @ w1 + b1)           — 3 products
    mma_gemm<0,3><<<dim3(HH / 128,   BB / 128), NTHREADS, SMEM_FOR(3)>>>(
        h1h, h1l, w1h, w1l, b1,   h2h, h2l, nullptr, BB, HH,   HH);
    // layer 3: tanh(h2 @ cw + cb + probs)   — hh only + flags (T=64, 9 sigma)
    mma_gemm<1,1><<<dim3(HH / 128,   BB / 128), NTHREADS, SMEM_FOR(1)>>>(
        h2h, h2l, cwh, cwl, cb,   xh,  xl,  nullptr, BB, HH,   HH);
    // repair flagged entries exactly
    repair_kernel<<<512, 256>>>((const __half2*)h2h, (const __half2*)h2l,
                                (const __half2*)cwh, (const __half2*)cwl,
                                cb, xh, xl);
    // layer 4: relu(h3 @ wout + bout)       — 1 product (h3 exact-fp16; wl term ~2e-4)
    mma_gemm<2,1><<<dim3(DOUT / 128, BB / 128), NTHREADS, SMEM_FOR(1)>>>(
        xh,  xl,  woh, wol, bout, nullptr, nullptr, out, BB, DOUT, HH);
}

// round 13
// speedup vs baseline: 2.7507x; 1.1534x over previous
#include <cuda_runtime.h>
#include <cuda.h>
#include <cuda_fp16.h>
#include <math.h>
#include <stdint.h>

#define BB   16384
#define DIN  1024
#define HH   1024
#define DOUT 256
#define DEPTH 7

#define FLAG_CAP (1u << 22)
#define FLAG_T   64.0f
#define SAT_T    20.0f

// ---------------- device scratch (fp16 hi/lo operand arrays) ------------------
__device__ __half g_xh[(size_t)BB * HH],  g_xl[(size_t)BB * HH];    // x split; reused for h3
__device__ __half g_h1h[(size_t)BB * HH], g_h1l[(size_t)BB * HH];
__device__ __half g_h2h[(size_t)BB * HH], g_h2l[(size_t)BB * HH];
__device__ __half g_w0h[(size_t)HH * DIN],  g_w0l[(size_t)HH * DIN];   // [N][K]
__device__ __half g_w1h[(size_t)HH * HH],   g_w1l[(size_t)HH * HH];
__device__ __half g_cwh[(size_t)HH * HH],   g_cwl[(size_t)HH * HH];
__device__ __half g_woh[(size_t)DOUT * HH], g_wol[(size_t)DOUT * HH];
__device__ float  g_probs[HH];
__device__ uint32_t g_flags[FLAG_CAP];
__device__ uint32_t g_flagn;

// ---------------- helpers -------------------------------------------------------
__device__ __forceinline__ uint32_t s2u(const void* p) {
    uint32_t a;
    asm("{ .reg .u64 t; cvta.to.shared.u64 t, %1; cvt.u32.u64 %0, t; }" : "=r"(a) : "l"(p));
    return a;
}
__device__ __forceinline__ void mma16(float c[4],
                                      uint32_t a0, uint32_t a1, uint32_t a2, uint32_t a3,
                                      uint32_t b0, uint32_t b1) {
    asm volatile(
        "mma.sync.aligned.m16n8k16.row.col.f32.f16.f16.f32 "
        "{%0,%1,%2,%3}, {%4,%5,%6,%7}, {%8,%9}, {%0,%1,%2,%3};"
        : "+f"(c[0]), "+f"(c[1]), "+f"(c[2]), "+f"(c[3])
        : "r"(a0), "r"(a1), "r"(a2), "r"(a3), "r"(b0), "r"(b1));
}
__device__ __forceinline__ void mma16h(uint32_t c[2],
                                       uint32_t a0, uint32_t a1, uint32_t a2, uint32_t a3,
                                       uint32_t b0, uint32_t b1) {
    asm volatile(
        "mma.sync.aligned.m16n8k16.row.col.f16.f16.f16.f16 "
        "{%0,%1}, {%2,%3,%4,%5}, {%6,%7}, {%0,%1};"
        : "+r"(c[0]), "+r"(c[1])
        : "r"(a0), "r"(a1), "r"(a2), "r"(a3), "r"(b0), "r"(b1));
}
__device__ __forceinline__ void ldsm4(uint32_t& r0, uint32_t& r1, uint32_t& r2, uint32_t& r3,
                                      uint32_t addr) {
    asm volatile("ldmatrix.sync.aligned.m8n8.x4.shared.b16 {%0,%1,%2,%3}, [%4];"
                 : "=r"(r0), "=r"(r1), "=r"(r2), "=r"(r3) : "r"(addr));
}
__device__ __forceinline__ void mbar_init(uint32_t m, uint32_t cnt) {
    asm volatile("mbarrier.init.shared.b64 [%0], %1;" :: "r"(m), "r"(cnt) : "memory");
}
__device__ __forceinline__ void mbar_expect_tx(uint32_t m, uint32_t bytes) {
    asm volatile("mbarrier.arrive.expect_tx.shared.b64 _, [%0], %1;" :: "r"(m), "r"(bytes) : "memory");
}
__device__ __forceinline__ void mbar_wait(uint32_t m, uint32_t parity) {
    asm volatile(
        "{\n\t.reg .pred P;\n"
        "WL%=:\n\t"
        "mbarrier.try_wait.parity.acquire.cta.shared::cta.b64 P, [%0], %1, 0x989680;\n\t"
        "@P bra WD%=;\n\t"
        "bra WL%=;\n"
        "WD%=:\n\t}"
        :: "r"(m), "r"(parity) : "memory");
}
__device__ __forceinline__ void tma2d(uint32_t dst, const CUtensorMap* map,
                                      int x, int y, uint32_t mbar) {
    asm volatile(
        "cp.async.bulk.tensor.2d.shared::cta.global.tile.mbarrier::complete_tx::bytes "
        "[%0], [%1, {%2, %3}], [%4];"
        :: "r"(dst), "l"(map), "r"(x), "r"(y), "r"(mbar) : "memory");
}
__device__ __forceinline__ void fsplit(float v, __half& h, __half& l) {
    h = __float2half_rn(v);
    l = __float2half_rn(v - __half2float(h));
}
__device__ __forceinline__ float tanh_sat(float v) {
    if (fabsf(v) >= SAT_T) return copysignf(1.0f, v);
    return tanhf(v);
}

// ---------------- probs (tiny) ---------------------------------------------------
__global__ void probs_kernel(const float* __restrict__ tw) {
    __shared__ float st[2][HH];
    const int r = blockIdx.x, t = threadIdx.x;
    for (int i = t; i < HH; i += blockDim.x) st[0][i] = 0.03125f;
    __syncthreads();
    int cur = 0;
    #pragma unroll 1
    for (int d = 0; d < DEPTH; ++d)
        #pragma unroll 1
        for (int k = 0; k < 3; ++k) {
            const float ang = tw[((size_t)d * HH + r) * HH + k];
            const float c = cosf(ang), s = sinf(ang);
            const int nxt = cur ^ 1;
            for (int i = t; i < HH; i += blockDim.x)
                st[nxt][i] = c * st[cur][i]
                           - s * st[cur][(i + 1) & (HH - 1)]
                           + s * st[cur][(i - 1) & (HH - 1)];
            __syncthreads();
            cur = nxt;
        }
    if (t == 0) { const float v = st[cur][0]; g_probs[r] = v * v; }
}

// ---------------- x split: fp32 -> fp16 hi/lo -------------------------------------
__global__ void splitx_kernel(const float4* __restrict__ in,
                              __half2* __restrict__ oh, __half2* __restrict__ ol, int n4) {
    int i = blockIdx.x * blockDim.x + threadIdx.x;
    if (i >= n4) return;
    float4 v = in[i];
    __half h0, h1, h2, h3, l0, l1, l2, l3;
    fsplit(v.x, h0, l0); fsplit(v.y, h1, l1);
    fsplit(v.z, h2, l2); fsplit(v.w, h3, l3);
    oh[2 * i]     = __halves2half2(h0, h1);
    oh[2 * i + 1] = __halves2half2(h2, h3);
    ol[2 * i]     = __halves2half2(l0, l1);
    ol[2 * i + 1] = __halves2half2(l2, l3);
}

// ---------------- weight transpose + split: w[K][N] fp32 -> [N][K] fp16 h/l -------
__global__ void tsplit_kernel(const float* __restrict__ w,
                              __half* __restrict__ th, __half* __restrict__ tl,
                              int Kd, int Nd) {
    __shared__ float tile[32][33];
    const int nb = blockIdx.x * 32, kb = blockIdx.y * 32;
    const int tx = threadIdx.x, ty = threadIdx.y;   // 32 x 8
    #pragma unroll
    for (int i = 0; i < 32; i += 8)
        tile[ty + i][tx] = w[(size_t)(kb + ty + i) * Nd + nb + tx];
    __syncthreads();
    #pragma unroll
    for (int i = 0; i < 32; i += 8) {
        const float v = tile[tx][ty + i];
        __half h, l;
        fsplit(v, h, l);
        const size_t o = (size_t)(nb + ty + i) * Kd + kb + tx;
        th[o] = h;
        tl[o] = l;
    }
}

// ---------------- repair: exact fp32 recompute of flagged tanh entries ------------
__global__ void repair_kernel(const __half2* __restrict__ h2h, const __half2* __restrict__ h2l,
                              const __half2* __restrict__ cwh, const __half2* __restrict__ cwl,
                              const float* __restrict__ cb,
                              __half* __restrict__ xh, __half* __restrict__ xl) {
    const uint32_t n = min(g_flagn, FLAG_CAP);
    const int lane = threadIdx.x & 31;
    const uint32_t warp = (blockIdx.x * blockDim.x + threadIdx.x) >> 5;
    const uint32_t nw = (gridDim.x * blockDim.x) >> 5;
    for (uint32_t e = warp; e < n; e += nw) {
        const uint32_t f = g_flags[e];
        const int row = f >> 10, col = f & 1023;
        const __half2* ah = h2h + (size_t)row * 512;
        const __half2* al = h2l + (size_t)row * 512;
        const __half2* wh = cwh + (size_t)col * 512;
        const __half2* wl = cwl + (size_t)col * 512;
        float s = 0.f;
        #pragma unroll 4
        for (int k = lane; k < 512; k += 32) {
            const float2 a0 = __half22float2(ah[k]);
            const float2 a1 = __half22float2(al[k]);
            const float2 w0 = __half22float2(wh[k]);
            const float2 w1 = __half22float2(wl[k]);
            s = fmaf(a0.x + a1.x, w0.x + w1.x, s);
            s = fmaf(a0.y + a1.y, w0.y + w1.y, s);
        }
        #pragma unroll
        for (int o = 16; o; o >>= 1) s += __shfl_xor_sync(0xFFFFFFFFu, s, o);
        if (lane == 0) {
            const float v = tanh_sat(s + cb[col] + g_probs[col]);
            __half h, l;
            fsplit(v, h, l);
            xh[(size_t)row * HH + col] = h;
            xl[(size_t)row * HH + col] = l;
        }
    }
}

// ---------------- split-fp16 GEMM: TMA loads + ldmatrix + mma.sync ----------------
// Loads via cp.async.bulk.tensor.2d (1 instr per 16KB tile vs 1024 cp.async) —
// removes the LSU-issue bottleneck. SW128-swizzled 128B-row tiles; ldmatrix
// addressing uses byte ^ ((row&7)<<4). 3-stage mbarrier pipeline, one
// __syncthreads per chunk as the stage-empty signal.
// PROD=3: hh(f32)+Al*Bh(f16)+Ah*Bl(f16).  PROD=1: hh only.
// EPI 0: relu->split   1: tanh_sat(+probs)->split + flag   2: relu->fp32
#define KT       64
#define TILE_BT  16384u                  // 128 rows x 128 B
#define NSTAGE   3
#define NTHREADS 512

template <int P> struct ArrCnt { static const int v = (P == 3) ? 4 : (P == 2) ? 3 : 2; };
#define SMEM_FOR(P) (NSTAGE * ArrCnt<P>::v * (int)TILE_BT + 64)

template <int EPI, int PROD>
__global__ void __launch_bounds__(NTHREADS, 1)
mma_gemm(const __grid_constant__ CUtensorMap mAh,
         const __grid_constant__ CUtensorMap mAl,
         const __grid_constant__ CUtensorMap mBh,
         const __grid_constant__ CUtensorMap mBl,
         const float* __restrict__ bias,
         __half* __restrict__ Ch, __half* __restrict__ Cl,
         float* __restrict__ Cf,
         int M, int N, int K)
{
    constexpr bool NEED_AL = (PROD == 3);
    constexpr bool NEED_BL = (PROD >= 2);
    constexpr uint32_t STAGE_B = ArrCnt<PROD>::v * TILE_BT;
    constexpr uint32_t OFF_AL  = TILE_BT;
    constexpr uint32_t OFF_BH  = (NEED_AL ? 2u : 1u) * TILE_BT;
    constexpr uint32_t OFF_BL  = OFF_BH + TILE_BT;
    constexpr uint32_t TX_BYTES = STAGE_B;

    extern __shared__ __align__(1024) char smem[];
    const uint32_t sbase = s2u(smem);
    const uint32_t barb  = sbase + NSTAGE * STAGE_B;   // 3 mbarriers (8B each)

    const int tid  = threadIdx.x;
    const int lane = tid & 31;
    const int warp = tid >> 5;
    const int wm   = (warp & 3) * 32;
    const int wn   = (warp >> 2) * 32;
    const int g    = lane >> 2;
    const int tg   = lane & 3;

    const int bm = blockIdx.y * 128;
    const int bn = blockIdx.x * 128;

    if (tid == 0) {
        mbar_init(barb + 0, 1);
        mbar_init(barb + 8, 1);
        mbar_init(barb + 16, 1);
    }
    __syncthreads();

    auto issue = [&](int c, int s) {
        const uint32_t st = sbase + (uint32_t)s * STAGE_B;
        const int k0 = c * KT;
        mbar_expect_tx(barb + 8 * s, TX_BYTES);
        tma2d(st,          &mAh, k0, bm, barb + 8 * s);
        if (NEED_AL) tma2d(st + OFF_AL, &mAl, k0, bm, barb + 8 * s);
        tma2d(st + OFF_BH, &mBh, k0, bn, barb + 8 * s);
        if (NEED_BL) tma2d(st + OFF_BL, &mBl, k0, bn, barb + 8 * s);
    };

    // ldmatrix swizzled addressing
    const uint32_t swz   = (uint32_t)(lane & 7) << 4;
    const uint32_t aRow0 = (uint32_t)((lane & 7) + 8 * ((lane >> 3) & 1)) * 128 + (uint32_t)wm * 128;
    const uint32_t aB0   = 16u * (uint32_t)(lane >> 4);
    const uint32_t bRow  = (uint32_t)(wn + 8 * (lane >> 3) + (lane & 7)) * 128;

    float    acc[2][4][4];
    uint32_t accx[2][4][2];
    #pragma unroll
    for (int i = 0; i < 2; ++i)
        #pragma unroll
        for (int j = 0; j < 4; ++j) {
            #pragma unroll
            for (int q = 0; q < 4; ++q) acc[i][j][q] = 0.f;
            accx[i][j][0] = 0u; accx[i][j][1] = 0u;
        }

    const int NC = K / KT;
    if (tid == 0) { issue(0, 0); issue(1, 1); }

    #pragma unroll 1
    for (int c = 0; c < NC; ++c) {
        const int s = c - (c / NSTAGE) * NSTAGE;   // c % 3
        __syncthreads();                            // stage (c+2)%3 fully consumed
        if (tid == 0 && c + 2 < NC) {
            const int ns = (c + 2) - ((c + 2) / NSTAGE) * NSTAGE;
            issue(c + 2, ns);
        }
        mbar_wait(barb + 8 * s, (uint32_t)(c / NSTAGE) & 1u);

        const uint32_t st  = sbase + (uint32_t)s * STAGE_B;
        const uint32_t tAh = st;
        const uint32_t tAl = st + OFF_AL;
        const uint32_t tBh = st + OFF_BH;
        const uint32_t tBl = st + OFF_BL;

        #pragma unroll
        for (int k16 = 0; k16 < KT / 16; ++k16) {
            const uint32_t kbase = (uint32_t)(k16 * 32);
            const uint32_t ka  = (kbase + aB0) ^ swz;
            const uint32_t kb0 = kbase ^ swz;
            const uint32_t kb1 = (kbase + 16u) ^ swz;

            uint32_t a_h[2][4], a_l[2][4];
            #pragma unroll
            for (int i = 0; i < 2; ++i) {
                const uint32_t ao = aRow0 + (uint32_t)(i * 16 * 128) + ka;
                ldsm4(a_h[i][0], a_h[i][1], a_h[i][2], a_h[i][3], tAh + ao);
                if (NEED_AL) ldsm4(a_l[i][0], a_l[i][1], a_l[i][2], a_l[i][3], tAl + ao);
            }
            uint32_t b_h[4][2], b_l[4][2];
            ldsm4(b_h[0][0], b_h[1][0], b_h[2][0], b_h[3][0], tBh + bRow + kb0);
            ldsm4(b_h[0][1], b_h[1][1], b_h[2][1], b_h[3][1], tBh + bRow + kb1);
            if (NEED_BL) {
                ldsm4(b_l[0][0], b_l[1][0], b_l[2][0], b_l[3][0], tBl + bRow + kb0);
                ldsm4(b_l[0][1], b_l[1][1], b_l[2][1], b_l[3][1], tBl + bRow + kb1);
            }

            #pragma unroll
            for (int i = 0; i < 2; ++i)
                #pragma unroll
                for (int j = 0; j < 4; ++j)
                    mma16(acc[i][j], a_h[i][0], a_h[i][1], a_h[i][2], a_h[i][3], b_h[j][0], b_h[j][1]);
            if (NEED_AL) {
                #pragma unroll
                for (int i = 0; i < 2; ++i)
                    #pragma unroll
                    for (int j = 0; j < 4; ++j)
                        mma16h(accx[i][j], a_l[i][0], a_l[i][1], a_l[i][2], a_l[i][3], b_h[j][0], b_h[j][1]);
            }
            if (NEED_BL) {
                #pragma unroll
                for (int i = 0; i < 2; ++i)
                    #pragma unroll
                    for (int j = 0; j < 4; ++j)
                        mma16h(accx[i][j], a_h[i][0], a_h[i][1], a_h[i][2], a_h[i][3], b_l[j][0], b_l[j][1]);
            }
        }
    }

    // ---- epilogue ----
    #pragma unroll
    for (int j = 0; j < 4; ++j) {
        const int col = bn + wn + j * 8 + 2 * tg;
        const float b0 = bias[col], b1 = bias[col + 1];
        float p0 = 0.f, p1 = 0.f;
        if (EPI == 1) { p0 = g_probs[col]; p1 = g_probs[col + 1]; }
        #pragma unroll
        for (int i = 0; i < 2; ++i) {
            const int row = bm + wm + i * 16 + g;
            const float2 x0 = __half22float2(*(__half2*)&accx[i][j][0]);
            const float2 x1 = __half22float2(*(__half2*)&accx[i][j][1]);
            float v0 = acc[i][j][0] + x0.x + b0;
            float v1 = acc[i][j][1] + x0.y + b1;
            float v2 = acc[i][j][2] + x1.x + b0;
            float v3 = acc[i][j][3] + x1.y + b1;
            if (EPI == 1) {
                v0 += p0; v1 += p1; v2 += p0; v3 += p1;
                auto push = [&](float pv, int r, int cc) {
                    if (fabsf(pv) < FLAG_T) {
                        const uint32_t idx = atomicAdd(&g_flagn, 1u);
                        if (idx < FLAG_CAP)
                            g_flags[idx] = ((uint32_t)r << 10) | (uint32_t)cc;
                    }
                };
                push(v0, row, col); push(v1, row, col + 1);
                push(v2, row + 8, col); push(v3, row + 8, col + 1);
                v0 = tanh_sat(v0); v1 = tanh_sat(v1);
                v2 = tanh_sat(v2); v3 = tanh_sat(v3);
            } else {
                v0 = fmaxf(v0, 0.f); v1 = fmaxf(v1, 0.f);
                v2 = fmaxf(v2, 0.f); v3 = fmaxf(v3, 0.f);
            }
            if (EPI == 2) {
                *reinterpret_cast<float2*>(&Cf[(size_t)row * N + col])       = make_float2(v0, v1);
                *reinterpret_cast<float2*>(&Cf[(size_t)(row + 8) * N + col]) = make_float2(v2, v3);
            } else {
                __half h0, h1, h2, h3, l0, l1, l2, l3;
                fsplit(v0, h0, l0); fsplit(v1, h1, l1);
                fsplit(v2, h2, l2); fsplit(v3, h3, l3);
                *reinterpret_cast<__half2*>(&Ch[(size_t)row * N + col])       = __halves2half2(h0, h1);
                *reinterpret_cast<__half2*>(&Ch[(size_t)(row + 8) * N + col]) = __halves2half2(h2, h3);
                *reinterpret_cast<__half2*>(&Cl[(size_t)row * N + col])       = __halves2half2(l0, l1);
                *reinterpret_cast<__half2*>(&Cl[(size_t)(row + 8) * N + col]) = __halves2half2(l2, l3);
            }
        }
    }
}

// ---------------- host --------------------------------------------------------------
typedef CUresult (*tmap_fn_t)(CUtensorMap*, CUtensorMapDataType, cuuint32_t, void*,
                              const cuuint64_t*, const cuuint64_t*,
                              const cuuint32_t*, const cuuint32_t*,
                              CUtensorMapInterleave, CUtensorMapSwizzle,
                              CUtensorMapL2promotion, CUtensorMapFloatOOBfill);

static void enc2d(tmap_fn_t f, CUtensorMap* m, __half* p, uint64_t Kd, uint64_t rows) {
    cuuint64_t dims[2] = {Kd, rows};
    cuuint64_t str[1]  = {Kd * 2};
    cuuint32_t box[2]  = {KT, 128};
    cuuint32_t es[2]   = {1, 1};
    f(m, CU_TENSOR_MAP_DATA_TYPE_FLOAT16, 2, (void*)p, dims, str, box, es,
      CU_TENSOR_MAP_INTERLEAVE_NONE, CU_TENSOR_MAP_SWIZZLE_128B,
      CU_TENSOR_MAP_L2_PROMOTION_L2_128B, CU_TENSOR_MAP_FLOAT_OOB_FILL_NONE);
}

extern "C" void kernel_launch(void* const* d_in, const int* in_sizes, int n_in,
                              void* d_out, int out_size) {
    const float* x    = (const float*)d_in[0];
    const float* w0   = (const float*)d_in[1];
    const float* b0   = (const float*)d_in[2];
    const float* w1   = (const float*)d_in[3];
    const float* b1   = (const float*)d_in[4];
    const float* tw   = (const float*)d_in[5];
    const float* cw   = (const float*)d_in[6];
    const float* cb   = (const float*)d_in[7];
    const float* wout = (const float*)d_in[8];
    const float* bout = (const float*)d_in[9];
    float* out = (float*)d_out;

    __half *xh, *xl, *h1h, *h1l, *h2h, *h2l;
    __half *w0h, *w0l, *w1h, *w1l, *cwh, *cwl, *woh, *wol;
    uint32_t* flagn;
    cudaGetSymbolAddress((void**)&xh,  g_xh);   cudaGetSymbolAddress((void**)&xl,  g_xl);
    cudaGetSymbolAddress((void**)&h1h, g_h1h);  cudaGetSymbolAddress((void**)&h1l, g_h1l);
    cudaGetSymbolAddress((void**)&h2h, g_h2h);  cudaGetSymbolAddress((void**)&h2l, g_h2l);
    cudaGetSymbolAddress((void**)&w0h, g_w0h);  cudaGetSymbolAddress((void**)&w0l, g_w0l);
    cudaGetSymbolAddress((void**)&w1h, g_w1h);  cudaGetSymbolAddress((void**)&w1l, g_w1l);
    cudaGetSymbolAddress((void**)&cwh, g_cwh);  cudaGetSymbolAddress((void**)&cwl, g_cwl);
    cudaGetSymbolAddress((void**)&woh, g_woh);  cudaGetSymbolAddress((void**)&wol, g_wol);
    cudaGetSymbolAddress((void**)&flagn, g_flagn);

    void* fp = nullptr;
    cudaDriverEntryPointQueryResult qr;
    cudaGetDriverEntryPoint("cuTensorMapEncodeTiled", &fp, cudaEnableDefault, &qr);
    tmap_fn_t enc = (tmap_fn_t)fp;

    CUtensorMap mXh, mXl, mH1h, mH1l, mH2h, mH2l;
    CUtensorMap mW0h, mW0l, mW1h, mW1l, mCWh, mCWl, mWOh, mWOl;
    enc2d(enc, &mXh,  xh,  DIN, BB);
    enc2d(enc, &mXl,  xl,  DIN, BB);
    enc2d(enc, &mH1h, h1h, HH,  BB);
    enc2d(enc, &mH1l, h1l, HH,  BB);
    enc2d(enc, &mH2h, h2h, HH,  BB);
    enc2d(enc, &mH2l, h2l, HH,  BB);
    enc2d(enc, &mW0h, w0h, DIN, HH);
    enc2d(enc, &mW0l, w0l, DIN, HH);
    enc2d(enc, &mW1h, w1h, HH,  HH);
    enc2d(enc, &mW1l, w1l, HH,  HH);
    enc2d(enc, &mCWh, cwh, HH,  HH);
    enc2d(enc, &mCWl, cwl, HH,  HH);
    enc2d(enc, &mWOh, woh, HH,  DOUT);
    enc2d(enc, &mWOl, wol, HH,  DOUT);

    cudaFuncSetAttribute(mma_gemm<0,3>, cudaFuncAttributeMaxDynamicSharedMemorySize, SMEM_FOR(3));
    cudaFuncSetAttribute(mma_gemm<1,1>, cudaFuncAttributeMaxDynamicSharedMemorySize, SMEM_FOR(1));
    cudaFuncSetAttribute(mma_gemm<2,1>, cudaFuncAttributeMaxDynamicSharedMemorySize, SMEM_FOR(1));

    probs_kernel<<<HH, 256>>>(tw);
    {
        const int n4 = BB * DIN / 4;
        splitx_kernel<<<(n4 + 255) / 256, 256>>>((const float4*)x, (__half2*)xh, (__half2*)xl, n4);
    }
    tsplit_kernel<<<dim3(HH / 32,   DIN / 32), dim3(32, 8)>>>(w0,   w0h, w0l, DIN, HH);
    tsplit_kernel<<<dim3(HH / 32,   HH  / 32), dim3(32, 8)>>>(w1,   w1h, w1l, HH,  HH);
    tsplit_kernel<<<dim3(HH / 32,   HH  / 32), dim3(32, 8)>>>(cw,   cwh, cwl, HH,  HH);
    tsplit_kernel<<<dim3(DOUT / 32, HH  / 32), dim3(32, 8)>>>(wout, woh, wol, HH,  DOUT);
    cudaMemsetAsync(flagn, 0, sizeof(uint32_t));

    // layer 1: relu(x @ w0 + b0)            — 3 products
    mma_gemm<0,3><<<dim3(HH / 128,   BB / 128), NTHREADS, SMEM_FOR(3)>>>(
        mXh, mXl, mW0h, mW0l, b0,   h1h, h1l, nullptr, BB, HH,   DIN);
    // layer 2: relu(h1 @ w1 + b1)           — 3 products
    mma_gemm<0,3><<<dim3(HH / 128,   BB / 128), NTHREADS, SMEM_FOR(3)>>>(
        mH1h, mH1l, mW1h, mW1l, b1,  h2h, h2l, nullptr, BB, HH,   HH);
    // layer 3: tanh(h2 @ cw + cb + probs)   — hh only + flags
    mma_gemm<1,1><<<dim3(HH / 128,   BB / 128), NTHREADS, SMEM_FOR(1)>>>(
        mH2h, mH2l, mCWh, mCWl, cb,  xh,  xl,  nullptr, BB, HH,   HH);
    // repair flagged entries exactly
    repair_kernel<<<512, 256>>>((const __half2*)h2h, (const __half2*)h2l,
                                (const __half2*)cwh, (const __half2*)cwl,
                                cb, xh, xl);
    // layer 4: relu(h3 @ wout + bout)       — 1 product
    mma_gemm<2,1><<<dim3(DOUT / 128, BB / 128), NTHREADS, SMEM_FOR(1)>>>(
        mXh, mXl, mWOh, mWOl, bout, nullptr, nullptr, out, BB, DOUT, HH);
}

// round 14
// speedup vs baseline: 2.8072x; 1.0205x over previous
#include <cuda_runtime.h>
#include <cuda.h>
#include <cuda_fp16.h>
#include <math.h>
#include <stdint.h>

#define BB   16384
#define DIN  1024
#define HH   1024
#define DOUT 256
#define DEPTH 7

#define FLAG_CAP (1u << 22)
#define FLAG_T   64.0f
#define SAT_T    20.0f

// ---------------- device scratch (fp16 hi/lo operand arrays) ------------------
__device__ __half g_xh[(size_t)BB * HH],  g_xl[(size_t)BB * HH];    // x split; xh reused for h3
__device__ __half g_h1h[(size_t)BB * HH], g_h1l[(size_t)BB * HH];
__device__ __half g_h2h[(size_t)BB * HH], g_h2l[(size_t)BB * HH];
__device__ __half g_w0h[(size_t)HH * DIN],  g_w0l[(size_t)HH * DIN];   // [N][K]
__device__ __half g_w1h[(size_t)HH * HH],   g_w1l[(size_t)HH * HH];
__device__ __half g_cwh[(size_t)HH * HH],   g_cwl[(size_t)HH * HH];
__device__ __half g_woh[(size_t)DOUT * HH], g_wol[(size_t)DOUT * HH];
__device__ float  g_probs[HH];
__device__ uint32_t g_flags[FLAG_CAP];
__device__ uint32_t g_flagn;

// ---------------- helpers -------------------------------------------------------
__device__ __forceinline__ uint32_t s2u(const void* p) {
    uint32_t a;
    asm("{ .reg .u64 t; cvta.to.shared.u64 t, %1; cvt.u32.u64 %0, t; }" : "=r"(a) : "l"(p));
    return a;
}
__device__ __forceinline__ void mma16(float c[4],
                                      uint32_t a0, uint32_t a1, uint32_t a2, uint32_t a3,
                                      uint32_t b0, uint32_t b1) {
    asm volatile(
        "mma.sync.aligned.m16n8k16.row.col.f32.f16.f16.f32 "
        "{%0,%1,%2,%3}, {%4,%5,%6,%7}, {%8,%9}, {%0,%1,%2,%3};"
        : "+f"(c[0]), "+f"(c[1]), "+f"(c[2]), "+f"(c[3])
        : "r"(a0), "r"(a1), "r"(a2), "r"(a3), "r"(b0), "r"(b1));
}
__device__ __forceinline__ void mma16h(uint32_t c[2],
                                       uint32_t a0, uint32_t a1, uint32_t a2, uint32_t a3,
                                       uint32_t b0, uint32_t b1) {
    asm volatile(
        "mma.sync.aligned.m16n8k16.row.col.f16.f16.f16.f16 "
        "{%0,%1}, {%2,%3,%4,%5}, {%6,%7}, {%0,%1};"
        : "+r"(c[0]), "+r"(c[1])
        : "r"(a0), "r"(a1), "r"(a2), "r"(a3), "r"(b0), "r"(b1));
}
__device__ __forceinline__ void ldsm4(uint32_t& r0, uint32_t& r1, uint32_t& r2, uint32_t& r3,
                                      uint32_t addr) {
    asm volatile("ldmatrix.sync.aligned.m8n8.x4.shared.b16 {%0,%1,%2,%3}, [%4];"
                 : "=r"(r0), "=r"(r1), "=r"(r2), "=r"(r3) : "r"(addr));
}
__device__ __forceinline__ void mbar_init(uint32_t m, uint32_t cnt) {
    asm volatile("mbarrier.init.shared.b64 [%0], %1;" :: "r"(m), "r"(cnt) : "memory");
}
__device__ __forceinline__ void mbar_expect_tx(uint32_t m, uint32_t bytes) {
    asm volatile("mbarrier.arrive.expect_tx.shared.b64 _, [%0], %1;" :: "r"(m), "r"(bytes) : "memory");
}
__device__ __forceinline__ void mbar_wait(uint32_t m, uint32_t parity) {
    asm volatile(
        "{\n\t.reg .pred P;\n"
        "WL%=:\n\t"
        "mbarrier.try_wait.parity.acquire.cta.shared::cta.b64 P, [%0], %1, 0x989680;\n\t"
        "@P bra WD%=;\n\t"
        "bra WL%=;\n"
        "WD%=:\n\t}"
        :: "r"(m), "r"(parity) : "memory");
}
__device__ __forceinline__ void tma2d(uint32_t dst, const CUtensorMap* map,
                                      int x, int y, uint32_t mbar) {
    asm volatile(
        "cp.async.bulk.tensor.2d.shared::cta.global.tile.mbarrier::complete_tx::bytes "
        "[%0], [%1, {%2, %3}], [%4];"
        :: "r"(dst), "l"(map), "r"(x), "r"(y), "r"(mbar) : "memory");
}
__device__ __forceinline__ void fsplit(float v, __half& h, __half& l) {
    h = __float2half_rn(v);
    l = __float2half_rn(v - __half2float(h));
}
__device__ __forceinline__ float tanh_sat(float v) {
    if (fabsf(v) >= SAT_T) return copysignf(1.0f, v);
    return tanhf(v);
}

// ---------------- probs (tiny; also zeroes the flag counter) ----------------------
__global__ void probs_kernel(const float* __restrict__ tw) {
    __shared__ float st[2][HH];
    const int r = blockIdx.x, t = threadIdx.x;
    if (r == 0 && t == 0) g_flagn = 0;
    for (int i = t; i < HH; i += blockDim.x) st[0][i] = 0.03125f;
    __syncthreads();
    int cur = 0;
    #pragma unroll 1
    for (int d = 0; d < DEPTH; ++d)
        #pragma unroll 1
        for (int k = 0; k < 3; ++k) {
            const float ang = tw[((size_t)d * HH + r) * HH + k];
            const float c = cosf(ang), s = sinf(ang);
            const int nxt = cur ^ 1;
            for (int i = t; i < HH; i += blockDim.x)
                st[nxt][i] = c * st[cur][i]
                           - s * st[cur][(i + 1) & (HH - 1)]
                           + s * st[cur][(i - 1) & (HH - 1)];
            __syncthreads();
            cur = nxt;
        }
    if (t == 0) { const float v = st[cur][0]; g_probs[r] = v * v; }
}

// ---------------- x split: fp32 -> fp16 hi/lo -------------------------------------
__global__ void splitx_kernel(const float4* __restrict__ in,
                              __half2* __restrict__ oh, __half2* __restrict__ ol, int n4) {
    int i = blockIdx.x * blockDim.x + threadIdx.x;
    if (i >= n4) return;
    float4 v = in[i];
    __half h0, h1, h2, h3, l0, l1, l2, l3;
    fsplit(v.x, h0, l0); fsplit(v.y, h1, l1);
    fsplit(v.z, h2, l2); fsplit(v.w, h3, l3);
    oh[2 * i]     = __halves2half2(h0, h1);
    oh[2 * i + 1] = __halves2half2(h2, h3);
    ol[2 * i]     = __halves2half2(l0, l1);
    ol[2 * i + 1] = __halves2half2(l2, l3);
}

// ---------------- weight transpose + split: w[K][N] fp32 -> [N][K] fp16 h/l -------
__global__ void tsplit_kernel(const float* __restrict__ w,
                              __half* __restrict__ th, __half* __restrict__ tl,
                              int Kd, int Nd) {
    __shared__ float tile[32][33];
    const int nb = blockIdx.x * 32, kb = blockIdx.y * 32;
    const int tx = threadIdx.x, ty = threadIdx.y;   // 32 x 8
    #pragma unroll
    for (int i = 0; i < 32; i += 8)
        tile[ty + i][tx] = w[(size_t)(kb + ty + i) * Nd + nb + tx];
    __syncthreads();
    #pragma unroll
    for (int i = 0; i < 32; i += 8) {
        const float v = tile[tx][ty + i];
        __half h, l;
        fsplit(v, h, l);
        const size_t o = (size_t)(nb + ty + i) * Kd + kb + tx;
        th[o] = h;
        tl[o] = l;
    }
}

// ---------------- repair: exact fp32 recompute of flagged tanh entries ------------
__global__ void repair_kernel(const __half2* __restrict__ h2h, const __half2* __restrict__ h2l,
                              const __half2* __restrict__ cwh, const __half2* __restrict__ cwl,
                              const float* __restrict__ cb,
                              __half* __restrict__ xh) {
    const uint32_t n = min(g_flagn, FLAG_CAP);
    const int lane = threadIdx.x & 31;
    const uint32_t warp = (blockIdx.x * blockDim.x + threadIdx.x) >> 5;
    const uint32_t nw = (gridDim.x * blockDim.x) >> 5;
    for (uint32_t e = warp; e < n; e += nw) {
        const uint32_t f = g_flags[e];
        const int row = f >> 10, col = f & 1023;
        const __half2* ah = h2h + (size_t)row * 512;
        const __half2* al = h2l + (size_t)row * 512;
        const __half2* wh = cwh + (size_t)col * 512;
        const __half2* wl = cwl + (size_t)col * 512;
        float s = 0.f;
        #pragma unroll 4
        for (int k = lane; k < 512; k += 32) {
            const float2 a0 = __half22float2(ah[k]);
            const float2 a1 = __half22float2(al[k]);
            const float2 w0 = __half22float2(wh[k]);
            const float2 w1 = __half22float2(wl[k]);
            s = fmaf(a0.x + a1.x, w0.x + w1.x, s);
            s = fmaf(a0.y + a1.y, w0.y + w1.y, s);
        }
        #pragma unroll
        for (int o = 16; o; o >>= 1) s += __shfl_xor_sync(0xFFFFFFFFu, s, o);
        if (lane == 0) {
            const float v = tanh_sat(s + cb[col] + g_probs[col]);
            xh[(size_t)row * HH + col] = __float2half_rn(v);
        }
    }
}

// ---------------- split-fp16 GEMM: TMA + ldmatrix + mma.sync -----------------------
// CTA tile 128 x NT (NT=128 or 256), 512 threads, 16 warps (4m x 4n), warp 32 x NT/4.
// 3-stage TMA/mbarrier pipeline, one __syncthreads per chunk.
// PROD=3: hh(f32)+Al*Bh(f16)+Ah*Bl(f16).  PROD=1: hh only.
// EPI 0: relu->split(Ch,Cl)   1: tanh_sat(+probs)->Ch only + flag   2: relu->fp32
#define KT       64
#define NSTAGE   3
#define NTHREADS 512

static constexpr int smem_for(int P, int NT) {
    return NSTAGE * (((P == 3) ? 2 : 1) * 16384 + ((P >= 2) ? 2 : 1) * NT * 128) + 64;
}

template <int EPI, int PROD, int NT>
__global__ void __launch_bounds__(NTHREADS, 1)
mma_gemm(const __grid_constant__ CUtensorMap mAh,
         const __grid_constant__ CUtensorMap mAl,
         const __grid_constant__ CUtensorMap mBh,
         const __grid_constant__ CUtensorMap mBl,
         const float* __restrict__ bias,
         __half* __restrict__ Ch, __half* __restrict__ Cl,
         float* __restrict__ Cf,
         int M, int N, int K)
{
    constexpr bool NEED_AL = (PROD == 3);
    constexpr bool NEED_BL = (PROD >= 2);
    constexpr int  WNF     = NT / 32;                 // n-frags per warp (4 or 8)
    constexpr uint32_t A_TILE = 16384u;
    constexpr uint32_t B_TILE = (uint32_t)NT * 128u;
    constexpr uint32_t OFF_AL = A_TILE;                              // iff NEED_AL
    constexpr uint32_t OFF_BH = (NEED_AL ? 2u : 1u) * A_TILE;
    constexpr uint32_t OFF_BL = OFF_BH + B_TILE;                     // iff NEED_BL
    constexpr uint32_t STAGE_B = OFF_BH + (NEED_BL ? 2u : 1u) * B_TILE;
    constexpr uint32_t TX_BYTES = STAGE_B;

    extern __shared__ __align__(1024) char smem[];
    const uint32_t sbase = s2u(smem);
    const uint32_t barb  = sbase + NSTAGE * STAGE_B;

    const int tid  = threadIdx.x;
    const int lane = tid & 31;
    const int warp = tid >> 5;
    const int wm   = (warp & 3) * 32;
    const int wn   = (warp >> 2) * (NT / 4);
    const int g    = lane >> 2;
    const int tg   = lane & 3;

    const int bm = blockIdx.y * 128;
    const int bn = blockIdx.x * NT;

    if (tid == 0) {
        mbar_init(barb + 0, 1);
        mbar_init(barb + 8, 1);
        mbar_init(barb + 16, 1);
    }
    __syncthreads();

    auto issue = [&](int c, int s) {
        const uint32_t st = sbase + (uint32_t)s * STAGE_B;
        const int k0 = c * KT;
        mbar_expect_tx(barb + 8 * s, TX_BYTES);
        tma2d(st,          &mAh, k0, bm, barb + 8 * s);
        if (NEED_AL) tma2d(st + OFF_AL, &mAl, k0, bm, barb + 8 * s);
        tma2d(st + OFF_BH, &mBh, k0, bn, barb + 8 * s);
        if (NEED_BL) tma2d(st + OFF_BL, &mBl, k0, bn, barb + 8 * s);
    };

    // ldmatrix swizzled addressing (SW128: byte ^ ((row&7)<<4))
    const uint32_t swz   = (uint32_t)(lane & 7) << 4;
    const uint32_t aRow0 = (uint32_t)((lane & 7) + 8 * ((lane >> 3) & 1)) * 128 + (uint32_t)wm * 128;
    const uint32_t aB0   = 16u * (uint32_t)(lane >> 4);
    const uint32_t bRow  = (uint32_t)(wn + 8 * (lane >> 3) + (lane & 7)) * 128;

    float    acc[2][WNF][4];
    uint32_t accx[2][WNF][2];
    #pragma unroll
    for (int i = 0; i < 2; ++i)
        #pragma unroll
        for (int j = 0; j < WNF; ++j) {
            #pragma unroll
            for (int q = 0; q < 4; ++q) acc[i][j][q] = 0.f;
            accx[i][j][0] = 0u; accx[i][j][1] = 0u;
        }

    const int NC = K / KT;
    if (tid == 0) { issue(0, 0); issue(1, 1); }

    #pragma unroll 1
    for (int c = 0; c < NC; ++c) {
        const int s = c - (c / NSTAGE) * NSTAGE;
        __syncthreads();
        if (tid == 0 && c + 2 < NC) {
            const int ns = (c + 2) - ((c + 2) / NSTAGE) * NSTAGE;
            issue(c + 2, ns);
        }
        mbar_wait(barb + 8 * s, (uint32_t)(c / NSTAGE) & 1u);

        const uint32_t st  = sbase + (uint32_t)s * STAGE_B;
        const uint32_t tAh = st;
        const uint32_t tAl = st + OFF_AL;
        const uint32_t tBh = st + OFF_BH;
        const uint32_t tBl = st + OFF_BL;

        #pragma unroll
        for (int k16 = 0; k16 < KT / 16; ++k16) {
            const uint32_t kbase = (uint32_t)(k16 * 32);
            const uint32_t ka  = (kbase + aB0) ^ swz;
            const uint32_t kb0 = kbase ^ swz;
            const uint32_t kb1 = (kbase + 16u) ^ swz;

            uint32_t a_h[2][4], a_l[2][4];
            #pragma unroll
            for (int i = 0; i < 2; ++i) {
                const uint32_t ao = aRow0 + (uint32_t)(i * 16 * 128) + ka;
                ldsm4(a_h[i][0], a_h[i][1], a_h[i][2], a_h[i][3], tAh + ao);
                if (NEED_AL) ldsm4(a_l[i][0], a_l[i][1], a_l[i][2], a_l[i][3], tAl + ao);
            }
            uint32_t b_h[WNF][2], b_l[WNF][2];
            #pragma unroll
            for (int nb = 0; nb < WNF / 4; ++nb) {
                const uint32_t bb = bRow + (uint32_t)(nb * 32 * 128);
                ldsm4(b_h[4*nb+0][0], b_h[4*nb+1][0], b_h[4*nb+2][0], b_h[4*nb+3][0], tBh + bb + kb0);
                ldsm4(b_h[4*nb+0][1], b_h[4*nb+1][1], b_h[4*nb+2][1], b_h[4*nb+3][1], tBh + bb + kb1);
                if (NEED_BL) {
                    ldsm4(b_l[4*nb+0][0], b_l[4*nb+1][0], b_l[4*nb+2][0], b_l[4*nb+3][0], tBl + bb + kb0);
                    ldsm4(b_l[4*nb+0][1], b_l[4*nb+1][1], b_l[4*nb+2][1], b_l[4*nb+3][1], tBl + bb + kb1);
                }
            }

            #pragma unroll
            for (int i = 0; i < 2; ++i)
                #pragma unroll
                for (int j = 0; j < WNF; ++j)
                    mma16(acc[i][j], a_h[i][0], a_h[i][1], a_h[i][2], a_h[i][3], b_h[j][0], b_h[j][1]);
            if (NEED_AL) {
                #pragma unroll
                for (int i = 0; i < 2; ++i)
                    #pragma unroll
                    for (int j = 0; j < WNF; ++j)
                        mma16h(accx[i][j], a_l[i][0], a_l[i][1], a_l[i][2], a_l[i][3], b_h[j][0], b_h[j][1]);
            }
            if (NEED_BL) {
                #pragma unroll
                for (int i = 0; i < 2; ++i)
                    #pragma unroll
                    for (int j = 0; j < WNF; ++j)
                        mma16h(accx[i][j], a_h[i][0], a_h[i][1], a_h[i][2], a_h[i][3], b_l[j][0], b_l[j][1]);
            }
        }
    }

    // ---- epilogue ----
    #pragma unroll
    for (int j = 0; j < WNF; ++j) {
        const int col = bn + wn + j * 8 + 2 * tg;
        const float b0 = bias[col], b1 = bias[col + 1];
        float p0 = 0.f, p1 = 0.f;
        if (EPI == 1) { p0 = g_probs[col]; p1 = g_probs[col + 1]; }
        #pragma unroll
        for (int i = 0; i < 2; ++i) {
            const int row = bm + wm + i * 16 + g;
            const float2 x0 = __half22float2(*(__half2*)&accx[i][j][0]);
            const float2 x1 = __half22float2(*(__half2*)&accx[i][j][1]);
            float v0 = acc[i][j][0] + x0.x + b0;
            float v1 = acc[i][j][1] + x0.y + b1;
            float v2 = acc[i][j][2] + x1.x + b0;
            float v3 = acc[i][j][3] + x1.y + b1;
            if (EPI == 1) {
                v0 += p0; v1 += p1; v2 += p0; v3 += p1;
                auto push = [&](float pv, int r, int cc) {
                    if (fabsf(pv) < FLAG_T) {
                        const uint32_t idx = atomicAdd(&g_flagn, 1u);
                        if (idx < FLAG_CAP)
                            g_flags[idx] = ((uint32_t)r << 10) | (uint32_t)cc;
                    }
                };
                push(v0, row, col); push(v1, row, col + 1);
                push(v2, row + 8, col); push(v3, row + 8, col + 1);
                v0 = tanh_sat(v0); v1 = tanh_sat(v1);
                v2 = tanh_sat(v2); v3 = tanh_sat(v3);
                *reinterpret_cast<__half2*>(&Ch[(size_t)row * N + col]) =
                    __halves2half2(__float2half_rn(v0), __float2half_rn(v1));
                *reinterpret_cast<__half2*>(&Ch[(size_t)(row + 8) * N + col]) =
                    __halves2half2(__float2half_rn(v2), __float2half_rn(v3));
            } else if (EPI == 2) {
                v0 = fmaxf(v0, 0.f); v1 = fmaxf(v1, 0.f);
                v2 = fmaxf(v2, 0.f); v3 = fmaxf(v3, 0.f);
                *reinterpret_cast<float2*>(&Cf[(size_t)row * N + col])       = make_float2(v0, v1);
                *reinterpret_cast<float2*>(&Cf[(size_t)(row + 8) * N + col]) = make_float2(v2, v3);
            } else {
                v0 = fmaxf(v0, 0.f); v1 = fmaxf(v1, 0.f);
                v2 = fmaxf(v2, 0.f); v3 = fmaxf(v3, 0.f);
                __half h0, h1, h2, h3, l0, l1, l2, l3;
                fsplit(v0, h0, l0); fsplit(v1, h1, l1);
                fsplit(v2, h2, l2); fsplit(v3, h3, l3);
                *reinterpret_cast<__half2*>(&Ch[(size_t)row * N + col])       = __halves2half2(h0, h1);
                *reinterpret_cast<__half2*>(&Ch[(size_t)(row + 8) * N + col]) = __halves2half2(h2, h3);
                *reinterpret_cast<__half2*>(&Cl[(size_t)row * N + col])       = __halves2half2(l0, l1);
                *reinterpret_cast<__half2*>(&Cl[(size_t)(row + 8) * N + col]) = __halves2half2(l2, l3);
            }
        }
    }
}

// ---------------- host --------------------------------------------------------------
typedef CUresult (*tmap_fn_t)(CUtensorMap*, CUtensorMapDataType, cuuint32_t, void*,
                              const cuuint64_t*, const cuuint64_t*,
                              const cuuint32_t*, const cuuint32_t*,
                              CUtensorMapInterleave, CUtensorMapSwizzle,
                              CUtensorMapL2promotion, CUtensorMapFloatOOBfill);

static void enc2d(tmap_fn_t f, CUtensorMap* m, __half* p, uint64_t Kd, uint64_t rows,
                  uint32_t box1) {
    cuuint64_t dims[2] = {Kd, rows};
    cuuint64_t str[1]  = {Kd * 2};
    cuuint32_t box[2]  = {KT, box1};
    cuuint32_t es[2]   = {1, 1};
    f(m, CU_TENSOR_MAP_DATA_TYPE_FLOAT16, 2, (void*)p, dims, str, box, es,
      CU_TENSOR_MAP_INTERLEAVE_NONE, CU_TENSOR_MAP_SWIZZLE_128B,
      CU_TENSOR_MAP_L2_PROMOTION_L2_128B, CU_TENSOR_MAP_FLOAT_OOB_FILL_NONE);
}

extern "C" void kernel_launch(void* const* d_in, const int* in_sizes, int n_in,
                              void* d_out, int out_size) {
    const float* x    = (const float*)d_in[0];
    const float* w0   = (const float*)d_in[1];
    const float* b0   = (const float*)d_in[2];
    const float* w1   = (const float*)d_in[3];
    const float* b1   = (const float*)d_in[4];
    const float* tw   = (const float*)d_in[5];
    const float* cw   = (const float*)d_in[6];
    const float* cb   = (const float*)d_in[7];
    const float* wout = (const float*)d_in[8];
    const float* bout = (const float*)d_in[9];
    float* out = (float*)d_out;

    __half *xh, *xl, *h1h, *h1l, *h2h, *h2l;
    __half *w0h, *w0l, *w1h, *w1l, *cwh, *cwl, *woh, *wol;
    cudaGetSymbolAddress((void**)&xh,  g_xh);   cudaGetSymbolAddress((void**)&xl,  g_xl);
    cudaGetSymbolAddress((void**)&h1h, g_h1h);  cudaGetSymbolAddress((void**)&h1l, g_h1l);
    cudaGetSymbolAddress((void**)&h2h, g_h2h);  cudaGetSymbolAddress((void**)&h2l, g_h2l);
    cudaGetSymbolAddress((void**)&w0h, g_w0h);  cudaGetSymbolAddress((void**)&w0l, g_w0l);
    cudaGetSymbolAddress((void**)&w1h, g_w1h);  cudaGetSymbolAddress((void**)&w1l, g_w1l);
    cudaGetSymbolAddress((void**)&cwh, g_cwh);  cudaGetSymbolAddress((void**)&cwl, g_cwl);
    cudaGetSymbolAddress((void**)&woh, g_woh);  cudaGetSymbolAddress((void**)&wol, g_wol);

    void* fp = nullptr;
    cudaDriverEntryPointQueryResult qr;
    cudaGetDriverEntryPoint("cuTensorMapEncodeTiled", &fp, cudaEnableDefault, &qr);
    tmap_fn_t enc = (tmap_fn_t)fp;

    CUtensorMap mXh, mXl, mH1h, mH1l, mH2h, mH2l;
    CUtensorMap mW0h, mW0l, mW1h, mW1l, mCWh, mCWl, mWOh, mWOl;
    enc2d(enc, &mXh,  xh,  DIN, BB, 128);
    enc2d(enc, &mXl,  xl,  DIN, BB, 128);
    enc2d(enc, &mH1h, h1h, HH,  BB, 128);
    enc2d(enc, &mH1l, h1l, HH,  BB, 128);
    enc2d(enc, &mH2h, h2h, HH,  BB, 128);
    enc2d(enc, &mH2l, h2l, HH,  BB, 128);
    enc2d(enc, &mW0h, w0h, DIN, HH, 128);
    enc2d(enc, &mW0l, w0l, DIN, HH, 128);
    enc2d(enc, &mW1h, w1h, HH,  HH, 128);
    enc2d(enc, &mW1l, w1l, HH,  HH, 128);
    enc2d(enc, &mCWh, cwh, HH,  HH, 256);      // L3 uses NT=256
    enc2d(enc, &mCWl, cwl, HH,  HH, 256);
    enc2d(enc, &mWOh, woh, HH,  DOUT, 256);    // L4 uses NT=256
    enc2d(enc, &mWOl, wol, HH,  DOUT, 256);

    cudaFuncSetAttribute(mma_gemm<0,3,128>, cudaFuncAttributeMaxDynamicSharedMemorySize, smem_for(3,128));
    cudaFuncSetAttribute(mma_gemm<1,1,256>, cudaFuncAttributeMaxDynamicSharedMemorySize, smem_for(1,256));
    cudaFuncSetAttribute(mma_gemm<2,1,256>, cudaFuncAttributeMaxDynamicSharedMemorySize, smem_for(1,256));

    // launch order arranged so ncu (-s 5 -c 1) captures the first big GEMM
    probs_kernel<<<HH, 256>>>(tw);                                              // 0
    {
        const int n4 = BB * DIN / 4;
        splitx_kernel<<<(n4 + 255) / 256, 256>>>((const float4*)x,
                                                 (__half2*)xh, (__half2*)xl, n4); // 1
    }
    tsplit_kernel<<<dim3(HH / 32,   DIN / 32), dim3(32, 8)>>>(w0, w0h, w0l, DIN, HH); // 2
    tsplit_kernel<<<dim3(HH / 32,   HH  / 32), dim3(32, 8)>>>(w1, w1h, w1l, HH,  HH); // 3
    tsplit_kernel<<<dim3(HH / 32,   HH  / 32), dim3(32, 8)>>>(cw, cwh, cwl, HH,  HH); // 4

    // layer 1: relu(x @ w0 + b0)            — 3 products             (launch idx 5)
    mma_gemm<0,3,128><<<dim3(HH / 128,   BB / 128), NTHREADS, smem_for(3,128)>>>(
        mXh, mXl, mW0h, mW0l, b0,   h1h, h1l, nullptr, BB, HH,   DIN);

    tsplit_kernel<<<dim3(DOUT / 32, HH / 32), dim3(32, 8)>>>(wout, woh, wol, HH, DOUT);

    // layer 2: relu(h1 @ w1 + b1)           — 3 products
    mma_gemm<0,3,128><<<dim3(HH / 128,   BB / 128), NTHREADS, smem_for(3,128)>>>(
        mH1h, mH1l, mW1h, mW1l, b1,  h2h, h2l, nullptr, BB, HH,   HH);
    // layer 3: tanh(h2 @ cw + cb + probs)   — hh only + flags, wide tile
    mma_gemm<1,1,256><<<dim3(HH / 256,   BB / 128), NTHREADS, smem_for(1,256)>>>(
        mH2h, mH2l, mCWh, mCWl, cb,  xh,  nullptr, nullptr, BB, HH,   HH);
    // repair flagged entries exactly (writes xh only; L4 never reads xl)
    repair_kernel<<<512, 256>>>((const __half2*)h2h, (const __half2*)h2l,
                                (const __half2*)cwh, (const __half2*)cwl,
                                cb, xh);
    // layer 4: relu(h3 @ wout + bout)       — 1 product, wide tile
    mma_gemm<2,1,256><<<dim3(DOUT / 256, BB / 128), NTHREADS, smem_for(1,256)>>>(
        mXh, mXl, mWOh, mWOl, bout, nullptr, nullptr, out, BB, DOUT, HH);
}

// round 15
// speedup vs baseline: 2.9899x; 1.0651x over previous
#include <cuda_runtime.h>
#include <cuda.h>
#include <cuda_fp16.h>
#include <math.h>
#include <stdint.h>

#define BB   16384
#define DIN  1024
#define HH   1024
#define DOUT 256
#define DEPTH 7

#define FLAG_CAP (1u << 22)
#define FLAG_T   64.0f
#define SAT_T    20.0f

// ---------------- device scratch (fp16 hi/lo operand arrays) ------------------
__device__ __half g_xh[(size_t)BB * HH],  g_xl[(size_t)BB * HH];    // x split; xh reused for h3
__device__ __half g_h1h[(size_t)BB * HH], g_h1l[(size_t)BB * HH];
__device__ __half g_h2h[(size_t)BB * HH], g_h2l[(size_t)BB * HH];
__device__ __half g_w0h[(size_t)HH * DIN],  g_w0l[(size_t)HH * DIN];   // [N][K]
__device__ __half g_w1h[(size_t)HH * HH],   g_w1l[(size_t)HH * HH];
__device__ __half g_cwh[(size_t)HH * HH],   g_cwl[(size_t)HH * HH];
__device__ __half g_woh[(size_t)DOUT * HH], g_wol[(size_t)DOUT * HH];
__device__ float  g_probs[HH];
__device__ uint32_t g_flags[FLAG_CAP];
__device__ uint32_t g_flagn;

// ---------------- helpers -------------------------------------------------------
__device__ __forceinline__ uint32_t s2u(const void* p) {
    uint32_t a;
    asm("{ .reg .u64 t; cvta.to.shared.u64 t, %1; cvt.u32.u64 %0, t; }" : "=r"(a) : "l"(p));
    return a;
}
__device__ __forceinline__ void mma16(float c[4],
                                      uint32_t a0, uint32_t a1, uint32_t a2, uint32_t a3,
                                      uint32_t b0, uint32_t b1) {
    asm volatile(
        "mma.sync.aligned.m16n8k16.row.col.f32.f16.f16.f32 "
        "{%0,%1,%2,%3}, {%4,%5,%6,%7}, {%8,%9}, {%0,%1,%2,%3};"
        : "+f"(c[0]), "+f"(c[1]), "+f"(c[2]), "+f"(c[3])
        : "r"(a0), "r"(a1), "r"(a2), "r"(a3), "r"(b0), "r"(b1));
}
__device__ __forceinline__ void mma16h(uint32_t c[2],
                                       uint32_t a0, uint32_t a1, uint32_t a2, uint32_t a3,
                                       uint32_t b0, uint32_t b1) {
    asm volatile(
        "mma.sync.aligned.m16n8k16.row.col.f16.f16.f16.f16 "
        "{%0,%1}, {%2,%3,%4,%5}, {%6,%7}, {%0,%1};"
        : "+r"(c[0]), "+r"(c[1])
        : "r"(a0), "r"(a1), "r"(a2), "r"(a3), "r"(b0), "r"(b1));
}
__device__ __forceinline__ void ldsm4(uint32_t& r0, uint32_t& r1, uint32_t& r2, uint32_t& r3,
                                      uint32_t addr) {
    asm volatile("ldmatrix.sync.aligned.m8n8.x4.shared.b16 {%0,%1,%2,%3}, [%4];"
                 : "=r"(r0), "=r"(r1), "=r"(r2), "=r"(r3) : "r"(addr));
}
__device__ __forceinline__ void mbar_init(uint32_t m, uint32_t cnt) {
    asm volatile("mbarrier.init.shared.b64 [%0], %1;" :: "r"(m), "r"(cnt) : "memory");
}
__device__ __forceinline__ void mbar_expect_tx(uint32_t m, uint32_t bytes) {
    asm volatile("mbarrier.arrive.expect_tx.shared.b64 _, [%0], %1;" :: "r"(m), "r"(bytes) : "memory");
}
__device__ __forceinline__ void mbar_arrive(uint32_t m) {
    asm volatile("mbarrier.arrive.shared.b64 _, [%0];" :: "r"(m) : "memory");
}
__device__ __forceinline__ void mbar_wait(uint32_t m, uint32_t parity) {
    asm volatile(
        "{\n\t.reg .pred P;\n"
        "WL%=:\n\t"
        "mbarrier.try_wait.parity.acquire.cta.shared::cta.b64 P, [%0], %1, 0x989680;\n\t"
        "@P bra WD%=;\n\t"
        "bra WL%=;\n"
        "WD%=:\n\t}"
        :: "r"(m), "r"(parity) : "memory");
}
__device__ __forceinline__ void tma2d(uint32_t dst, const CUtensorMap* map,
                                      int x, int y, uint32_t mbar) {
    asm volatile(
        "cp.async.bulk.tensor.2d.shared::cta.global.tile.mbarrier::complete_tx::bytes "
        "[%0], [%1, {%2, %3}], [%4];"
        :: "r"(dst), "l"(map), "r"(x), "r"(y), "r"(mbar) : "memory");
}
__device__ __forceinline__ void fsplit(float v, __half& h, __half& l) {
    h = __float2half_rn(v);
    l = __float2half_rn(v - __half2float(h));
}
__device__ __forceinline__ float tanh_sat(float v) {
    if (fabsf(v) >= SAT_T) return copysignf(1.0f, v);
    return tanhf(v);
}

// ---------------- probs (tiny; also zeroes the flag counter) ----------------------
__global__ void probs_kernel(const float* __restrict__ tw) {
    __shared__ float st[2][HH];
    const int r = blockIdx.x, t = threadIdx.x;
    if (r == 0 && t == 0) g_flagn = 0;
    for (int i = t; i < HH; i += blockDim.x) st[0][i] = 0.03125f;
    __syncthreads();
    int cur = 0;
    #pragma unroll 1
    for (int d = 0; d < DEPTH; ++d)
        #pragma unroll 1
        for (int k = 0; k < 3; ++k) {
            const float ang = tw[((size_t)d * HH + r) * HH + k];
            const float c = cosf(ang), s = sinf(ang);
            const int nxt = cur ^ 1;
            for (int i = t; i < HH; i += blockDim.x)
                st[nxt][i] = c * st[cur][i]
                           - s * st[cur][(i + 1) & (HH - 1)]
                           + s * st[cur][(i - 1) & (HH - 1)];
            __syncthreads();
            cur = nxt;
        }
    if (t == 0) { const float v = st[cur][0]; g_probs[r] = v * v; }
}

// ---------------- x split: fp32 -> fp16 hi/lo -------------------------------------
__global__ void splitx_kernel(const float4* __restrict__ in,
                              __half2* __restrict__ oh, __half2* __restrict__ ol, int n4) {
    int i = blockIdx.x * blockDim.x + threadIdx.x;
    if (i >= n4) return;
    float4 v = in[i];
    __half h0, h1, h2, h3, l0, l1, l2, l3;
    fsplit(v.x, h0, l0); fsplit(v.y, h1, l1);
    fsplit(v.z, h2, l2); fsplit(v.w, h3, l3);
    oh[2 * i]     = __halves2half2(h0, h1);
    oh[2 * i + 1] = __halves2half2(h2, h3);
    ol[2 * i]     = __halves2half2(l0, l1);
    ol[2 * i + 1] = __halves2half2(l2, l3);
}

// ---------------- weight transpose + split: w[K][N] fp32 -> [N][K] fp16 h/l -------
__global__ void tsplit_kernel(const float* __restrict__ w,
                              __half* __restrict__ th, __half* __restrict__ tl,
                              int Kd, int Nd) {
    __shared__ float tile[32][33];
    const int nb = blockIdx.x * 32, kb = blockIdx.y * 32;
    const int tx = threadIdx.x, ty = threadIdx.y;   // 32 x 8
    #pragma unroll
    for (int i = 0; i < 32; i += 8)
        tile[ty + i][tx] = w[(size_t)(kb + ty + i) * Nd + nb + tx];
    __syncthreads();
    #pragma unroll
    for (int i = 0; i < 32; i += 8) {
        const float v = tile[tx][ty + i];
        __half h, l;
        fsplit(v, h, l);
        const size_t o = (size_t)(nb + ty + i) * Kd + kb + tx;
        th[o] = h;
        tl[o] = l;
    }
}

// ---------------- repair: exact fp32 recompute of flagged tanh entries ------------
__global__ void repair_kernel(const __half2* __restrict__ h2h, const __half2* __restrict__ h2l,
                              const __half2* __restrict__ cwh, const __half2* __restrict__ cwl,
                              const float* __restrict__ cb,
                              __half* __restrict__ xh) {
    const uint32_t n = min(g_flagn, FLAG_CAP);
    const int lane = threadIdx.x & 31;
    const uint32_t warp = (blockIdx.x * blockDim.x + threadIdx.x) >> 5;
    const uint32_t nw = (gridDim.x * blockDim.x) >> 5;
    for (uint32_t e = warp; e < n; e += nw) {
        const uint32_t f = g_flags[e];
        const int row = f >> 10, col = f & 1023;
        const __half2* ah = h2h + (size_t)row * 512;
        const __half2* al = h2l + (size_t)row * 512;
        const __half2* wh = cwh + (size_t)col * 512;
        const __half2* wl = cwl + (size_t)col * 512;
        float s = 0.f;
        #pragma unroll 4
        for (int k = lane; k < 512; k += 32) {
            const float2 a0 = __half22float2(ah[k]);
            const float2 a1 = __half22float2(al[k]);
            const float2 w0 = __half22float2(wh[k]);
            const float2 w1 = __half22float2(wl[k]);
            s = fmaf(a0.x + a1.x, w0.x + w1.x, s);
            s = fmaf(a0.y + a1.y, w0.y + w1.y, s);
        }
        #pragma unroll
        for (int o = 16; o; o >>= 1) s += __shfl_xor_sync(0xFFFFFFFFu, s, o);
        if (lane == 0) {
            const float v = tanh_sat(s + cb[col] + g_probs[col]);
            xh[(size_t)row * HH + col] = __float2half_rn(v);
        }
    }
}

// ---------------- split-fp16 GEMM: TMA + ldmatrix + mma.sync -----------------------
// Barrier-free mainloop: per-stage full/empty mbarriers replace __syncthreads.
// Each warp arrives on empty[s] after consuming; only the producer (tid 0) waits
// on empty before re-issuing TMA into that stage. Warps free-run with 3-stage
// elasticity (lookahead +2; +3 would deadlock on the stage being consumed).
// CTA tile 128 x NT, 512 threads, 16 warps (4m x 4n), warp 32 x NT/4.
// PROD=3: hh(f32)+Al*Bh(f16)+Ah*Bl(f16).  PROD=1: hh only.
// EPI 0: relu->split(Ch,Cl)   1: tanh_sat(+probs)->Ch + flag   2: relu->fp32
#define KT       64
#define NSTAGE   3
#define NTHREADS 512

static constexpr int smem_for(int P, int NT) {
    return NSTAGE * (((P == 3) ? 2 : 1) * 16384 + ((P >= 2) ? 2 : 1) * NT * 128) + 128;
}

template <int EPI, int PROD, int NT>
__global__ void __launch_bounds__(NTHREADS, 1)
mma_gemm(const __grid_constant__ CUtensorMap mAh,
         const __grid_constant__ CUtensorMap mAl,
         const __grid_constant__ CUtensorMap mBh,
         const __grid_constant__ CUtensorMap mBl,
         const float* __restrict__ bias,
         __half* __restrict__ Ch, __half* __restrict__ Cl,
         float* __restrict__ Cf,
         int M, int N, int K)
{
    constexpr bool NEED_AL = (PROD == 3);
    constexpr bool NEED_BL = (PROD >= 2);
    constexpr int  WNF     = NT / 32;
    constexpr uint32_t A_TILE = 16384u;
    constexpr uint32_t B_TILE = (uint32_t)NT * 128u;
    constexpr uint32_t OFF_AL = A_TILE;
    constexpr uint32_t OFF_BH = (NEED_AL ? 2u : 1u) * A_TILE;
    constexpr uint32_t OFF_BL = OFF_BH + B_TILE;
    constexpr uint32_t STAGE_B = OFF_BH + (NEED_BL ? 2u : 1u) * B_TILE;
    constexpr uint32_t TX_BYTES = STAGE_B;

    extern __shared__ __align__(1024) char smem[];
    const uint32_t sbase = s2u(smem);
    const uint32_t fullb  = sbase + NSTAGE * STAGE_B;        // 3 x 8B
    const uint32_t emptyb = fullb + 24;                      // 3 x 8B

    const int tid  = threadIdx.x;
    const int lane = tid & 31;
    const int warp = tid >> 5;
    const int wm   = (warp & 3) * 32;
    const int wn   = (warp >> 2) * (NT / 4);
    const int g    = lane >> 2;
    const int tg   = lane & 3;

    const int bm = blockIdx.y * 128;
    const int bn = blockIdx.x * NT;

    if (tid == 0) {
        mbar_init(fullb + 0, 1);  mbar_init(fullb + 8, 1);  mbar_init(fullb + 16, 1);
        mbar_init(emptyb + 0, 16); mbar_init(emptyb + 8, 16); mbar_init(emptyb + 16, 16);
    }
    __syncthreads();

    auto issue = [&](int q, int s) {
        const uint32_t st = sbase + (uint32_t)s * STAGE_B;
        const int k0 = q * KT;
        mbar_expect_tx(fullb + 8 * s, TX_BYTES);
        tma2d(st,          &mAh, k0, bm, fullb + 8 * s);
        if (NEED_AL) tma2d(st + OFF_AL, &mAl, k0, bm, fullb + 8 * s);
        tma2d(st + OFF_BH, &mBh, k0, bn, fullb + 8 * s);
        if (NEED_BL) tma2d(st + OFF_BL, &mBl, k0, bn, fullb + 8 * s);
    };

    // ldmatrix swizzled addressing (SW128: byte ^ ((row&7)<<4))
    const uint32_t swz   = (uint32_t)(lane & 7) << 4;
    const uint32_t aRow0 = (uint32_t)((lane & 7) + 8 * ((lane >> 3) & 1)) * 128 + (uint32_t)wm * 128;
    const uint32_t aB0   = 16u * (uint32_t)(lane >> 4);
    const uint32_t bRow  = (uint32_t)(wn + 8 * (lane >> 3) + (lane & 7)) * 128;

    float    acc[2][WNF][4];
    uint32_t accx[2][WNF][2];
    #pragma unroll
    for (int i = 0; i < 2; ++i)
        #pragma unroll
        for (int j = 0; j < WNF; ++j) {
            #pragma unroll
            for (int q = 0; q < 4; ++q) acc[i][j][q] = 0.f;
            accx[i][j][0] = 0u; accx[i][j][1] = 0u;
        }

    const int NC = K / KT;
    if (tid == 0) { issue(0, 0); issue(1, 1); }

    #pragma unroll 1
    for (int c = 0; c < NC; ++c) {
        const int s = c - (c / NSTAGE) * NSTAGE;           // c % 3
        if (tid == 0 && c + 2 < NC) {
            const int q  = c + 2;
            const int ns = q - (q / NSTAGE) * NSTAGE;      // q % 3
            if (q >= NSTAGE)
                mbar_wait(emptyb + 8 * ns, (uint32_t)(q / NSTAGE - 1) & 1u);
            issue(q, ns);
        }
        mbar_wait(fullb + 8 * s, (uint32_t)(c / NSTAGE) & 1u);

        const uint32_t st  = sbase + (uint32_t)s * STAGE_B;
        const uint32_t tAh = st;
        const uint32_t tAl = st + OFF_AL;
        const uint32_t tBh = st + OFF_BH;
        const uint32_t tBl = st + OFF_BL;

        #pragma unroll
        for (int k16 = 0; k16 < KT / 16; ++k16) {
            const uint32_t kbase = (uint32_t)(k16 * 32);
            const uint32_t ka  = (kbase + aB0) ^ swz;
            const uint32_t kb0 = kbase ^ swz;
            const uint32_t kb1 = (kbase + 16u) ^ swz;

            uint32_t a_h[2][4], a_l[2][4];
            #pragma unroll
            for (int i = 0; i < 2; ++i) {
                const uint32_t ao = aRow0 + (uint32_t)(i * 16 * 128) + ka;
                ldsm4(a_h[i][0], a_h[i][1], a_h[i][2], a_h[i][3], tAh + ao);
                if (NEED_AL) ldsm4(a_l[i][0], a_l[i][1], a_l[i][2], a_l[i][3], tAl + ao);
            }
            uint32_t b_h[WNF][2], b_l[WNF][2];
            #pragma unroll
            for (int nb = 0; nb < WNF / 4; ++nb) {
                const uint32_t bb = bRow + (uint32_t)(nb * 32 * 128);
                ldsm4(b_h[4*nb+0][0], b_h[4*nb+1][0], b_h[4*nb+2][0], b_h[4*nb+3][0], tBh + bb + kb0);
                ldsm4(b_h[4*nb+0][1], b_h[4*nb+1][1], b_h[4*nb+2][1], b_h[4*nb+3][1], tBh + bb + kb1);
                if (NEED_BL) {
                    ldsm4(b_l[4*nb+0][0], b_l[4*nb+1][0], b_l[4*nb+2][0], b_l[4*nb+3][0], tBl + bb + kb0);
                    ldsm4(b_l[4*nb+0][1], b_l[4*nb+1][1], b_l[4*nb+2][1], b_l[4*nb+3][1], tBl + bb + kb1);
                }
            }

            #pragma unroll
            for (int i = 0; i < 2; ++i)
                #pragma unroll
                for (int j = 0; j < WNF; ++j)
                    mma16(acc[i][j], a_h[i][0], a_h[i][1], a_h[i][2], a_h[i][3], b_h[j][0], b_h[j][1]);
            if (NEED_AL) {
                #pragma unroll
                for (int i = 0; i < 2; ++i)
                    #pragma unroll
                    for (int j = 0; j < WNF; ++j)
                        mma16h(accx[i][j], a_l[i][0], a_l[i][1], a_l[i][2], a_l[i][3], b_h[j][0], b_h[j][1]);
            }
            if (NEED_BL) {
                #pragma unroll
                for (int i = 0; i < 2; ++i)
                    #pragma unroll
                    for (int j = 0; j < WNF; ++j)
                        mma16h(accx[i][j], a_h[i][0], a_h[i][1], a_h[i][2], a_h[i][3], b_l[j][0], b_l[j][1]);
            }
        }
        if (lane == 0) mbar_arrive(emptyb + 8 * s);
    }

    // ---- epilogue ----
    #pragma unroll
    for (int j = 0; j < WNF; ++j) {
        const int col = bn + wn + j * 8 + 2 * tg;
        const float b0 = bias[col], b1 = bias[col + 1];
        float p0 = 0.f, p1 = 0.f;
        if (EPI == 1) { p0 = g_probs[col]; p1 = g_probs[col + 1]; }
        #pragma unroll
        for (int i = 0; i < 2; ++i) {
            const int row = bm + wm + i * 16 + g;
            const float2 x0 = __half22float2(*(__half2*)&accx[i][j][0]);
            const float2 x1 = __half22float2(*(__half2*)&accx[i][j][1]);
            float v0 = acc[i][j][0] + x0.x + b0;
            float v1 = acc[i][j][1] + x0.y + b1;
            float v2 = acc[i][j][2] + x1.x + b0;
            float v3 = acc[i][j][3] + x1.y + b1;
            if (EPI == 1) {
                v0 += p0; v1 += p1; v2 += p0; v3 += p1;
                auto push = [&](float pv, int r, int cc) {
                    if (fabsf(pv) < FLAG_T) {
                        const uint32_t idx = atomicAdd(&g_flagn, 1u);
                        if (idx < FLAG_CAP)
                            g_flags[idx] = ((uint32_t)r << 10) | (uint32_t)cc;
                    }
                };
                push(v0, row, col); push(v1, row, col + 1);
                push(v2, row + 8, col); push(v3, row + 8, col + 1);
                v0 = tanh_sat(v0); v1 = tanh_sat(v1);
                v2 = tanh_sat(v2); v3 = tanh_sat(v3);
                *reinterpret_cast<__half2*>(&Ch[(size_t)row * N + col]) =
                    __halves2half2(__float2half_rn(v0), __float2half_rn(v1));
                *reinterpret_cast<__half2*>(&Ch[(size_t)(row + 8) * N + col]) =
                    __halves2half2(__float2half_rn(v2), __float2half_rn(v3));
            } else if (EPI == 2) {
                v0 = fmaxf(v0, 0.f); v1 = fmaxf(v1, 0.f);
                v2 = fmaxf(v2, 0.f); v3 = fmaxf(v3, 0.f);
                *reinterpret_cast<float2*>(&Cf[(size_t)row * N + col])       = make_float2(v0, v1);
                *reinterpret_cast<float2*>(&Cf[(size_t)(row + 8) * N + col]) = make_float2(v2, v3);
            } else {
                v0 = fmaxf(v0, 0.f); v1 = fmaxf(v1, 0.f);
                v2 = fmaxf(v2, 0.f); v3 = fmaxf(v3, 0.f);
                __half h0, h1, h2, h3, l0, l1, l2, l3;
                fsplit(v0, h0, l0); fsplit(v1, h1, l1);
                fsplit(v2, h2, l2); fsplit(v3, h3, l3);
                *reinterpret_cast<__half2*>(&Ch[(size_t)row * N + col])       = __halves2half2(h0, h1);
                *reinterpret_cast<__half2*>(&Ch[(size_t)(row + 8) * N + col]) = __halves2half2(h2, h3);
                *reinterpret_cast<__half2*>(&Cl[(size_t)row * N + col])       = __halves2half2(l0, l1);
                *reinterpret_cast<__half2*>(&Cl[(size_t)(row + 8) * N + col]) = __halves2half2(l2, l3);
            }
        }
    }
}

// ---------------- host --------------------------------------------------------------
typedef CUresult (*tmap_fn_t)(CUtensorMap*, CUtensorMapDataType, cuuint32_t, void*,
                              const cuuint64_t*, const cuuint64_t*,
                              const cuuint32_t*, const cuuint32_t*,
                              CUtensorMapInterleave, CUtensorMapSwizzle,
                              CUtensorMapL2promotion, CUtensorMapFloatOOBfill);

static void enc2d(tmap_fn_t f, CUtensorMap* m, __half* p, uint64_t Kd, uint64_t rows,
                  uint32_t box1) {
    cuuint64_t dims[2] = {Kd, rows};
    cuuint64_t str[1]  = {Kd * 2};
    cuuint32_t box[2]  = {KT, box1};
    cuuint32_t es[2]   = {1, 1};
    f(m, CU_TENSOR_MAP_DATA_TYPE_FLOAT16, 2, (void*)p, dims, str, box, es,
      CU_TENSOR_MAP_INTERLEAVE_NONE, CU_TENSOR_MAP_SWIZZLE_128B,
      CU_TENSOR_MAP_L2_PROMOTION_L2_128B, CU_TENSOR_MAP_FLOAT_OOB_FILL_NONE);
}

extern "C" void kernel_launch(void* const* d_in, const int* in_sizes, int n_in,
                              void* d_out, int out_size) {
    const float* x    = (const float*)d_in[0];
    const float* w0   = (const float*)d_in[1];
    const float* b0   = (const float*)d_in[2];
    const float* w1   = (const float*)d_in[3];
    const float* b1   = (const float*)d_in[4];
    const float* tw   = (const float*)d_in[5];
    const float* cw   = (const float*)d_in[6];
    const float* cb   = (const float*)d_in[7];
    const float* wout = (const float*)d_in[8];
    const float* bout = (const float*)d_in[9];
    float* out = (float*)d_out;

    __half *xh, *xl, *h1h, *h1l, *h2h, *h2l;
    __half *w0h, *w0l, *w1h, *w1l, *cwh, *cwl, *woh, *wol;
    cudaGetSymbolAddress((void**)&xh,  g_xh);   cudaGetSymbolAddress((void**)&xl,  g_xl);
    cudaGetSymbolAddress((void**)&h1h, g_h1h);  cudaGetSymbolAddress((void**)&h1l, g_h1l);
    cudaGetSymbolAddress((void**)&h2h, g_h2h);  cudaGetSymbolAddress((void**)&h2l, g_h2l);
    cudaGetSymbolAddress((void**)&w0h, g_w0h);  cudaGetSymbolAddress((void**)&w0l, g_w0l);
    cudaGetSymbolAddress((void**)&w1h, g_w1h);  cudaGetSymbolAddress((void**)&w1l, g_w1l);
    cudaGetSymbolAddress((void**)&cwh, g_cwh);  cudaGetSymbolAddress((void**)&cwl, g_cwl);
    cudaGetSymbolAddress((void**)&woh, g_woh);  cudaGetSymbolAddress((void**)&wol, g_wol);

    void* fp = nullptr;
    cudaDriverEntryPointQueryResult qr;
    cudaGetDriverEntryPoint("cuTensorMapEncodeTiled", &fp, cudaEnableDefault, &qr);
    tmap_fn_t enc = (tmap_fn_t)fp;

    CUtensorMap mXh, mXl, mH1h, mH1l, mH2h, mH2l;
    CUtensorMap mW0h, mW0l, mW1h, mW1l, mCWh, mCWl, mWOh, mWOl;
    enc2d(enc, &mXh,  xh,  DIN, BB, 128);
    enc2d(enc, &mXl,  xl,  DIN, BB, 128);
    enc2d(enc, &mH1h, h1h, HH,  BB, 128);
    enc2d(enc, &mH1l, h1l, HH,  BB, 128);
    enc2d(enc, &mH2h, h2h, HH,  BB, 128);
    enc2d(enc, &mH2l, h2l, HH,  BB, 128);
    enc2d(enc, &mW0h, w0h, DIN, HH, 128);
    enc2d(enc, &mW0l, w0l, DIN, HH, 128);
    enc2d(enc, &mW1h, w1h, HH,  HH, 128);
    enc2d(enc, &mW1l, w1l, HH,  HH, 128);
    enc2d(enc, &mCWh, cwh, HH,  HH, 256);
    enc2d(enc, &mCWl, cwl, HH,  HH, 256);
    enc2d(enc, &mWOh, woh, HH,  DOUT, 256);
    enc2d(enc, &mWOl, wol, HH,  DOUT, 256);

    cudaFuncSetAttribute(mma_gemm<0,3,128>, cudaFuncAttributeMaxDynamicSharedMemorySize, smem_for(3,128));
    cudaFuncSetAttribute(mma_gemm<1,1,256>, cudaFuncAttributeMaxDynamicSharedMemorySize, smem_for(1,256));
    cudaFuncSetAttribute(mma_gemm<2,1,256>, cudaFuncAttributeMaxDynamicSharedMemorySize, smem_for(1,256));

    probs_kernel<<<HH, 256>>>(tw);
    {
        const int n4 = BB * DIN / 4;
        splitx_kernel<<<(n4 + 255) / 256, 256>>>((const float4*)x,
                                                 (__half2*)xh, (__half2*)xl, n4);
    }
    tsplit_kernel<<<dim3(HH / 32,   DIN / 32), dim3(32, 8)>>>(w0, w0h, w0l, DIN, HH);
    tsplit_kernel<<<dim3(HH / 32,   HH  / 32), dim3(32, 8)>>>(w1, w1h, w1l, HH,  HH);
    tsplit_kernel<<<dim3(HH / 32,   HH  / 32), dim3(32, 8)>>>(cw, cwh, cwl, HH,  HH);

    // layer 1: relu(x @ w0 + b0)            — 3 products
    mma_gemm<0,3,128><<<dim3(HH / 128,   BB / 128), NTHREADS, smem_for(3,128)>>>(
        mXh, mXl, mW0h, mW0l, b0,   h1h, h1l, nullptr, BB, HH,   DIN);

    tsplit_kernel<<<dim3(DOUT / 32, HH / 32), dim3(32, 8)>>>(wout, woh, wol, HH, DOUT);

    // layer 2: relu(h1 @ w1 + b1)           — 3 products
    mma_gemm<0,3,128><<<dim3(HH / 128,   BB / 128), NTHREADS, smem_for(3,128)>>>(
        mH1h, mH1l, mW1h, mW1l, b1,  h2h, h2l, nullptr, BB, HH,   HH);
    // layer 3: tanh(h2 @ cw + cb + probs)   — hh only + flags, wide tile
    mma_gemm<1,1,256><<<dim3(HH / 256,   BB / 128), NTHREADS, smem_for(1,256)>>>(
        mH2h, mH2l, mCWh, mCWl, cb,  xh,  nullptr, nullptr, BB, HH,   HH);
    // repair flagged entries exactly
    repair_kernel<<<512, 256>>>((const __half2*)h2h, (const __half2*)h2l,
                                (const __half2*)cwh, (const __half2*)cwl,
                                cb, xh);
    // layer 4: relu(h3 @ wout + bout)       — 1 product, wide tile
    mma_gemm<2,1,256><<<dim3(DOUT / 256, BB / 128), NTHREADS, smem_for(1,256)>>>(
        mXh, mXl, mWOh, mWOl, bout, nullptr, nullptr, out, BB, DOUT, HH);
}

// round 17
// speedup vs baseline: 3.0807x; 1.0303x over previous
#include <cuda_runtime.h>
#include <cuda.h>
#include <cuda_fp16.h>
#include <math.h>
#include <stdint.h>

#define BB   16384
#define DIN  1024
#define HH   1024
#define DOUT 256
#define DEPTH 7

#define FLAG_CAP (1u << 22)
#define FLAG_T   48.0f
#define SAT_T    20.0f

// ---------------- device scratch (fp16 hi/lo operand arrays) ------------------
__device__ __half g_xh[(size_t)BB * HH],  g_xl[(size_t)BB * HH];    // x split; xh reused for h3
__device__ __half g_h1h[(size_t)BB * HH], g_h1l[(size_t)BB * HH];
__device__ __half g_h2h[(size_t)BB * HH], g_h2l[(size_t)BB * HH];
__device__ __half g_w0h[(size_t)HH * DIN],  g_w0l[(size_t)HH * DIN];   // [N][K]
__device__ __half g_w1h[(size_t)HH * HH],   g_w1l[(size_t)HH * HH];
__device__ __half g_cwh[(size_t)HH * HH],   g_cwl[(size_t)HH * HH];
__device__ __half g_woh[(size_t)DOUT * HH], g_wol[(size_t)DOUT * HH];
__device__ float  g_probs[HH];
__device__ uint32_t g_flags[FLAG_CAP];
__device__ uint32_t g_flagn;

// ---------------- helpers -------------------------------------------------------
__device__ __forceinline__ uint32_t s2u(const void* p) {
    uint32_t a;
    asm("{ .reg .u64 t; cvta.to.shared.u64 t, %1; cvt.u32.u64 %0, t; }" : "=r"(a) : "l"(p));
    return a;
}
__device__ __forceinline__ void mma16(float c[4],
                                      uint32_t a0, uint32_t a1, uint32_t a2, uint32_t a3,
                                      uint32_t b0, uint32_t b1) {
    asm volatile(
        "mma.sync.aligned.m16n8k16.row.col.f32.f16.f16.f32 "
        "{%0,%1,%2,%3}, {%4,%5,%6,%7}, {%8,%9}, {%0,%1,%2,%3};"
        : "+f"(c[0]), "+f"(c[1]), "+f"(c[2]), "+f"(c[3])
        : "r"(a0), "r"(a1), "r"(a2), "r"(a3), "r"(b0), "r"(b1));
}
__device__ __forceinline__ void mma16h(uint32_t c[2],
                                       uint32_t a0, uint32_t a1, uint32_t a2, uint32_t a3,
                                       uint32_t b0, uint32_t b1) {
    asm volatile(
        "mma.sync.aligned.m16n8k16.row.col.f16.f16.f16.f16 "
        "{%0,%1}, {%2,%3,%4,%5}, {%6,%7}, {%0,%1};"
        : "+r"(c[0]), "+r"(c[1])
        : "r"(a0), "r"(a1), "r"(a2), "r"(a3), "r"(b0), "r"(b1));
}
__device__ __forceinline__ void ldsm4(uint32_t& r0, uint32_t& r1, uint32_t& r2, uint32_t& r3,
                                      uint32_t addr) {
    asm volatile("ldmatrix.sync.aligned.m8n8.x4.shared.b16 {%0,%1,%2,%3}, [%4];"
                 : "=r"(r0), "=r"(r1), "=r"(r2), "=r"(r3) : "r"(addr));
}
__device__ __forceinline__ void mbar_init(uint32_t m, uint32_t cnt) {
    asm volatile("mbarrier.init.shared.b64 [%0], %1;" :: "r"(m), "r"(cnt) : "memory");
}
__device__ __forceinline__ void mbar_expect_tx(uint32_t m, uint32_t bytes) {
    asm volatile("mbarrier.arrive.expect_tx.shared.b64 _, [%0], %1;" :: "r"(m), "r"(bytes) : "memory");
}
__device__ __forceinline__ void mbar_arrive(uint32_t m) {
    asm volatile("mbarrier.arrive.shared.b64 _, [%0];" :: "r"(m) : "memory");
}
__device__ __forceinline__ void mbar_wait(uint32_t m, uint32_t parity) {
    asm volatile(
        "{\n\t.reg .pred P;\n"
        "WL%=:\n\t"
        "mbarrier.try_wait.parity.acquire.cta.shared::cta.b64 P, [%0], %1, 0x989680;\n\t"
        "@P bra WD%=;\n\t"
        "bra WL%=;\n"
        "WD%=:\n\t}"
        :: "r"(m), "r"(parity) : "memory");
}
__device__ __forceinline__ void tma2d(uint32_t dst, const CUtensorMap* map,
                                      int x, int y, uint32_t mbar) {
    asm volatile(
        "cp.async.bulk.tensor.2d.shared::cta.global.tile.mbarrier::complete_tx::bytes "
        "[%0], [%1, {%2, %3}], [%4];"
        :: "r"(dst), "l"(map), "r"(x), "r"(y), "r"(mbar) : "memory");
}
__device__ __forceinline__ void fsplit(float v, __half& h, __half& l) {
    h = __float2half_rn(v);
    l = __float2half_rn(v - __half2float(h));
}
__device__ __forceinline__ float tanh_sat(float v) {
    if (fabsf(v) >= SAT_T) return copysignf(1.0f, v);
    return tanhf(v);
}

// ---------------- probs (tiny; also zeroes the flag counter) ----------------------
__global__ void probs_kernel(const float* __restrict__ tw) {
    __shared__ float st[2][HH];
    const int r = blockIdx.x, t = threadIdx.x;
    if (r == 0 && t == 0) g_flagn = 0;
    for (int i = t; i < HH; i += blockDim.x) st[0][i] = 0.03125f;
    __syncthreads();
    int cur = 0;
    #pragma unroll 1
    for (int d = 0; d < DEPTH; ++d)
        #pragma unroll 1
        for (int k = 0; k < 3; ++k) {
            const float ang = tw[((size_t)d * HH + r) * HH + k];
            const float c = cosf(ang), s = sinf(ang);
            const int nxt = cur ^ 1;
            for (int i = t; i < HH; i += blockDim.x)
                st[nxt][i] = c * st[cur][i]
                           - s * st[cur][(i + 1) & (HH - 1)]
                           + s * st[cur][(i - 1) & (HH - 1)];
            __syncthreads();
            cur = nxt;
        }
    if (t == 0) { const float v = st[cur][0]; g_probs[r] = v * v; }
}

// ---------------- x split: fp32 -> fp16 hi/lo (8 floats/thread, 16B stores) -------
__global__ void splitx_kernel(const float4* __restrict__ in,
                              uint4* __restrict__ oh, uint4* __restrict__ ol, int n8) {
    int i = blockIdx.x * blockDim.x + threadIdx.x;
    if (i >= n8) return;
    const float4 a = in[2 * i];
    const float4 b = in[2 * i + 1];
    __half h[8], l[8];
    fsplit(a.x, h[0], l[0]); fsplit(a.y, h[1], l[1]);
    fsplit(a.z, h[2], l[2]); fsplit(a.w, h[3], l[3]);
    fsplit(b.x, h[4], l[4]); fsplit(b.y, h[5], l[5]);
    fsplit(b.z, h[6], l[6]); fsplit(b.w, h[7], l[7]);
    uint4 vh, vl;
    { __half2 t2 = __halves2half2(h[0], h[1]); vh.x = *reinterpret_cast<uint32_t*>(&t2); }
    { __half2 t2 = __halves2half2(h[2], h[3]); vh.y = *reinterpret_cast<uint32_t*>(&t2); }
    { __half2 t2 = __halves2half2(h[4], h[5]); vh.z = *reinterpret_cast<uint32_t*>(&t2); }
    { __half2 t2 = __halves2half2(h[6], h[7]); vh.w = *reinterpret_cast<uint32_t*>(&t2); }
    { __half2 t2 = __halves2half2(l[0], l[1]); vl.x = *reinterpret_cast<uint32_t*>(&t2); }
    { __half2 t2 = __halves2half2(l[2], l[3]); vl.y = *reinterpret_cast<uint32_t*>(&t2); }
    { __half2 t2 = __halves2half2(l[4], l[5]); vl.z = *reinterpret_cast<uint32_t*>(&t2); }
    { __half2 t2 = __halves2half2(l[6], l[7]); vl.w = *reinterpret_cast<uint32_t*>(&t2); }
    oh[i] = vh;
    ol[i] = vl;
}

// ---------------- weight transpose + split: w[K][N] fp32 -> [N][K] fp16 h/l -------
__global__ void tsplit_kernel(const float* __restrict__ w,
                              __half* __restrict__ th, __half* __restrict__ tl,
                              int Kd, int Nd) {
    __shared__ float tile[32][33];
    const int nb = blockIdx.x * 32, kb = blockIdx.y * 32;
    const int tx = threadIdx.x, ty = threadIdx.y;   // 32 x 8
    #pragma unroll
    for (int i = 0; i < 32; i += 8)
        tile[ty + i][tx] = w[(size_t)(kb + ty + i) * Nd + nb + tx];
    __syncthreads();
    #pragma unroll
    for (int i = 0; i < 32; i += 8) {
        const float v = tile[tx][ty + i];
        __half h, l;
        fsplit(v, h, l);
        const size_t o = (size_t)(nb + ty + i) * Kd + kb + tx;
        th[o] = h;
        tl[o] = l;
    }
}

// ---------------- repair: exact fp32 recompute of flagged tanh entries ------------
__global__ void repair_kernel(const __half2* __restrict__ h2h, const __half2* __restrict__ h2l,
                              const __half2* __restrict__ cwh, const __half2* __restrict__ cwl,
                              const float* __restrict__ cb,
                              __half* __restrict__ xh) {
    const uint32_t n = min(g_flagn, FLAG_CAP);
    const int lane = threadIdx.x & 31;
    const uint32_t warp = (blockIdx.x * blockDim.x + threadIdx.x) >> 5;
    const uint32_t nw = (gridDim.x * blockDim.x) >> 5;
    for (uint32_t e = warp; e < n; e += nw) {
        const uint32_t f = g_flags[e];
        const int row = f >> 10, col = f & 1023;
        const __half2* ah = h2h + (size_t)row * 512;
        const __half2* al = h2l + (size_t)row * 512;
        const __half2* wh = cwh + (size_t)col * 512;
        const __half2* wl = cwl + (size_t)col * 512;
        float s = 0.f;
        #pragma unroll 4
        for (int k = lane; k < 512; k += 32) {
            const float2 a0 = __half22float2(ah[k]);
            const float2 a1 = __half22float2(al[k]);
            const float2 w0 = __half22float2(wh[k]);
            const float2 w1 = __half22float2(wl[k]);
            s = fmaf(a0.x + a1.x, w0.x + w1.x, s);
            s = fmaf(a0.y + a1.y, w0.y + w1.y, s);
        }
        #pragma unroll
        for (int o = 16; o; o >>= 1) s += __shfl_xor_sync(0xFFFFFFFFu, s, o);
        if (lane == 0) {
            const float v = tanh_sat(s + cb[col] + g_probs[col]);
            xh[(size_t)row * HH + col] = __float2half_rn(v);
        }
    }
}

// ---------------- split-fp16 GEMM: TMA + ldmatrix + mma.sync -----------------------
// Barrier-free mainloop (per-stage full/empty mbarriers). NST-stage pipeline.
// CTA tile 128 x NT, 512 threads, 16 warps (4m x 4n), warp 32 x NT/4.
// PROD=3: hh(f32)+Al*Bh(f16)+Ah*Bl(f16).  PROD=1: hh only.
// EPI 0: relu->split(Ch,Cl)   1: tanh_sat(+probs)->Ch + flag   2: relu->fp32
#define KT       64
#define NTHREADS 512

static constexpr int smem_for(int P, int NT, int NST) {
    return NST * (((P == 3) ? 2 : 1) * 16384 + ((P >= 2) ? 2 : 1) * NT * 128) + 128;
}

template <int EPI, int PROD, int NT, int NST>
__global__ void __launch_bounds__(NTHREADS, 1)
mma_gemm(const __grid_constant__ CUtensorMap mAh,
         const __grid_constant__ CUtensorMap mAl,
         const __grid_constant__ CUtensorMap mBh,
         const __grid_constant__ CUtensorMap mBl,
         const float* __restrict__ bias,
         __half* __restrict__ Ch, __half* __restrict__ Cl,
         float* __restrict__ Cf,
         int M, int N, int K)
{
    constexpr bool NEED_AL = (PROD == 3);
    constexpr bool NEED_BL = (PROD >= 2);
    constexpr int  WNF     = NT / 32;
    constexpr uint32_t A_TILE = 16384u;
    constexpr uint32_t B_TILE = (uint32_t)NT * 128u;
    constexpr uint32_t OFF_AL = A_TILE;
    constexpr uint32_t OFF_BH = (NEED_AL ? 2u : 1u) * A_TILE;
    constexpr uint32_t OFF_BL = OFF_BH + B_TILE;
    constexpr uint32_t STAGE_B = OFF_BH + (NEED_BL ? 2u : 1u) * B_TILE;
    constexpr uint32_t TX_BYTES = STAGE_B;

    extern __shared__ __align__(1024) char smem[];
    const uint32_t sbase  = s2u(smem);
    const uint32_t fullb  = sbase + NST * STAGE_B;           // NST x 8B
    const uint32_t emptyb = fullb + 8 * NST;                 // NST x 8B

    const int tid  = threadIdx.x;
    const int lane = tid & 31;
    const int warp = tid >> 5;
    const int wm   = (warp & 3) * 32;
    const int wn   = (warp >> 2) * (NT / 4);
    const int g    = lane >> 2;
    const int tg   = lane & 3;

    const int bm = blockIdx.y * 128;
    const int bn = blockIdx.x * NT;

    if (tid == 0) {
        #pragma unroll
        for (int s = 0; s < NST; ++s) {
            mbar_init(fullb + 8 * s, 1);
            mbar_init(emptyb + 8 * s, 16);
        }
    }
    __syncthreads();

    auto issue = [&](int q, int s) {
        const uint32_t st = sbase + (uint32_t)s * STAGE_B;
        const int k0 = q * KT;
        mbar_expect_tx(fullb + 8 * s, TX_BYTES);
        tma2d(st,          &mAh, k0, bm, fullb + 8 * s);
        if (NEED_AL) tma2d(st + OFF_AL, &mAl, k0, bm, fullb + 8 * s);
        tma2d(st + OFF_BH, &mBh, k0, bn, fullb + 8 * s);
        if (NEED_BL) tma2d(st + OFF_BL, &mBl, k0, bn, fullb + 8 * s);
    };

    // ldmatrix swizzled addressing (SW128: byte ^ ((row&7)<<4))
    const uint32_t swz   = (uint32_t)(lane & 7) << 4;
    const uint32_t aRow0 = (uint32_t)((lane & 7) + 8 * ((lane >> 3) & 1)) * 128 + (uint32_t)wm * 128;
    const uint32_t aB0   = 16u * (uint32_t)(lane >> 4);
    const uint32_t bRow  = (uint32_t)(wn + 8 * (lane >> 3) + (lane & 7)) * 128;

    float    acc[2][WNF][4];
    uint32_t accx[2][WNF][2];
    #pragma unroll
    for (int i = 0; i < 2; ++i)
        #pragma unroll
        for (int j = 0; j < WNF; ++j) {
            #pragma unroll
            for (int q = 0; q < 4; ++q) acc[i][j][q] = 0.f;
            accx[i][j][0] = 0u; accx[i][j][1] = 0u;
        }

    const int NC = K / KT;
    if (tid == 0) {
        #pragma unroll
        for (int q = 0; q < NST - 1; ++q) issue(q, q);
    }

    #pragma unroll 1
    for (int c = 0; c < NC; ++c) {
        const int s = c - (c / NST) * NST;                 // c % NST
        if (tid == 0 && c + NST - 1 < NC) {
            const int q  = c + NST - 1;
            const int ns = q - (q / NST) * NST;            // q % NST
            if (q >= NST)
                mbar_wait(emptyb + 8 * ns, (uint32_t)(q / NST - 1) & 1u);
            issue(q, ns);
        }
        mbar_wait(fullb + 8 * s, (uint32_t)(c / NST) & 1u);

        const uint32_t st  = sbase + (uint32_t)s * STAGE_B;
        const uint32_t tAh = st;
        const uint32_t tAl = st + OFF_AL;
        const uint32_t tBh = st + OFF_BH;
        const uint32_t tBl = st + OFF_BL;

        #pragma unroll
        for (int k16 = 0; k16 < KT / 16; ++k16) {
            const uint32_t kbase = (uint32_t)(k16 * 32);
            const uint32_t ka  = (kbase + aB0) ^ swz;
            const uint32_t kb0 = kbase ^ swz;
            const uint32_t kb1 = (kbase + 16u) ^ swz;

            uint32_t a_h[2][4], a_l[2][4];
            #pragma unroll
            for (int i = 0; i < 2; ++i) {
                const uint32_t ao = aRow0 + (uint32_t)(i * 16 * 128) + ka;
                ldsm4(a_h[i][0], a_h[i][1], a_h[i][2], a_h[i][3], tAh + ao);
                if (NEED_AL) ldsm4(a_l[i][0], a_l[i][1], a_l[i][2], a_l[i][3], tAl + ao);
            }
            uint32_t b_h[WNF][2], b_l[WNF][2];
            #pragma unroll
            for (int nb = 0; nb < WNF / 4; ++nb) {
                const uint32_t bb = bRow + (uint32_t)(nb * 32 * 128);
                ldsm4(b_h[4*nb+0][0], b_h[4*nb+1][0], b_h[4*nb+2][0], b_h[4*nb+3][0], tBh + bb + kb0);
                ldsm4(b_h[4*nb+0][1], b_h[4*nb+1][1], b_h[4*nb+2][1], b_h[4*nb+3][1], tBh + bb + kb1);
                if (NEED_BL) {
                    ldsm4(b_l[4*nb+0][0], b_l[4*nb+1][0], b_l[4*nb+2][0], b_l[4*nb+3][0], tBl + bb + kb0);
                    ldsm4(b_l[4*nb+0][1], b_l[4*nb+1][1], b_l[4*nb+2][1], b_l[4*nb+3][1], tBl + bb + kb1);
                }
            }

            #pragma unroll
            for (int i = 0; i < 2; ++i)
                #pragma unroll
                for (int j = 0; j < WNF; ++j)
                    mma16(acc[i][j], a_h[i][0], a_h[i][1], a_h[i][2], a_h[i][3], b_h[j][0], b_h[j][1]);
            if (NEED_AL) {
                #pragma unroll
                for (int i = 0; i < 2; ++i)
                    #pragma unroll
                    for (int j = 0; j < WNF; ++j)
                        mma16h(accx[i][j], a_l[i][0], a_l[i][1], a_l[i][2], a_l[i][3], b_h[j][0], b_h[j][1]);
            }
            if (NEED_BL) {
                #pragma unroll
                for (int i = 0; i < 2; ++i)
                    #pragma unroll
                    for (int j = 0; j < WNF; ++j)
                        mma16h(accx[i][j], a_h[i][0], a_h[i][1], a_h[i][2], a_h[i][3], b_l[j][0], b_l[j][1]);
            }
        }
        if (lane == 0) mbar_arrive(emptyb + 8 * s);
    }

    // ---- epilogue ----
    #pragma unroll
    for (int j = 0; j < WNF; ++j) {
        const int col = bn + wn + j * 8 + 2 * tg;
        const float b0 = bias[col], b1 = bias[col + 1];
        float p0 = 0.f, p1 = 0.f;
        if (EPI == 1) { p0 = g_probs[col]; p1 = g_probs[col + 1]; }
        #pragma unroll
        for (int i = 0; i < 2; ++i) {
            const int row = bm + wm + i * 16 + g;
            const float2 x0 = __half22float2(*(__half2*)&accx[i][j][0]);
            const float2 x1 = __half22float2(*(__half2*)&accx[i][j][1]);
            float v0 = acc[i][j][0] + x0.x + b0;
            float v1 = acc[i][j][1] + x0.y + b1;
            float v2 = acc[i][j][2] + x1.x + b0;
            float v3 = acc[i][j][3] + x1.y + b1;
            if (EPI == 1) {
                v0 += p0; v1 += p1; v2 += p0; v3 += p1;
                auto push = [&](float pv, int r, int cc) {
                    if (fabsf(pv) < FLAG_T) {
                        const uint32_t idx = atomicAdd(&g_flagn, 1u);
                        if (idx < FLAG_CAP)
                            g_flags[idx] = ((uint32_t)r << 10) | (uint32_t)cc;
                    }
                };
                push(v0, row, col); push(v1, row, col + 1);
                push(v2, row + 8, col); push(v3, row + 8, col + 1);
                v0 = tanh_sat(v0); v1 = tanh_sat(v1);
                v2 = tanh_sat(v2); v3 = tanh_sat(v3);
                *reinterpret_cast<__half2*>(&Ch[(size_t)row * N + col]) =
                    __halves2half2(__float2half_rn(v0), __float2half_rn(v1));
                *reinterpret_cast<__half2*>(&Ch[(size_t)(row + 8) * N + col]) =
                    __halves2half2(__float2half_rn(v2), __float2half_rn(v3));
            } else if (EPI == 2) {
                v0 = fmaxf(v0, 0.f); v1 = fmaxf(v1, 0.f);
                v2 = fmaxf(v2, 0.f); v3 = fmaxf(v3, 0.f);
                *reinterpret_cast<float2*>(&Cf[(size_t)row * N + col])       = make_float2(v0, v1);
                *reinterpret_cast<float2*>(&Cf[(size_t)(row + 8) * N + col]) = make_float2(v2, v3);
            } else {
                v0 = fmaxf(v0, 0.f); v1 = fmaxf(v1, 0.f);
                v2 = fmaxf(v2, 0.f); v3 = fmaxf(v3, 0.f);
                __half h0, h1, h2, h3, l0, l1, l2, l3;
                fsplit(v0, h0, l0); fsplit(v1, h1, l1);
                fsplit(v2, h2, l2); fsplit(v3, h3, l3);
                *reinterpret_cast<__half2*>(&Ch[(size_t)row * N + col])       = __halves2half2(h0, h1);
                *reinterpret_cast<__half2*>(&Ch[(size_t)(row + 8) * N + col]) = __halves2half2(h2, h3);
                *reinterpret_cast<__half2*>(&Cl[(size_t)row * N + col])       = __halves2half2(l0, l1);
                *reinterpret_cast<__half2*>(&Cl[(size_t)(row + 8) * N + col]) = __halves2half2(l2, l3);
            }
        }
    }
}

// ---------------- host --------------------------------------------------------------
typedef CUresult (*tmap_fn_t)(CUtensorMap*, CUtensorMapDataType, cuuint32_t, void*,
                              const cuuint64_t*, const cuuint64_t*,
                              const cuuint32_t*, const cuuint32_t*,
                              CUtensorMapInterleave, CUtensorMapSwizzle,
                              CUtensorMapL2promotion, CUtensorMapFloatOOBfill);

static void enc2d(tmap_fn_t f, CUtensorMap* m, __half* p, uint64_t Kd, uint64_t rows,
                  uint32_t box1) {
    cuuint64_t dims[2] = {Kd, rows};
    cuuint64_t str[1]  = {Kd * 2};
    cuuint32_t box[2]  = {KT, box1};
    cuuint32_t es[2]   = {1, 1};
    f(m, CU_TENSOR_MAP_DATA_TYPE_FLOAT16, 2, (void*)p, dims, str, box, es,
      CU_TENSOR_MAP_INTERLEAVE_NONE, CU_TENSOR_MAP_SWIZZLE_128B,
      CU_TENSOR_MAP_L2_PROMOTION_L2_128B, CU_TENSOR_MAP_FLOAT_OOB_FILL_NONE);
}

extern "C" void kernel_launch(void* const* d_in, const int* in_sizes, int n_in,
                              void* d_out, int out_size) {
    const float* x    = (const float*)d_in[0];
    const float* w0   = (const float*)d_in[1];
    const float* b0   = (const float*)d_in[2];
    const float* w1   = (const float*)d_in[3];
    const float* b1   = (const float*)d_in[4];
    const float* tw   = (const float*)d_in[5];
    const float* cw   = (const float*)d_in[6];
    const float* cb   = (const float*)d_in[7];
    const float* wout = (const float*)d_in[8];
    const float* bout = (const float*)d_in[9];
    float* out = (float*)d_out;

    __half *xh, *xl, *h1h, *h1l, *h2h, *h2l;
    __half *w0h, *w0l, *w1h, *w1l, *cwh, *cwl, *woh, *wol;
    cudaGetSymbolAddress((void**)&xh,  g_xh);   cudaGetSymbolAddress((void**)&xl,  g_xl);
    cudaGetSymbolAddress((void**)&h1h, g_h1h);  cudaGetSymbolAddress((void**)&h1l, g_h1l);
    cudaGetSymbolAddress((void**)&h2h, g_h2h);  cudaGetSymbolAddress((void**)&h2l, g_h2l);
    cudaGetSymbolAddress((void**)&w0h, g_w0h);  cudaGetSymbolAddress((void**)&w0l, g_w0l);
    cudaGetSymbolAddress((void**)&w1h, g_w1h);  cudaGetSymbolAddress((void**)&w1l, g_w1l);
    cudaGetSymbolAddress((void**)&cwh, g_cwh);  cudaGetSymbolAddress((void**)&cwl, g_cwl);
    cudaGetSymbolAddress((void**)&woh, g_woh);  cudaGetSymbolAddress((void**)&wol, g_wol);

    void* fp = nullptr;
    cudaDriverEntryPointQueryResult qr;
    cudaGetDriverEntryPoint("cuTensorMapEncodeTiled", &fp, cudaEnableDefault, &qr);
    tmap_fn_t enc = (tmap_fn_t)fp;

    CUtensorMap mXh, mXl, mH1h, mH1l, mH2h, mH2l;
    CUtensorMap mW0h, mW0l, mW1h, mW1l, mCWh, mCWl, mWOh, mWOl;
    enc2d(enc, &mXh,  xh,  DIN, BB, 128);
    enc2d(enc, &mXl,  xl,  DIN, BB, 128);
    enc2d(enc, &mH1h, h1h, HH,  BB, 128);
    enc2d(enc, &mH1l, h1l, HH,  BB, 128);
    enc2d(enc, &mH2h, h2h, HH,  BB, 128);
    enc2d(enc, &mH2l, h2l, HH,  BB, 128);
    enc2d(enc, &mW0h, w0h, DIN, HH, 128);
    enc2d(enc, &mW0l, w0l, DIN, HH, 128);
    enc2d(enc, &mW1h, w1h, HH,  HH, 128);
    enc2d(enc, &mW1l, w1l, HH,  HH, 128);
    enc2d(enc, &mCWh, cwh, HH,  HH, 256);
    enc2d(enc, &mCWl, cwl, HH,  HH, 256);
    enc2d(enc, &mWOh, woh, HH,  DOUT, 256);
    enc2d(enc, &mWOl, wol, HH,  DOUT, 256);

    cudaFuncSetAttribute(mma_gemm<0,3,128,3>, cudaFuncAttributeMaxDynamicSharedMemorySize, smem_for(3,128,3));
    cudaFuncSetAttribute(mma_gemm<1,1,256,4>, cudaFuncAttributeMaxDynamicSharedMemorySize, smem_for(1,256,4));
    cudaFuncSetAttribute(mma_gemm<2,1,256,4>, cudaFuncAttributeMaxDynamicSharedMemorySize, smem_for(1,256,4));

    probs_kernel<<<HH, 256>>>(tw);
    {
        const int n8 = BB * DIN / 8;
        splitx_kernel<<<(n8 + 255) / 256, 256>>>((const float4*)x,
                                                 (uint4*)xh, (uint4*)xl, n8);
    }
    tsplit_kernel<<<dim3(HH / 32,   DIN / 32), dim3(32, 8)>>>(w0, w0h, w0l, DIN, HH);
    tsplit_kernel<<<dim3(HH / 32,   HH  / 32), dim3(32, 8)>>>(w1, w1h, w1l, HH,  HH);
    tsplit_kernel<<<dim3(HH / 32,   HH  / 32), dim3(32, 8)>>>(cw, cwh, cwl, HH,  HH);

    // layer 1: relu(x @ w0 + b0)            — 3 products, 3-stage
    mma_gemm<0,3,128,3><<<dim3(HH / 128,   BB / 128), NTHREADS, smem_for(3,128,3)>>>(
        mXh, mXl, mW0h, mW0l, b0,   h1h, h1l, nullptr, BB, HH,   DIN);

    tsplit_kernel<<<dim3(DOUT / 32, HH / 32), dim3(32, 8)>>>(wout, woh, wol, HH, DOUT);

    // layer 2: relu(h1 @ w1 + b1)           — 3 products, 3-stage
    mma_gemm<0,3,128,3><<<dim3(HH / 128,   BB / 128), NTHREADS, smem_for(3,128,3)>>>(
        mH1h, mH1l, mW1h, mW1l, b1,  h2h, h2l, nullptr, BB, HH,   HH);
    // layer 3: tanh(h2 @ cw + cb + probs)   — hh only + flags, wide tile, 4-stage
    mma_gemm<1,1,256,4><<<dim3(HH / 256,   BB / 128), NTHREADS, smem_for(1,256,4)>>>(
        mH2h, mH2l, mCWh, mCWl, cb,  xh,  nullptr, nullptr, BB, HH,   HH);
    // repair flagged entries exactly
    repair_kernel<<<512, 256>>>((const __half2*)h2h, (const __half2*)h2l,
                                (const __half2*)cwh, (const __half2*)cwl,
                                cb, xh);
    // layer 4: relu(h3 @ wout + bout)       — 1 product, wide tile, 4-stage
    mma_gemm<2,1,256,4><<<dim3(DOUT / 256, BB / 128), NTHREADS, smem_for(1,256,4)>>>(
        mXh, mXl, mWOh, mWOl, bout, nullptr, nullptr, out, BB, DOUT, HH);
}